// round 1
// baseline (speedup 1.0000x reference)
#include <cuda_runtime.h>
#include <math.h>

#define SEQ      2048
#define DIM      1280
#define HEADS    16
#define HEAD_DIM 80
#define QKV_DIM  3840   // 3 * DIM

// Scratch (no cudaMalloc allowed)
__device__ float g_qkv[SEQ * QKV_DIM];   // 31.5 MB: (S, 3, H, D) flattened
__device__ float g_attn[SEQ * DIM];      // 10.5 MB: attention output pre-proj

// ---------------------------------------------------------------------------
// GEMM: C[M,N] = A[M,K] @ B[N,K]^T + bias[N]
// 128x128 block tile, BK=16, 256 threads, 8x8 micro-tile per thread.
// ---------------------------------------------------------------------------
__global__ void __launch_bounds__(256) gemm_bias_kernel(
    const float* __restrict__ A, const float* __restrict__ B,
    const float* __restrict__ bias, float* __restrict__ C,
    int M, int N, int K)
{
    const int BM = 128, BN = 128, BK = 16;
    __shared__ float As[BK][BM + 4];
    __shared__ float Bs[BK][BN + 4];

    int tid = threadIdx.x;
    int ty = tid >> 4;        // 0..15 -> row group
    int tx = tid & 15;        // 0..15 -> col group
    int m0 = blockIdx.y * BM;
    int n0 = blockIdx.x * BN;

    float acc[8][8];
    #pragma unroll
    for (int i = 0; i < 8; i++)
        #pragma unroll
        for (int j = 0; j < 8; j++) acc[i][j] = 0.f;

    for (int k0 = 0; k0 < K; k0 += BK) {
        #pragma unroll
        for (int i = 0; i < 8; i++) {
            int e = tid + i * 256;      // 0..2047
            int r = e >> 4;             // 0..127
            int c = e & 15;             // 0..15
            As[c][r] = A[(size_t)(m0 + r) * K + k0 + c];
            Bs[c][r] = B[(size_t)(n0 + r) * K + k0 + c];
        }
        __syncthreads();

        #pragma unroll
        for (int c = 0; c < BK; c++) {
            float a[8], b[8];
            #pragma unroll
            for (int i = 0; i < 8; i++) a[i] = As[c][ty * 8 + i];
            #pragma unroll
            for (int j = 0; j < 8; j++) b[j] = Bs[c][tx * 8 + j];
            #pragma unroll
            for (int i = 0; i < 8; i++)
                #pragma unroll
                for (int j = 0; j < 8; j++)
                    acc[i][j] += a[i] * b[j];
        }
        __syncthreads();
    }

    #pragma unroll
    for (int i = 0; i < 8; i++) {
        int row = m0 + ty * 8 + i;
        #pragma unroll
        for (int j = 0; j < 8; j++) {
            int col = n0 + tx * 8 + j;
            C[(size_t)row * N + col] = acc[i][j] + bias[col];
        }
    }
}

// ---------------------------------------------------------------------------
// RoPE (vision variant) applied in-place to q (part 0) and k (part 1).
// Each thread handles one (s, part, h, d2) pair: elements d2 and d2+40.
// ---------------------------------------------------------------------------
__global__ void __launch_bounds__(256) rope_kernel(const float* __restrict__ rot)
{
    int t = blockIdx.x * blockDim.x + threadIdx.x;
    const int total = SEQ * 2 * HEADS * (HEAD_DIM / 2);
    if (t >= total) return;

    int d2   = t % 40;
    int h    = (t / 40) % HEADS;
    int part = (t / (40 * HEADS)) % 2;
    int s    = t / (40 * HEADS * 2);

    float f = rot[s * 40 + d2];
    float si, co;
    sincosf(f, &si, &co);

    size_t base = (size_t)s * QKV_DIM + (size_t)part * DIM + h * HEAD_DIM;
    float x1 = g_qkv[base + d2];
    float x2 = g_qkv[base + 40 + d2];
    g_qkv[base + d2]      = x1 * co - x2 * si;
    g_qkv[base + 40 + d2] = x2 * co + x1 * si;
}

// ---------------------------------------------------------------------------
// Fused flash attention with block-diagonal (segment) masking.
// Grid: (SEQ/64, HEADS). Block: 256 threads.
// Each block: 64 queries of one head. Keys iterated in 64-tiles over the
// segment range covered by this query block. Online softmax, fp32.
// Thread (ty,tx): owns score micro-tile rows ty*4..+3, cols tx*4..+3,
// and output cols tx + 16*j (j<5).
// ---------------------------------------------------------------------------
#define QK_STRIDE 81
#define SS_STRIDE 65

__global__ void __launch_bounds__(256) attn_kernel(const int* __restrict__ cu, int ncu)
{
    extern __shared__ float sm[];
    float* Qs  = sm;                      // 64 * 81
    float* KVs = Qs + 64 * QK_STRIDE;     // 64 * 81 (K then reused for V)
    float* Ss  = KVs + 64 * QK_STRIDE;    // 64 * 65
    int*   segq  = (int*)(Ss + 64 * SS_STRIDE);  // 64
    int*   segk  = segq + 64;                    // 64
    int*   range = segk + 64;                    // lo, hi

    int tid = threadIdx.x;
    int ty = tid >> 4;
    int tx = tid & 15;
    int head  = blockIdx.y;
    int qbase = blockIdx.x * 64;
    const float scale = rsqrtf((float)HEAD_DIM);

    // Load Q tile (pre-scaled)
    #pragma unroll
    for (int i = 0; i < 20; i++) {
        int e = tid + i * 256;
        int r = e / HEAD_DIM, d = e % HEAD_DIM;
        Qs[r * QK_STRIDE + d] =
            g_qkv[(size_t)(qbase + r) * QKV_DIM + head * HEAD_DIM + d] * scale;
    }
    // Segment id per query row
    if (tid < 64) {
        int i = qbase + tid;
        int s = 0;
        for (int j = 1; j < ncu; j++) s += (cu[j] <= i);
        segq[tid] = s;
    }
    __syncthreads();
    if (tid == 0) {
        int smin = segq[0], smax = segq[0];
        for (int r = 1; r < 64; r++) {
            smin = min(smin, segq[r]);
            smax = max(smax, segq[r]);
        }
        range[0] = cu[smin];
        range[1] = cu[smax + 1];
    }
    __syncthreads();
    int lo = range[0], hi = range[1];

    float m_i[4], l_i[4], acc[4][5];
    int myseg[4];
    #pragma unroll
    for (int i = 0; i < 4; i++) {
        m_i[i] = -1e30f;
        l_i[i] = 0.f;
        myseg[i] = segq[ty * 4 + i];
        #pragma unroll
        for (int j = 0; j < 5; j++) acc[i][j] = 0.f;
    }

    for (int kt = lo; kt < hi; kt += 64) {
        // Load K tile
        #pragma unroll
        for (int i = 0; i < 20; i++) {
            int e = tid + i * 256;
            int r = e / HEAD_DIM, d = e % HEAD_DIM;
            int key = kt + r;
            KVs[r * QK_STRIDE + d] = (key < hi)
                ? g_qkv[(size_t)key * QKV_DIM + DIM + head * HEAD_DIM + d] : 0.f;
        }
        if (tid < 64) {
            int key = kt + tid;
            int s = -1;
            if (key < hi) {
                s = 0;
                for (int j = 1; j < ncu; j++) s += (cu[j] <= key);
            }
            segk[tid] = s;
        }
        __syncthreads();

        // Scores: 4x4 micro-tile per thread
        float sf[4][4];
        #pragma unroll
        for (int i = 0; i < 4; i++)
            #pragma unroll
            for (int j = 0; j < 4; j++) sf[i][j] = 0.f;

        for (int d = 0; d < HEAD_DIM; d++) {
            float qv[4], kv[4];
            #pragma unroll
            for (int i = 0; i < 4; i++) qv[i] = Qs[(ty * 4 + i) * QK_STRIDE + d];
            #pragma unroll
            for (int j = 0; j < 4; j++) kv[j] = KVs[(tx * 4 + j) * QK_STRIDE + d];
            #pragma unroll
            for (int i = 0; i < 4; i++)
                #pragma unroll
                for (int j = 0; j < 4; j++)
                    sf[i][j] += qv[i] * kv[j];
        }

        // Mask + online softmax per owned row
        #pragma unroll
        for (int i = 0; i < 4; i++) {
            int sq = myseg[i];
            float tmax = -1e30f;
            #pragma unroll
            for (int j = 0; j < 4; j++) {
                if (segk[tx * 4 + j] != sq) sf[i][j] = -1e30f;
                tmax = fmaxf(tmax, sf[i][j]);
            }
            #pragma unroll
            for (int msk = 8; msk >= 1; msk >>= 1)
                tmax = fmaxf(tmax, __shfl_xor_sync(0xffffffffu, tmax, msk));

            float mnew  = fmaxf(m_i[i], tmax);
            float alpha = expf(m_i[i] - mnew);
            float psum  = 0.f;
            #pragma unroll
            for (int j = 0; j < 4; j++) {
                float p = expf(sf[i][j] - mnew);
                Ss[(ty * 4 + i) * SS_STRIDE + tx * 4 + j] = p;
                psum += p;
            }
            #pragma unroll
            for (int msk = 8; msk >= 1; msk >>= 1)
                psum += __shfl_xor_sync(0xffffffffu, psum, msk);

            l_i[i] = l_i[i] * alpha + psum;
            m_i[i] = mnew;
            #pragma unroll
            for (int j = 0; j < 5; j++) acc[i][j] *= alpha;
        }
        __syncthreads();

        // Load V tile into the same buffer
        #pragma unroll
        for (int i = 0; i < 20; i++) {
            int e = tid + i * 256;
            int r = e / HEAD_DIM, d = e % HEAD_DIM;
            int key = kt + r;
            KVs[r * QK_STRIDE + d] = (key < hi)
                ? g_qkv[(size_t)key * QKV_DIM + 2 * DIM + head * HEAD_DIM + d] : 0.f;
        }
        __syncthreads();

        // acc += P @ V
        for (int k = 0; k < 64; k++) {
            float vv[5];
            #pragma unroll
            for (int j = 0; j < 5; j++) vv[j] = KVs[k * QK_STRIDE + tx + 16 * j];
            #pragma unroll
            for (int i = 0; i < 4; i++) {
                float p = Ss[(ty * 4 + i) * SS_STRIDE + k];
                #pragma unroll
                for (int j = 0; j < 5; j++) acc[i][j] += p * vv[j];
            }
        }
        __syncthreads();
    }

    // Epilogue: normalize and write
    #pragma unroll
    for (int i = 0; i < 4; i++) {
        float invl = (l_i[i] > 0.f) ? (1.f / l_i[i]) : 0.f;
        int row = qbase + ty * 4 + i;
        #pragma unroll
        for (int j = 0; j < 5; j++) {
            int col = tx + 16 * j;
            g_attn[(size_t)row * DIM + head * HEAD_DIM + col] = acc[i][j] * invl;
        }
    }
}

// ---------------------------------------------------------------------------
extern "C" void kernel_launch(void* const* d_in, const int* in_sizes, int n_in,
                              void* d_out, int out_size)
{
    const float* hidden = (const float*)d_in[0];
    const float* rotary = (const float*)d_in[1];
    const int*   cu     = (const int*)d_in[2];
    const float* qkv_w  = (const float*)d_in[3];
    const float* qkv_b  = (const float*)d_in[4];
    const float* proj_w = (const float*)d_in[5];
    const float* proj_b = (const float*)d_in[6];
    float* out = (float*)d_out;
    int ncu = in_sizes[2];

    float *qkv_ptr = nullptr, *attn_ptr = nullptr;
    cudaGetSymbolAddress((void**)&qkv_ptr, g_qkv);
    cudaGetSymbolAddress((void**)&attn_ptr, g_attn);

    // 1) QKV GEMM + bias
    gemm_bias_kernel<<<dim3(QKV_DIM / 128, SEQ / 128), 256>>>(
        hidden, qkv_w, qkv_b, qkv_ptr, SEQ, QKV_DIM, DIM);

    // 2) RoPE in-place on q, k
    {
        int total = SEQ * 2 * HEADS * (HEAD_DIM / 2);
        rope_kernel<<<(total + 255) / 256, 256>>>(rotary);
    }

    // 3) Fused segment-masked flash attention
    {
        size_t smem = (size_t)(2 * 64 * QK_STRIDE + 64 * SS_STRIDE) * sizeof(float)
                    + 130 * sizeof(int);
        cudaFuncSetAttribute(attn_kernel,
                             cudaFuncAttributeMaxDynamicSharedMemorySize, (int)smem);
        attn_kernel<<<dim3(SEQ / 64, HEADS), 256, smem>>>(cu, ncu);
    }

    // 4) Output projection + bias
    gemm_bias_kernel<<<dim3(DIM / 128, SEQ / 128), 256>>>(
        attn_ptr, proj_w, proj_b, out, SEQ, DIM, DIM);
}

// round 2
// speedup vs baseline: 1.1597x; 1.1597x over previous
#include <cuda_runtime.h>
#include <math.h>

#define SEQ      2048
#define DIM      1280
#define HEADS    16
#define HEAD_DIM 80
#define QKV_DIM  3840   // 3 * DIM

// Scratch (no cudaMalloc allowed)
__device__ float g_qkv[SEQ * QKV_DIM];   // (S, 3, H, D) flattened
__device__ float g_attn[SEQ * DIM];      // attention output pre-proj

// ---------------------------------------------------------------------------
// SGEMM: C[M,N] = A[M,K] @ B[N,K]^T + bias[N]
// 128x128 tile, BK=16, 256 threads, 8x8 micro-tile, double-buffered smem,
// register prefetch of next K-slab, float4 LDG/LDS/STG throughout.
// Requires M%128==0, N%128==0, K%16==0.
// ---------------------------------------------------------------------------
#define SM_PAD 132   // 128 + 4 (keeps float4 alignment, avoids LDS conflicts)

__global__ void __launch_bounds__(256, 2) sgemm_bias_kernel(
    const float* __restrict__ A, const float* __restrict__ B,
    const float* __restrict__ bias, float* __restrict__ C,
    int M, int N, int K)
{
    __shared__ float As[2][16][SM_PAD];
    __shared__ float Bs[2][16][SM_PAD];

    const int tid = threadIdx.x;
    const int ty  = tid >> 4;       // 0..15
    const int tx  = tid & 15;       // 0..15
    const int m0  = blockIdx.y * 128;
    const int n0  = blockIdx.x * 128;

    // Global-load mapping: thread covers rows (lrow, lrow+64), 4 k-cols at lcol
    const int lrow = tid >> 2;          // 0..63
    const int lcol = (tid & 3) * 4;     // 0,4,8,12

    const float* Ap = A + (size_t)(m0 + lrow) * K + lcol;
    const float* Bp = B + (size_t)(n0 + lrow) * K + lcol;
    const size_t rowK64 = (size_t)64 * K;

    float4 a0 = *(const float4*)(Ap);
    float4 a1 = *(const float4*)(Ap + rowK64);
    float4 b0 = *(const float4*)(Bp);
    float4 b1 = *(const float4*)(Bp + rowK64);

    // store staged regs transposed into buffer
    {
        As[0][lcol+0][lrow] = a0.x; As[0][lcol+1][lrow] = a0.y;
        As[0][lcol+2][lrow] = a0.z; As[0][lcol+3][lrow] = a0.w;
        As[0][lcol+0][lrow+64] = a1.x; As[0][lcol+1][lrow+64] = a1.y;
        As[0][lcol+2][lrow+64] = a1.z; As[0][lcol+3][lrow+64] = a1.w;
        Bs[0][lcol+0][lrow] = b0.x; Bs[0][lcol+1][lrow] = b0.y;
        Bs[0][lcol+2][lrow] = b0.z; Bs[0][lcol+3][lrow] = b0.w;
        Bs[0][lcol+0][lrow+64] = b1.x; Bs[0][lcol+1][lrow+64] = b1.y;
        Bs[0][lcol+2][lrow+64] = b1.z; Bs[0][lcol+3][lrow+64] = b1.w;
    }
    __syncthreads();

    float acc[8][8];
    #pragma unroll
    for (int i = 0; i < 8; i++)
        #pragma unroll
        for (int j = 0; j < 8; j++) acc[i][j] = 0.f;

    const int nIter = K >> 4;   // K / 16
    int buf = 0;

    for (int it = 0; it < nIter; ++it) {
        // Prefetch next slab into registers while computing current
        if (it + 1 < nIter) {
            const float* An = Ap + (it + 1) * 16;
            const float* Bn = Bp + (it + 1) * 16;
            a0 = *(const float4*)(An);
            a1 = *(const float4*)(An + rowK64);
            b0 = *(const float4*)(Bn);
            b1 = *(const float4*)(Bn + rowK64);
        }

        #pragma unroll
        for (int k = 0; k < 16; k++) {
            float4 av0 = *(const float4*)&As[buf][k][ty * 8];
            float4 av1 = *(const float4*)&As[buf][k][ty * 8 + 4];
            float4 bv0 = *(const float4*)&Bs[buf][k][tx * 8];
            float4 bv1 = *(const float4*)&Bs[buf][k][tx * 8 + 4];
            float a[8] = {av0.x, av0.y, av0.z, av0.w, av1.x, av1.y, av1.z, av1.w};
            float b[8] = {bv0.x, bv0.y, bv0.z, bv0.w, bv1.x, bv1.y, bv1.z, bv1.w};
            #pragma unroll
            for (int i = 0; i < 8; i++)
                #pragma unroll
                for (int j = 0; j < 8; j++)
                    acc[i][j] += a[i] * b[j];
        }

        if (it + 1 < nIter) {
            buf ^= 1;
            As[buf][lcol+0][lrow] = a0.x; As[buf][lcol+1][lrow] = a0.y;
            As[buf][lcol+2][lrow] = a0.z; As[buf][lcol+3][lrow] = a0.w;
            As[buf][lcol+0][lrow+64] = a1.x; As[buf][lcol+1][lrow+64] = a1.y;
            As[buf][lcol+2][lrow+64] = a1.z; As[buf][lcol+3][lrow+64] = a1.w;
            Bs[buf][lcol+0][lrow] = b0.x; Bs[buf][lcol+1][lrow] = b0.y;
            Bs[buf][lcol+2][lrow] = b0.z; Bs[buf][lcol+3][lrow] = b0.w;
            Bs[buf][lcol+0][lrow+64] = b1.x; Bs[buf][lcol+1][lrow+64] = b1.y;
            Bs[buf][lcol+2][lrow+64] = b1.z; Bs[buf][lcol+3][lrow+64] = b1.w;
            __syncthreads();
        }
    }

    // Epilogue: bias + vectorized store
    float bb[8];
    #pragma unroll
    for (int j = 0; j < 8; j++) bb[j] = bias[n0 + tx * 8 + j];

    #pragma unroll
    for (int i = 0; i < 8; i++) {
        int row = m0 + ty * 8 + i;
        float4 c0 = make_float4(acc[i][0] + bb[0], acc[i][1] + bb[1],
                                acc[i][2] + bb[2], acc[i][3] + bb[3]);
        float4 c1 = make_float4(acc[i][4] + bb[4], acc[i][5] + bb[5],
                                acc[i][6] + bb[6], acc[i][7] + bb[7]);
        float* cp = C + (size_t)row * N + n0 + tx * 8;
        *(float4*)(cp)     = c0;
        *(float4*)(cp + 4) = c1;
    }
}

// ---------------------------------------------------------------------------
// RoPE (vision variant) applied in-place to q (part 0) and k (part 1).
// ---------------------------------------------------------------------------
__global__ void __launch_bounds__(256) rope_kernel(const float* __restrict__ rot)
{
    int t = blockIdx.x * blockDim.x + threadIdx.x;
    const int total = SEQ * 2 * HEADS * (HEAD_DIM / 2);
    if (t >= total) return;

    int d2   = t % 40;
    int h    = (t / 40) % HEADS;
    int part = (t / (40 * HEADS)) % 2;
    int s    = t / (40 * HEADS * 2);

    float f = rot[s * 40 + d2];
    float si, co;
    sincosf(f, &si, &co);

    size_t base = (size_t)s * QKV_DIM + (size_t)part * DIM + h * HEAD_DIM;
    float x1 = g_qkv[base + d2];
    float x2 = g_qkv[base + 40 + d2];
    g_qkv[base + d2]      = x1 * co - x2 * si;
    g_qkv[base + 40 + d2] = x2 * co + x1 * si;
}

// ---------------------------------------------------------------------------
// Fused flash attention with block-diagonal (segment) masking.
// Grid: (SEQ/64, HEADS). Block: 256 threads.
// ---------------------------------------------------------------------------
#define QK_STRIDE 81
#define SS_STRIDE 65

__global__ void __launch_bounds__(256) attn_kernel(const int* __restrict__ cu, int ncu)
{
    extern __shared__ float sm[];
    float* Qs  = sm;                      // 64 * 81
    float* KVs = Qs + 64 * QK_STRIDE;     // 64 * 81 (K then reused for V)
    float* Ss  = KVs + 64 * QK_STRIDE;    // 64 * 65
    int*   segq  = (int*)(Ss + 64 * SS_STRIDE);  // 64
    int*   segk  = segq + 64;                    // 64
    int*   range = segk + 64;                    // lo, hi

    int tid = threadIdx.x;
    int ty = tid >> 4;
    int tx = tid & 15;
    int head  = blockIdx.y;
    int qbase = blockIdx.x * 64;
    const float scale = rsqrtf((float)HEAD_DIM);

    #pragma unroll
    for (int i = 0; i < 20; i++) {
        int e = tid + i * 256;
        int r = e / HEAD_DIM, d = e % HEAD_DIM;
        Qs[r * QK_STRIDE + d] =
            g_qkv[(size_t)(qbase + r) * QKV_DIM + head * HEAD_DIM + d] * scale;
    }
    if (tid < 64) {
        int i = qbase + tid;
        int s = 0;
        for (int j = 1; j < ncu; j++) s += (cu[j] <= i);
        segq[tid] = s;
    }
    __syncthreads();
    if (tid == 0) {
        int smin = segq[0], smax = segq[0];
        for (int r = 1; r < 64; r++) {
            smin = min(smin, segq[r]);
            smax = max(smax, segq[r]);
        }
        range[0] = cu[smin];
        range[1] = cu[smax + 1];
    }
    __syncthreads();
    int lo = range[0], hi = range[1];

    float m_i[4], l_i[4], acc[4][5];
    int myseg[4];
    #pragma unroll
    for (int i = 0; i < 4; i++) {
        m_i[i] = -1e30f;
        l_i[i] = 0.f;
        myseg[i] = segq[ty * 4 + i];
        #pragma unroll
        for (int j = 0; j < 5; j++) acc[i][j] = 0.f;
    }

    for (int kt = lo; kt < hi; kt += 64) {
        #pragma unroll
        for (int i = 0; i < 20; i++) {
            int e = tid + i * 256;
            int r = e / HEAD_DIM, d = e % HEAD_DIM;
            int key = kt + r;
            KVs[r * QK_STRIDE + d] = (key < hi)
                ? g_qkv[(size_t)key * QKV_DIM + DIM + head * HEAD_DIM + d] : 0.f;
        }
        if (tid < 64) {
            int key = kt + tid;
            int s = -1;
            if (key < hi) {
                s = 0;
                for (int j = 1; j < ncu; j++) s += (cu[j] <= key);
            }
            segk[tid] = s;
        }
        __syncthreads();

        float sf[4][4];
        #pragma unroll
        for (int i = 0; i < 4; i++)
            #pragma unroll
            for (int j = 0; j < 4; j++) sf[i][j] = 0.f;

        for (int d = 0; d < HEAD_DIM; d++) {
            float qv[4], kv[4];
            #pragma unroll
            for (int i = 0; i < 4; i++) qv[i] = Qs[(ty * 4 + i) * QK_STRIDE + d];
            #pragma unroll
            for (int j = 0; j < 4; j++) kv[j] = KVs[(tx * 4 + j) * QK_STRIDE + d];
            #pragma unroll
            for (int i = 0; i < 4; i++)
                #pragma unroll
                for (int j = 0; j < 4; j++)
                    sf[i][j] += qv[i] * kv[j];
        }

        #pragma unroll
        for (int i = 0; i < 4; i++) {
            int sq = myseg[i];
            float tmax = -1e30f;
            #pragma unroll
            for (int j = 0; j < 4; j++) {
                if (segk[tx * 4 + j] != sq) sf[i][j] = -1e30f;
                tmax = fmaxf(tmax, sf[i][j]);
            }
            #pragma unroll
            for (int msk = 8; msk >= 1; msk >>= 1)
                tmax = fmaxf(tmax, __shfl_xor_sync(0xffffffffu, tmax, msk));

            float mnew  = fmaxf(m_i[i], tmax);
            float alpha = expf(m_i[i] - mnew);
            float psum  = 0.f;
            #pragma unroll
            for (int j = 0; j < 4; j++) {
                float p = expf(sf[i][j] - mnew);
                Ss[(ty * 4 + i) * SS_STRIDE + tx * 4 + j] = p;
                psum += p;
            }
            #pragma unroll
            for (int msk = 8; msk >= 1; msk >>= 1)
                psum += __shfl_xor_sync(0xffffffffu, psum, msk);

            l_i[i] = l_i[i] * alpha + psum;
            m_i[i] = mnew;
            #pragma unroll
            for (int j = 0; j < 5; j++) acc[i][j] *= alpha;
        }
        __syncthreads();

        #pragma unroll
        for (int i = 0; i < 20; i++) {
            int e = tid + i * 256;
            int r = e / HEAD_DIM, d = e % HEAD_DIM;
            int key = kt + r;
            KVs[r * QK_STRIDE + d] = (key < hi)
                ? g_qkv[(size_t)key * QKV_DIM + 2 * DIM + head * HEAD_DIM + d] : 0.f;
        }
        __syncthreads();

        for (int k = 0; k < 64; k++) {
            float vv[5];
            #pragma unroll
            for (int j = 0; j < 5; j++) vv[j] = KVs[k * QK_STRIDE + tx + 16 * j];
            #pragma unroll
            for (int i = 0; i < 4; i++) {
                float p = Ss[(ty * 4 + i) * SS_STRIDE + k];
                #pragma unroll
                for (int j = 0; j < 5; j++) acc[i][j] += p * vv[j];
            }
        }
        __syncthreads();
    }

    #pragma unroll
    for (int i = 0; i < 4; i++) {
        float invl = (l_i[i] > 0.f) ? (1.f / l_i[i]) : 0.f;
        int row = qbase + ty * 4 + i;
        #pragma unroll
        for (int j = 0; j < 5; j++) {
            int col = tx + 16 * j;
            g_attn[(size_t)row * DIM + head * HEAD_DIM + col] = acc[i][j] * invl;
        }
    }
}

// ---------------------------------------------------------------------------
extern "C" void kernel_launch(void* const* d_in, const int* in_sizes, int n_in,
                              void* d_out, int out_size)
{
    const float* hidden = (const float*)d_in[0];
    const float* rotary = (const float*)d_in[1];
    const int*   cu     = (const int*)d_in[2];
    const float* qkv_w  = (const float*)d_in[3];
    const float* qkv_b  = (const float*)d_in[4];
    const float* proj_w = (const float*)d_in[5];
    const float* proj_b = (const float*)d_in[6];
    float* out = (float*)d_out;
    int ncu = in_sizes[2];

    float *qkv_ptr = nullptr, *attn_ptr = nullptr;
    cudaGetSymbolAddress((void**)&qkv_ptr, g_qkv);
    cudaGetSymbolAddress((void**)&attn_ptr, g_attn);

    // 1) QKV GEMM + bias
    sgemm_bias_kernel<<<dim3(QKV_DIM / 128, SEQ / 128), 256>>>(
        hidden, qkv_w, qkv_b, qkv_ptr, SEQ, QKV_DIM, DIM);

    // 2) RoPE in-place on q, k
    {
        int total = SEQ * 2 * HEADS * (HEAD_DIM / 2);
        rope_kernel<<<(total + 255) / 256, 256>>>(rotary);
    }

    // 3) Fused segment-masked flash attention
    {
        size_t smem = (size_t)(2 * 64 * QK_STRIDE + 64 * SS_STRIDE) * sizeof(float)
                    + 130 * sizeof(int);
        cudaFuncSetAttribute(attn_kernel,
                             cudaFuncAttributeMaxDynamicSharedMemorySize, (int)smem);
        attn_kernel<<<dim3(SEQ / 64, HEADS), 256, smem>>>(cu, ncu);
    }

    // 4) Output projection + bias
    sgemm_bias_kernel<<<dim3(DIM / 128, SEQ / 128), 256>>>(
        attn_ptr, proj_w, proj_b, out, SEQ, DIM, DIM);
}

// round 3
// speedup vs baseline: 1.8312x; 1.5790x over previous
#include <cuda_runtime.h>
#include <cuda_bf16.h>
#include <math.h>
#include <stdint.h>

#define SEQ      2048
#define DIM      1280
#define HEADS    16
#define HEAD_DIM 80
#define QKV_DIM  3840   // 3 * DIM
#define K3       3840   // 3 * DIM (split-K concat)

// ---------------------------------------------------------------------------
// Scratch (__device__ globals; no cudaMalloc allowed)
// ---------------------------------------------------------------------------
__device__ float g_qkv[SEQ * QKV_DIM];            // QKV output (S,3,H,D)
__device__ float g_attn[SEQ * DIM];               // attention out pre-proj
__device__ __nv_bfloat16 g_Ah[SEQ * K3];          // hidden decomp  [hi|hi|lo]
__device__ __nv_bfloat16 g_Wq[QKV_DIM * K3];      // qkv_w decomp   [hi|lo|hi]
__device__ __nv_bfloat16 g_Wp[DIM * K3];          // proj_w decomp  [hi|lo|hi]
__device__ __nv_bfloat16 g_At[SEQ * K3];          // attn decomp    [hi|hi|lo]

// ---------------------------------------------------------------------------
// Decomposition kernels: fp32 [R][DIM] -> bf16 [R][3*DIM]
// A-type layout: [hi | hi | lo]   B-type layout: [hi | lo | hi]
// ---------------------------------------------------------------------------
__global__ void __launch_bounds__(256) decomp_kernel(
    const float* __restrict__ in, __nv_bfloat16* __restrict__ out,
    int total, int K, int loSlot /* 2 for A-type, 1 for B-type */)
{
    int idx = blockIdx.x * blockDim.x + threadIdx.x;
    if (idx >= total) return;
    int r = idx / K;
    int k = idx - r * K;
    float x = in[idx];
    __nv_bfloat16 hi = __float2bfloat16(x);
    __nv_bfloat16 lo = __float2bfloat16(x - __bfloat162float(hi));
    size_t base = (size_t)r * (3 * K) + k;
    out[base + 0 * K] = hi;
    out[base + 1 * K] = (loSlot == 1) ? lo : hi;
    out[base + 2 * K] = (loSlot == 2) ? lo : hi;
}

// ---------------------------------------------------------------------------
// bf16 HGEMM (TN): C[M][N] = A[M][K] @ B[N][K]^T + bias[N], fp32 accumulate.
// 128x128 block, KBLK=32, 8 warps (2x4), warp tile 64x32, mma.m16n8k16.
// cp.async double-buffered smem, ldmatrix with 40-elem padded rows.
// Requires M%128==0, N%128==0, K%32==0.
// ---------------------------------------------------------------------------
#define KBLK 32
#define KPAD 40

#define CP_ASYNC16(dst, src) \
    asm volatile("cp.async.cg.shared.global [%0], [%1], 16;" :: "r"(dst), "l"(src))
#define CP_COMMIT() asm volatile("cp.async.commit_group;")
#define CP_WAIT0()  asm volatile("cp.async.wait_group 0;")

#define LDSM_X4(r0,r1,r2,r3,addr) \
    asm volatile("ldmatrix.sync.aligned.m8n8.x4.shared.b16 {%0,%1,%2,%3}, [%4];" \
        : "=r"(r0),"=r"(r1),"=r"(r2),"=r"(r3) : "r"(addr))
#define LDSM_X2(r0,r1,addr) \
    asm volatile("ldmatrix.sync.aligned.m8n8.x2.shared.b16 {%0,%1}, [%2];" \
        : "=r"(r0),"=r"(r1) : "r"(addr))

#define MMA16816(c0,c1,c2,c3,a0,a1,a2,a3,b0,b1) \
    asm volatile("mma.sync.aligned.m16n8k16.row.col.f32.bf16.bf16.f32 " \
        "{%0,%1,%2,%3}, {%4,%5,%6,%7}, {%8,%9}, {%0,%1,%2,%3};" \
        : "+f"(c0),"+f"(c1),"+f"(c2),"+f"(c3) \
        : "r"(a0),"r"(a1),"r"(a2),"r"(a3),"r"(b0),"r"(b1))

__global__ void __launch_bounds__(256, 2) hgemm_bias_kernel(
    const __nv_bfloat16* __restrict__ A, const __nv_bfloat16* __restrict__ B,
    const float* __restrict__ bias, float* __restrict__ C,
    int M, int N, int K)
{
    __shared__ __nv_bfloat16 As[2][128][KPAD];
    __shared__ __nv_bfloat16 Bs[2][128][KPAD];

    const int tid = threadIdx.x;
    const int ln  = tid & 31;
    const int wid = tid >> 5;       // 0..7
    const int wm  = wid & 1;        // m half
    const int wn  = wid >> 1;       // n quarter
    const int m0  = blockIdx.y * 128;
    const int n0  = blockIdx.x * 128;

    const uint32_t sA = (uint32_t)__cvta_generic_to_shared(&As[0][0][0]);
    const uint32_t sB = (uint32_t)__cvta_generic_to_shared(&Bs[0][0][0]);
    const uint32_t STAGE = 128 * KPAD * 2;   // bytes per buffer

    // Loader mapping: 2 chunks of 16B per thread per tile
    const int lrow0 = tid >> 2;              // e = tid      -> row 0..63
    const int lrow1 = (tid + 256) >> 2;      // e = tid+256  -> row 64..127
    const int lch   = (tid & 3);             // 16B chunk within 64B row slab
    const int lcol  = lch * 8;               // bf16 col

    float acc[4][4][4];
    #pragma unroll
    for (int mi = 0; mi < 4; mi++)
        #pragma unroll
        for (int ni = 0; ni < 4; ni++)
            #pragma unroll
            for (int c = 0; c < 4; c++) acc[mi][ni][c] = 0.f;

    // --- stage 0 loads ---
    {
        CP_ASYNC16(sA + (uint32_t)(lrow0 * KPAD + lcol) * 2,
                   A + (size_t)(m0 + lrow0) * K + lcol);
        CP_ASYNC16(sA + (uint32_t)(lrow1 * KPAD + lcol) * 2,
                   A + (size_t)(m0 + lrow1) * K + lcol);
        CP_ASYNC16(sB + (uint32_t)(lrow0 * KPAD + lcol) * 2,
                   B + (size_t)(n0 + lrow0) * K + lcol);
        CP_ASYNC16(sB + (uint32_t)(lrow1 * KPAD + lcol) * 2,
                   B + (size_t)(n0 + lrow1) * K + lcol);
        CP_COMMIT();
        CP_WAIT0();
        __syncthreads();
    }

    // ldmatrix lane addressing (within a buffer)
    const int a_row = (ln & 15);                 // + m-tile base
    const int a_kof = (ln < 16) ? 0 : 8;
    const int b_row = (ln & 7);                  // + n-tile base
    const int b_kof = (ln & 8);

    int buf = 0;
    for (int kt = 0; kt < K; kt += KBLK) {
        const bool hasNext = (kt + KBLK) < K;
        if (hasNext) {
            const int kn = kt + KBLK;
            const uint32_t db = (buf ^ 1) * STAGE;
            CP_ASYNC16(sA + db + (uint32_t)(lrow0 * KPAD + lcol) * 2,
                       A + (size_t)(m0 + lrow0) * K + kn + lcol);
            CP_ASYNC16(sA + db + (uint32_t)(lrow1 * KPAD + lcol) * 2,
                       A + (size_t)(m0 + lrow1) * K + kn + lcol);
            CP_ASYNC16(sB + db + (uint32_t)(lrow0 * KPAD + lcol) * 2,
                       B + (size_t)(n0 + lrow0) * K + kn + lcol);
            CP_ASYNC16(sB + db + (uint32_t)(lrow1 * KPAD + lcol) * 2,
                       B + (size_t)(n0 + lrow1) * K + kn + lcol);
            CP_COMMIT();
        }

        const uint32_t bA = sA + buf * STAGE;
        const uint32_t bBm = sB + buf * STAGE;

        #pragma unroll
        for (int ks = 0; ks < 2; ks++) {
            const int k0 = ks * 16;
            uint32_t af[4][4];
            #pragma unroll
            for (int mi = 0; mi < 4; mi++) {
                int row = wm * 64 + mi * 16 + a_row;
                uint32_t addr = bA + (uint32_t)(row * KPAD + k0 + a_kof) * 2;
                LDSM_X4(af[mi][0], af[mi][1], af[mi][2], af[mi][3], addr);
            }
            uint32_t bfr[4][2];
            #pragma unroll
            for (int ni = 0; ni < 4; ni++) {
                int row = wn * 32 + ni * 8 + b_row;
                uint32_t addr = bBm + (uint32_t)(row * KPAD + k0 + b_kof) * 2;
                LDSM_X2(bfr[ni][0], bfr[ni][1], addr);
            }
            #pragma unroll
            for (int mi = 0; mi < 4; mi++)
                #pragma unroll
                for (int ni = 0; ni < 4; ni++)
                    MMA16816(acc[mi][ni][0], acc[mi][ni][1],
                             acc[mi][ni][2], acc[mi][ni][3],
                             af[mi][0], af[mi][1], af[mi][2], af[mi][3],
                             bfr[ni][0], bfr[ni][1]);
        }

        if (hasNext) {
            CP_WAIT0();
            __syncthreads();
            buf ^= 1;
        }
    }

    // Epilogue: c-fragment (ln/4, 2*(ln%4)) + bias, float2 stores
    const int crow = ln >> 2;
    const int ccol = (ln & 3) * 2;
    #pragma unroll
    for (int mi = 0; mi < 4; mi++) {
        #pragma unroll
        for (int ni = 0; ni < 4; ni++) {
            int col = n0 + wn * 32 + ni * 8 + ccol;
            float b0 = bias[col], b1 = bias[col + 1];
            int r0 = m0 + wm * 64 + mi * 16 + crow;
            float2 v0 = make_float2(acc[mi][ni][0] + b0, acc[mi][ni][1] + b1);
            float2 v1 = make_float2(acc[mi][ni][2] + b0, acc[mi][ni][3] + b1);
            *(float2*)(C + (size_t)r0 * N + col)       = v0;
            *(float2*)(C + (size_t)(r0 + 8) * N + col) = v1;
        }
    }
}

// ---------------------------------------------------------------------------
// RoPE (vision variant) in-place on q (part 0) and k (part 1).
// ---------------------------------------------------------------------------
__global__ void __launch_bounds__(256) rope_kernel(const float* __restrict__ rot)
{
    int t = blockIdx.x * blockDim.x + threadIdx.x;
    const int total = SEQ * 2 * HEADS * (HEAD_DIM / 2);
    if (t >= total) return;

    int d2   = t % 40;
    int h    = (t / 40) % HEADS;
    int part = (t / (40 * HEADS)) % 2;
    int s    = t / (40 * HEADS * 2);

    float f = rot[s * 40 + d2];
    float si, co;
    sincosf(f, &si, &co);

    size_t base = (size_t)s * QKV_DIM + (size_t)part * DIM + h * HEAD_DIM;
    float x1 = g_qkv[base + d2];
    float x2 = g_qkv[base + 40 + d2];
    g_qkv[base + d2]      = x1 * co - x2 * si;
    g_qkv[base + 40 + d2] = x2 * co + x1 * si;
}

// ---------------------------------------------------------------------------
// Fused flash attention with block-diagonal (segment) masking. (unchanged)
// ---------------------------------------------------------------------------
#define QK_STRIDE 81
#define SS_STRIDE 65

__global__ void __launch_bounds__(256) attn_kernel(const int* __restrict__ cu, int ncu)
{
    extern __shared__ float sm[];
    float* Qs  = sm;
    float* KVs = Qs + 64 * QK_STRIDE;
    float* Ss  = KVs + 64 * QK_STRIDE;
    int*   segq  = (int*)(Ss + 64 * SS_STRIDE);
    int*   segk  = segq + 64;
    int*   range = segk + 64;

    int tid = threadIdx.x;
    int ty = tid >> 4;
    int tx = tid & 15;
    int head  = blockIdx.y;
    int qbase = blockIdx.x * 64;
    const float scale = rsqrtf((float)HEAD_DIM);

    #pragma unroll
    for (int i = 0; i < 20; i++) {
        int e = tid + i * 256;
        int r = e / HEAD_DIM, d = e % HEAD_DIM;
        Qs[r * QK_STRIDE + d] =
            g_qkv[(size_t)(qbase + r) * QKV_DIM + head * HEAD_DIM + d] * scale;
    }
    if (tid < 64) {
        int i = qbase + tid;
        int s = 0;
        for (int j = 1; j < ncu; j++) s += (cu[j] <= i);
        segq[tid] = s;
    }
    __syncthreads();
    if (tid == 0) {
        int smin = segq[0], smax = segq[0];
        for (int r = 1; r < 64; r++) {
            smin = min(smin, segq[r]);
            smax = max(smax, segq[r]);
        }
        range[0] = cu[smin];
        range[1] = cu[smax + 1];
    }
    __syncthreads();
    int lo = range[0], hi = range[1];

    float m_i[4], l_i[4], acc[4][5];
    int myseg[4];
    #pragma unroll
    for (int i = 0; i < 4; i++) {
        m_i[i] = -1e30f;
        l_i[i] = 0.f;
        myseg[i] = segq[ty * 4 + i];
        #pragma unroll
        for (int j = 0; j < 5; j++) acc[i][j] = 0.f;
    }

    for (int kt = lo; kt < hi; kt += 64) {
        #pragma unroll
        for (int i = 0; i < 20; i++) {
            int e = tid + i * 256;
            int r = e / HEAD_DIM, d = e % HEAD_DIM;
            int key = kt + r;
            KVs[r * QK_STRIDE + d] = (key < hi)
                ? g_qkv[(size_t)key * QKV_DIM + DIM + head * HEAD_DIM + d] : 0.f;
        }
        if (tid < 64) {
            int key = kt + tid;
            int s = -1;
            if (key < hi) {
                s = 0;
                for (int j = 1; j < ncu; j++) s += (cu[j] <= key);
            }
            segk[tid] = s;
        }
        __syncthreads();

        float sf[4][4];
        #pragma unroll
        for (int i = 0; i < 4; i++)
            #pragma unroll
            for (int j = 0; j < 4; j++) sf[i][j] = 0.f;

        for (int d = 0; d < HEAD_DIM; d++) {
            float qv[4], kv[4];
            #pragma unroll
            for (int i = 0; i < 4; i++) qv[i] = Qs[(ty * 4 + i) * QK_STRIDE + d];
            #pragma unroll
            for (int j = 0; j < 4; j++) kv[j] = KVs[(tx * 4 + j) * QK_STRIDE + d];
            #pragma unroll
            for (int i = 0; i < 4; i++)
                #pragma unroll
                for (int j = 0; j < 4; j++)
                    sf[i][j] += qv[i] * kv[j];
        }

        #pragma unroll
        for (int i = 0; i < 4; i++) {
            int sq = myseg[i];
            float tmax = -1e30f;
            #pragma unroll
            for (int j = 0; j < 4; j++) {
                if (segk[tx * 4 + j] != sq) sf[i][j] = -1e30f;
                tmax = fmaxf(tmax, sf[i][j]);
            }
            #pragma unroll
            for (int msk = 8; msk >= 1; msk >>= 1)
                tmax = fmaxf(tmax, __shfl_xor_sync(0xffffffffu, tmax, msk));

            float mnew  = fmaxf(m_i[i], tmax);
            float alpha = expf(m_i[i] - mnew);
            float psum  = 0.f;
            #pragma unroll
            for (int j = 0; j < 4; j++) {
                float p = expf(sf[i][j] - mnew);
                Ss[(ty * 4 + i) * SS_STRIDE + tx * 4 + j] = p;
                psum += p;
            }
            #pragma unroll
            for (int msk = 8; msk >= 1; msk >>= 1)
                psum += __shfl_xor_sync(0xffffffffu, psum, msk);

            l_i[i] = l_i[i] * alpha + psum;
            m_i[i] = mnew;
            #pragma unroll
            for (int j = 0; j < 5; j++) acc[i][j] *= alpha;
        }
        __syncthreads();

        #pragma unroll
        for (int i = 0; i < 20; i++) {
            int e = tid + i * 256;
            int r = e / HEAD_DIM, d = e % HEAD_DIM;
            int key = kt + r;
            KVs[r * QK_STRIDE + d] = (key < hi)
                ? g_qkv[(size_t)key * QKV_DIM + 2 * DIM + head * HEAD_DIM + d] : 0.f;
        }
        __syncthreads();

        for (int k = 0; k < 64; k++) {
            float vv[5];
            #pragma unroll
            for (int j = 0; j < 5; j++) vv[j] = KVs[k * QK_STRIDE + tx + 16 * j];
            #pragma unroll
            for (int i = 0; i < 4; i++) {
                float p = Ss[(ty * 4 + i) * SS_STRIDE + k];
                #pragma unroll
                for (int j = 0; j < 5; j++) acc[i][j] += p * vv[j];
            }
        }
        __syncthreads();
    }

    #pragma unroll
    for (int i = 0; i < 4; i++) {
        float invl = (l_i[i] > 0.f) ? (1.f / l_i[i]) : 0.f;
        int row = qbase + ty * 4 + i;
        #pragma unroll
        for (int j = 0; j < 5; j++) {
            int col = tx + 16 * j;
            g_attn[(size_t)row * DIM + head * HEAD_DIM + col] = acc[i][j] * invl;
        }
    }
}

// ---------------------------------------------------------------------------
extern "C" void kernel_launch(void* const* d_in, const int* in_sizes, int n_in,
                              void* d_out, int out_size)
{
    const float* hidden = (const float*)d_in[0];
    const float* rotary = (const float*)d_in[1];
    const int*   cu     = (const int*)d_in[2];
    const float* qkv_w  = (const float*)d_in[3];
    const float* qkv_b  = (const float*)d_in[4];
    const float* proj_w = (const float*)d_in[5];
    const float* proj_b = (const float*)d_in[6];
    float* out = (float*)d_out;
    int ncu = in_sizes[2];

    float *qkv_ptr = nullptr, *attn_ptr = nullptr;
    __nv_bfloat16 *Ah, *Wq, *Wp, *At;
    cudaGetSymbolAddress((void**)&qkv_ptr, g_qkv);
    cudaGetSymbolAddress((void**)&attn_ptr, g_attn);
    cudaGetSymbolAddress((void**)&Ah, g_Ah);
    cudaGetSymbolAddress((void**)&Wq, g_Wq);
    cudaGetSymbolAddress((void**)&Wp, g_Wp);
    cudaGetSymbolAddress((void**)&At, g_At);

    // 0) Decompose fp32 -> bf16 hi/lo concatenated-K layouts
    {
        int tA = SEQ * DIM;
        decomp_kernel<<<(tA + 255) / 256, 256>>>(hidden, Ah, tA, DIM, 2);
        int tWq = QKV_DIM * DIM;
        decomp_kernel<<<(tWq + 255) / 256, 256>>>(qkv_w, Wq, tWq, DIM, 1);
        int tWp = DIM * DIM;
        decomp_kernel<<<(tWp + 255) / 256, 256>>>(proj_w, Wp, tWp, DIM, 1);
    }

    // 1) QKV GEMM + bias (bf16x3 tensor-core path)
    hgemm_bias_kernel<<<dim3(QKV_DIM / 128, SEQ / 128), 256>>>(
        Ah, Wq, qkv_b, qkv_ptr, SEQ, QKV_DIM, K3);

    // 2) RoPE in-place on q, k
    {
        int total = SEQ * 2 * HEADS * (HEAD_DIM / 2);
        rope_kernel<<<(total + 255) / 256, 256>>>(rotary);
    }

    // 3) Fused segment-masked flash attention
    {
        size_t smem = (size_t)(2 * 64 * QK_STRIDE + 64 * SS_STRIDE) * sizeof(float)
                    + 130 * sizeof(int);
        cudaFuncSetAttribute(attn_kernel,
                             cudaFuncAttributeMaxDynamicSharedMemorySize, (int)smem);
        attn_kernel<<<dim3(SEQ / 64, HEADS), 256, smem>>>(cu, ncu);
    }

    // 4) Decompose attention output, then proj GEMM + bias
    {
        int tA = SEQ * DIM;
        decomp_kernel<<<(tA + 255) / 256, 256>>>(attn_ptr, At, tA, DIM, 2);
    }
    hgemm_bias_kernel<<<dim3(DIM / 128, SEQ / 128), 256>>>(
        At, Wp, proj_b, out, SEQ, DIM, K3);
}

// round 5
// speedup vs baseline: 2.3618x; 1.2898x over previous
#include <cuda_runtime.h>
#include <cuda_bf16.h>
#include <math.h>
#include <stdint.h>

#define SEQ      2048
#define DIM      1280
#define HEADS    16
#define HEAD_DIM 80
#define QKV_DIM  3840
#define K3       3840

// ---------------------------------------------------------------------------
// Scratch
// ---------------------------------------------------------------------------
__device__ float g_qkv[SEQ * QKV_DIM];
__device__ float g_attn[SEQ * DIM];
__device__ __nv_bfloat16 g_Ah[SEQ * K3];          // hidden decomp  [hi|hi|lo]
__device__ __nv_bfloat16 g_Wq[QKV_DIM * K3];      // qkv_w decomp   [hi|lo|hi]
__device__ __nv_bfloat16 g_Wp[DIM * K3];          // proj_w decomp  [hi|lo|hi]
__device__ __nv_bfloat16 g_At[SEQ * K3];          // attn decomp    [hi|hi|lo]

// ---------------------------------------------------------------------------
// Common PTX helpers (non-'a' features only: cp.async, ldmatrix, mma.sync)
// ---------------------------------------------------------------------------
#define CP_ASYNC16(dst, src) \
    asm volatile("cp.async.cg.shared.global [%0], [%1], 16;" :: "r"(dst), "l"(src))
#define CP_COMMIT() asm volatile("cp.async.commit_group;")
#define CP_WAIT0()  asm volatile("cp.async.wait_group 0;")

#define LDSM_X4(r0,r1,r2,r3,addr) \
    asm volatile("ldmatrix.sync.aligned.m8n8.x4.shared.b16 {%0,%1,%2,%3}, [%4];" \
        : "=r"(r0),"=r"(r1),"=r"(r2),"=r"(r3) : "r"(addr))
#define LDSM_X2(r0,r1,addr) \
    asm volatile("ldmatrix.sync.aligned.m8n8.x2.shared.b16 {%0,%1}, [%2];" \
        : "=r"(r0),"=r"(r1) : "r"(addr))

#define MMA16816(c0,c1,c2,c3,a0,a1,a2,a3,b0,b1) \
    asm volatile("mma.sync.aligned.m16n8k16.row.col.f32.bf16.bf16.f32 " \
        "{%0,%1,%2,%3}, {%4,%5,%6,%7}, {%8,%9}, {%0,%1,%2,%3};" \
        : "+f"(c0),"+f"(c1),"+f"(c2),"+f"(c3) \
        : "r"(a0),"r"(a1),"r"(a2),"r"(a3),"r"(b0),"r"(b1))

__device__ __forceinline__ uint32_t smem_u32(const void* p) {
    return (uint32_t)__cvta_generic_to_shared(p);
}
__device__ __forceinline__ uint32_t pack_bf2(float a, float b) {
    __nv_bfloat162 v = __float22bfloat162_rn(make_float2(a, b));
    return *(uint32_t*)&v;
}

// ---------------------------------------------------------------------------
// bf16 HGEMM (TN): C = A[M,K] @ B[N,K]^T + bias, fp32 accum. (round-3, proven)
// ---------------------------------------------------------------------------
#define KBLK 32
#define KPAD 40

__global__ void __launch_bounds__(256, 2) hgemm_bias_kernel(
    const __nv_bfloat16* __restrict__ A, const __nv_bfloat16* __restrict__ B,
    const float* __restrict__ bias, float* __restrict__ C,
    int M, int N, int K)
{
    __shared__ __nv_bfloat16 As[2][128][KPAD];
    __shared__ __nv_bfloat16 Bs[2][128][KPAD];

    const int tid = threadIdx.x;
    const int ln  = tid & 31;
    const int wid = tid >> 5;
    const int wm  = wid & 1;
    const int wn  = wid >> 1;
    const int m0  = blockIdx.y * 128;
    const int n0  = blockIdx.x * 128;

    const uint32_t sA = smem_u32(&As[0][0][0]);
    const uint32_t sB = smem_u32(&Bs[0][0][0]);
    const uint32_t STAGE = 128 * KPAD * 2;

    const int lrow0 = tid >> 2;
    const int lrow1 = (tid + 256) >> 2;
    const int lcol  = (tid & 3) * 8;

    float acc[4][4][4];
    #pragma unroll
    for (int mi = 0; mi < 4; mi++)
        #pragma unroll
        for (int ni = 0; ni < 4; ni++)
            #pragma unroll
            for (int c = 0; c < 4; c++) acc[mi][ni][c] = 0.f;

    CP_ASYNC16(sA + (uint32_t)(lrow0 * KPAD + lcol) * 2, A + (size_t)(m0 + lrow0) * K + lcol);
    CP_ASYNC16(sA + (uint32_t)(lrow1 * KPAD + lcol) * 2, A + (size_t)(m0 + lrow1) * K + lcol);
    CP_ASYNC16(sB + (uint32_t)(lrow0 * KPAD + lcol) * 2, B + (size_t)(n0 + lrow0) * K + lcol);
    CP_ASYNC16(sB + (uint32_t)(lrow1 * KPAD + lcol) * 2, B + (size_t)(n0 + lrow1) * K + lcol);
    CP_COMMIT();
    CP_WAIT0();
    __syncthreads();

    const int a_row = (ln & 15);
    const int a_kof = (ln < 16) ? 0 : 8;
    const int b_row = (ln & 7);
    const int b_kof = (ln & 8);

    int buf = 0;
    for (int kt = 0; kt < K; kt += KBLK) {
        const bool hasNext = (kt + KBLK) < K;
        if (hasNext) {
            const int kn = kt + KBLK;
            const uint32_t db = (buf ^ 1) * STAGE;
            CP_ASYNC16(sA + db + (uint32_t)(lrow0 * KPAD + lcol) * 2,
                       A + (size_t)(m0 + lrow0) * K + kn + lcol);
            CP_ASYNC16(sA + db + (uint32_t)(lrow1 * KPAD + lcol) * 2,
                       A + (size_t)(m0 + lrow1) * K + kn + lcol);
            CP_ASYNC16(sB + db + (uint32_t)(lrow0 * KPAD + lcol) * 2,
                       B + (size_t)(n0 + lrow0) * K + kn + lcol);
            CP_ASYNC16(sB + db + (uint32_t)(lrow1 * KPAD + lcol) * 2,
                       B + (size_t)(n0 + lrow1) * K + kn + lcol);
            CP_COMMIT();
        }

        const uint32_t bA = sA + buf * STAGE;
        const uint32_t bBm = sB + buf * STAGE;

        #pragma unroll
        for (int ks = 0; ks < 2; ks++) {
            const int k0 = ks * 16;
            uint32_t af[4][4];
            #pragma unroll
            for (int mi = 0; mi < 4; mi++) {
                int row = wm * 64 + mi * 16 + a_row;
                LDSM_X4(af[mi][0], af[mi][1], af[mi][2], af[mi][3],
                        bA + (uint32_t)(row * KPAD + k0 + a_kof) * 2);
            }
            uint32_t bfr[4][2];
            #pragma unroll
            for (int ni = 0; ni < 4; ni++) {
                int row = wn * 32 + ni * 8 + b_row;
                LDSM_X2(bfr[ni][0], bfr[ni][1],
                        bBm + (uint32_t)(row * KPAD + k0 + b_kof) * 2);
            }
            #pragma unroll
            for (int mi = 0; mi < 4; mi++)
                #pragma unroll
                for (int ni = 0; ni < 4; ni++)
                    MMA16816(acc[mi][ni][0], acc[mi][ni][1],
                             acc[mi][ni][2], acc[mi][ni][3],
                             af[mi][0], af[mi][1], af[mi][2], af[mi][3],
                             bfr[ni][0], bfr[ni][1]);
        }

        if (hasNext) {
            CP_WAIT0();
            __syncthreads();
            buf ^= 1;
        }
    }

    const int crow = ln >> 2;
    const int ccol = (ln & 3) * 2;
    #pragma unroll
    for (int mi = 0; mi < 4; mi++) {
        #pragma unroll
        for (int ni = 0; ni < 4; ni++) {
            int col = n0 + wn * 32 + ni * 8 + ccol;
            float b0 = bias[col], b1 = bias[col + 1];
            int r0 = m0 + wm * 64 + mi * 16 + crow;
            float2 v0 = make_float2(acc[mi][ni][0] + b0, acc[mi][ni][1] + b1);
            float2 v1 = make_float2(acc[mi][ni][2] + b0, acc[mi][ni][3] + b1);
            *(float2*)(C + (size_t)r0 * N + col)       = v0;
            *(float2*)(C + (size_t)(r0 + 8) * N + col) = v1;
        }
    }
}

// ---------------------------------------------------------------------------
// Decompose fp32 [R][K] -> bf16 [R][3K];  A-type loSlot=2, B-type loSlot=1
// ---------------------------------------------------------------------------
__global__ void __launch_bounds__(256) decomp_kernel(
    const float* __restrict__ in, __nv_bfloat16* __restrict__ out,
    int total, int K, int loSlot)
{
    int idx = blockIdx.x * blockDim.x + threadIdx.x;
    if (idx >= total) return;
    int r = idx / K;
    int k = idx - r * K;
    float x = in[idx];
    __nv_bfloat16 hi = __float2bfloat16(x);
    __nv_bfloat16 lo = __float2bfloat16(x - __bfloat162float(hi));
    size_t base = (size_t)r * (3 * K) + k;
    out[base + 0 * K] = hi;
    out[base + 1 * K] = (loSlot == 1) ? lo : hi;
    out[base + 2 * K] = (loSlot == 2) ? lo : hi;
}

// ---------------------------------------------------------------------------
// RoPE in-place on q, k
// ---------------------------------------------------------------------------
__global__ void __launch_bounds__(256) rope_kernel(const float* __restrict__ rot)
{
    int t = blockIdx.x * blockDim.x + threadIdx.x;
    const int total = SEQ * 2 * HEADS * (HEAD_DIM / 2);
    if (t >= total) return;
    int d2   = t % 40;
    int h    = (t / 40) % HEADS;
    int part = (t / (40 * HEADS)) % 2;
    int s    = t / (40 * HEADS * 2);
    float f = rot[s * 40 + d2];
    float si, co;
    sincosf(f, &si, &co);
    size_t base = (size_t)s * QKV_DIM + (size_t)part * DIM + h * HEAD_DIM;
    float x1 = g_qkv[base + d2];
    float x2 = g_qkv[base + 40 + d2];
    g_qkv[base + d2]      = x1 * co - x2 * si;
    g_qkv[base + 40 + d2] = x2 * co + x1 * si;
}

// ---------------------------------------------------------------------------
// Tensor-core flash attention, bf16 3-term split, segment-masked.
// Block = (head, 128 queries), 8 warps; warp w owns query rows [16w,16w+16).
// K iterated in 64-key tiles. S = Q@K^T and O += P@V on mma.m16n8k16.
// ---------------------------------------------------------------------------
#define AQ   128
#define AK   64
#define QSTR 88    // bf16 stride for Q/K planes (conflict-free ldmatrix)
#define VSTR 72    // bf16 stride for V^T planes

#define FA_SMEM ((2*AQ*QSTR + 2*AK*QSTR + 2*HEAD_DIM*VSTR) * 2 + (AQ + AK + 4) * 4)

__global__ void __launch_bounds__(256) fattn_kernel(const int* __restrict__ cu, int ncu)
{
    extern __shared__ char smraw[];
    __nv_bfloat16* Qh = (__nv_bfloat16*)smraw;
    __nv_bfloat16* Ql = Qh + AQ * QSTR;
    __nv_bfloat16* Kh = Ql + AQ * QSTR;
    __nv_bfloat16* Kl = Kh + AK * QSTR;
    __nv_bfloat16* Vh = Kl + AK * QSTR;       // transposed: [d][key]
    __nv_bfloat16* Vl = Vh + HEAD_DIM * VSTR;
    int* segq  = (int*)(Vl + HEAD_DIM * VSTR);
    int* segk  = segq + AQ;
    int* range = segk + AK;

    const int tid = threadIdx.x;
    const int w   = tid >> 5;
    const int ln  = tid & 31;
    const int head  = blockIdx.y;
    const int qbase = blockIdx.x * AQ;
    const float scale = rsqrtf((float)HEAD_DIM);

    // ---- load Q (scaled) as hi/lo bf16 planes ----
    #pragma unroll
    for (int i = 0; i < 40; i++) {
        int idx = tid + i * 256;
        int r = idx / HEAD_DIM, d = idx - r * HEAD_DIM;
        float v = g_qkv[(size_t)(qbase + r) * QKV_DIM + head * HEAD_DIM + d] * scale;
        __nv_bfloat16 hi = __float2bfloat16(v);
        Qh[r * QSTR + d] = hi;
        Ql[r * QSTR + d] = __float2bfloat16(v - __bfloat162float(hi));
    }
    if (tid < AQ) {
        int i = qbase + tid;
        int s = 0;
        for (int j = 1; j < ncu; j++) s += (cu[j] <= i);
        segq[tid] = s;
    }
    __syncthreads();
    if (tid == 0) {
        int smin = segq[0], smax = segq[0];
        for (int r = 1; r < AQ; r++) { smin = min(smin, segq[r]); smax = max(smax, segq[r]); }
        range[0] = cu[smin];
        range[1] = cu[smax + 1];
    }
    __syncthreads();
    const int lo = range[0], hi_ = range[1];

    // per-thread row state (rows row0 = 16w + ln/4, row1 = row0 + 8)
    const int qr = ln >> 2;
    const int kq = (ln & 3) * 2;
    const int row0 = w * 16 + qr;
    const int row1 = row0 + 8;
    const int sq0 = segq[row0], sq1 = segq[row1];

    float m0 = -1e30f, m1 = -1e30f, l0 = 0.f, l1 = 0.f;
    float acc[10][4];
    #pragma unroll
    for (int n = 0; n < 10; n++)
        #pragma unroll
        for (int c = 0; c < 4; c++) acc[n][c] = 0.f;

    const int a_row = (ln & 15);
    const int a_kof = (ln < 16) ? 0 : 8;
    const int b_row = (ln & 7);
    const int b_kof = (ln & 8);

    for (int kt = lo; kt < hi_; kt += AK) {
        __syncthreads();   // previous tile's smem reads done before overwrite
        // ---- load K (hi/lo) and V^T (hi/lo) ----
        #pragma unroll
        for (int i = 0; i < 20; i++) {
            int idx = tid + i * 256;
            int r = idx / HEAD_DIM, d = idx - r * HEAD_DIM;
            int key = kt + r;
            float kv = 0.f, vv = 0.f;
            if (key < hi_) {
                size_t base = (size_t)key * QKV_DIM + head * HEAD_DIM + d;
                kv = g_qkv[base + DIM];
                vv = g_qkv[base + 2 * DIM];
            }
            __nv_bfloat16 kh = __float2bfloat16(kv);
            Kh[r * QSTR + d] = kh;
            Kl[r * QSTR + d] = __float2bfloat16(kv - __bfloat162float(kh));
            __nv_bfloat16 vh = __float2bfloat16(vv);
            Vh[d * VSTR + r] = vh;
            Vl[d * VSTR + r] = __float2bfloat16(vv - __bfloat162float(vh));
        }
        if (tid < AK) {
            int key = kt + tid;
            int s = -1;
            if (key < hi_) {
                s = 0;
                for (int j = 1; j < ncu; j++) s += (cu[j] <= key);
            }
            segk[tid] = s;
        }
        __syncthreads();

        // ---- S = Q @ K^T, 3-term split ----
        float S[8][4];
        #pragma unroll
        for (int j = 0; j < 8; j++)
            #pragma unroll
            for (int c = 0; c < 4; c++) S[j][c] = 0.f;

        #pragma unroll
        for (int kc = 0; kc < 5; kc++) {
            uint32_t ah[4], al[4];
            uint32_t qoff = (uint32_t)((w * 16 + a_row) * QSTR + kc * 16 + a_kof) * 2;
            LDSM_X4(ah[0], ah[1], ah[2], ah[3], smem_u32(Qh) + qoff);
            LDSM_X4(al[0], al[1], al[2], al[3], smem_u32(Ql) + qoff);
            #pragma unroll
            for (int j = 0; j < 8; j++) {
                uint32_t bh[2], bl[2];
                uint32_t koff = (uint32_t)((j * 8 + b_row) * QSTR + kc * 16 + b_kof) * 2;
                LDSM_X2(bh[0], bh[1], smem_u32(Kh) + koff);
                LDSM_X2(bl[0], bl[1], smem_u32(Kl) + koff);
                MMA16816(S[j][0], S[j][1], S[j][2], S[j][3],
                         ah[0], ah[1], ah[2], ah[3], bh[0], bh[1]);
                MMA16816(S[j][0], S[j][1], S[j][2], S[j][3],
                         ah[0], ah[1], ah[2], ah[3], bl[0], bl[1]);
                MMA16816(S[j][0], S[j][1], S[j][2], S[j][3],
                         al[0], al[1], al[2], al[3], bh[0], bh[1]);
            }
        }

        // ---- masked online softmax (rows fully within warp) ----
        float mt0 = -1e30f, mt1 = -1e30f;
        #pragma unroll
        for (int j = 0; j < 8; j++) {
            int k0 = j * 8 + kq;
            int sk0 = segk[k0], sk1 = segk[k0 + 1];
            mt0 = fmaxf(mt0, (sk0 == sq0) ? S[j][0] : -1e30f);
            mt0 = fmaxf(mt0, (sk1 == sq0) ? S[j][1] : -1e30f);
            mt1 = fmaxf(mt1, (sk0 == sq1) ? S[j][2] : -1e30f);
            mt1 = fmaxf(mt1, (sk1 == sq1) ? S[j][3] : -1e30f);
        }
        #pragma unroll
        for (int msk = 1; msk <= 2; msk <<= 1) {
            mt0 = fmaxf(mt0, __shfl_xor_sync(0xffffffffu, mt0, msk));
            mt1 = fmaxf(mt1, __shfl_xor_sync(0xffffffffu, mt1, msk));
        }
        float mn0 = fmaxf(m0, mt0), mn1 = fmaxf(m1, mt1);
        float alpha0 = __expf(m0 - mn0), alpha1 = __expf(m1 - mn1);
        float rs0 = 0.f, rs1 = 0.f;
        #pragma unroll
        for (int j = 0; j < 8; j++) {
            int k0 = j * 8 + kq;
            int sk0 = segk[k0], sk1 = segk[k0 + 1];
            float p0 = (sk0 == sq0) ? __expf(S[j][0] - mn0) : 0.f;
            float p1 = (sk1 == sq0) ? __expf(S[j][1] - mn0) : 0.f;
            float p2 = (sk0 == sq1) ? __expf(S[j][2] - mn1) : 0.f;
            float p3 = (sk1 == sq1) ? __expf(S[j][3] - mn1) : 0.f;
            S[j][0] = p0; S[j][1] = p1; S[j][2] = p2; S[j][3] = p3;
            rs0 += p0 + p1;
            rs1 += p2 + p3;
        }
        #pragma unroll
        for (int msk = 1; msk <= 2; msk <<= 1) {
            rs0 += __shfl_xor_sync(0xffffffffu, rs0, msk);
            rs1 += __shfl_xor_sync(0xffffffffu, rs1, msk);
        }
        l0 = l0 * alpha0 + rs0;
        l1 = l1 * alpha1 + rs1;
        m0 = mn0; m1 = mn1;
        #pragma unroll
        for (int n = 0; n < 10; n++) {
            acc[n][0] *= alpha0; acc[n][1] *= alpha0;
            acc[n][2] *= alpha1; acc[n][3] *= alpha1;
        }

        // ---- O += P @ V (3-term), P repacked in-register ----
        #pragma unroll
        for (int jc = 0; jc < 4; jc++) {
            // hi parts
            float h00 = __bfloat162float(__float2bfloat16(S[2*jc][0]));
            float h01 = __bfloat162float(__float2bfloat16(S[2*jc][1]));
            float h02 = __bfloat162float(__float2bfloat16(S[2*jc][2]));
            float h03 = __bfloat162float(__float2bfloat16(S[2*jc][3]));
            float h10 = __bfloat162float(__float2bfloat16(S[2*jc+1][0]));
            float h11 = __bfloat162float(__float2bfloat16(S[2*jc+1][1]));
            float h12 = __bfloat162float(__float2bfloat16(S[2*jc+1][2]));
            float h13 = __bfloat162float(__float2bfloat16(S[2*jc+1][3]));
            uint32_t aPh[4], aPl[4];
            aPh[0] = pack_bf2(h00, h01);
            aPh[1] = pack_bf2(h02, h03);
            aPh[2] = pack_bf2(h10, h11);
            aPh[3] = pack_bf2(h12, h13);
            aPl[0] = pack_bf2(S[2*jc][0] - h00, S[2*jc][1] - h01);
            aPl[1] = pack_bf2(S[2*jc][2] - h02, S[2*jc][3] - h03);
            aPl[2] = pack_bf2(S[2*jc+1][0] - h10, S[2*jc+1][1] - h11);
            aPl[3] = pack_bf2(S[2*jc+1][2] - h12, S[2*jc+1][3] - h13);

            #pragma unroll
            for (int n = 0; n < 10; n++) {
                uint32_t bh[2], bl[2];
                uint32_t voff = (uint32_t)((n * 8 + b_row) * VSTR + jc * 16 + b_kof) * 2;
                LDSM_X2(bh[0], bh[1], smem_u32(Vh) + voff);
                LDSM_X2(bl[0], bl[1], smem_u32(Vl) + voff);
                MMA16816(acc[n][0], acc[n][1], acc[n][2], acc[n][3],
                         aPh[0], aPh[1], aPh[2], aPh[3], bh[0], bh[1]);
                MMA16816(acc[n][0], acc[n][1], acc[n][2], acc[n][3],
                         aPh[0], aPh[1], aPh[2], aPh[3], bl[0], bl[1]);
                MMA16816(acc[n][0], acc[n][1], acc[n][2], acc[n][3],
                         aPl[0], aPl[1], aPl[2], aPl[3], bh[0], bh[1]);
            }
        }
    }

    // ---- epilogue ----
    float il0 = (l0 > 0.f) ? (1.f / l0) : 0.f;
    float il1 = (l1 > 0.f) ? (1.f / l1) : 0.f;
    #pragma unroll
    for (int n = 0; n < 10; n++) {
        int d = n * 8 + kq;
        size_t o0 = (size_t)(qbase + row0) * DIM + head * HEAD_DIM + d;
        size_t o1 = (size_t)(qbase + row1) * DIM + head * HEAD_DIM + d;
        g_attn[o0]     = acc[n][0] * il0;
        g_attn[o0 + 1] = acc[n][1] * il0;
        g_attn[o1]     = acc[n][2] * il1;
        g_attn[o1 + 1] = acc[n][3] * il1;
    }
}

// ---------------------------------------------------------------------------
extern "C" void kernel_launch(void* const* d_in, const int* in_sizes, int n_in,
                              void* d_out, int out_size)
{
    const float* hidden = (const float*)d_in[0];
    const float* rotary = (const float*)d_in[1];
    const int*   cu     = (const int*)d_in[2];
    const float* qkv_w  = (const float*)d_in[3];
    const float* qkv_b  = (const float*)d_in[4];
    const float* proj_w = (const float*)d_in[5];
    const float* proj_b = (const float*)d_in[6];
    float* out = (float*)d_out;
    int ncu = in_sizes[2];

    float *qkv_ptr = nullptr, *attn_ptr = nullptr;
    __nv_bfloat16 *Ah, *Wq, *Wp, *At;
    cudaGetSymbolAddress((void**)&qkv_ptr, g_qkv);
    cudaGetSymbolAddress((void**)&attn_ptr, g_attn);
    cudaGetSymbolAddress((void**)&Ah, g_Ah);
    cudaGetSymbolAddress((void**)&Wq, g_Wq);
    cudaGetSymbolAddress((void**)&Wp, g_Wp);
    cudaGetSymbolAddress((void**)&At, g_At);

    // 0) Decompose fp32 -> bf16 hi/lo concatenated-K layouts
    {
        int tA = SEQ * DIM;
        decomp_kernel<<<(tA + 255) / 256, 256>>>(hidden, Ah, tA, DIM, 2);
        int tWq = QKV_DIM * DIM;
        decomp_kernel<<<(tWq + 255) / 256, 256>>>(qkv_w, Wq, tWq, DIM, 1);
        int tWp = DIM * DIM;
        decomp_kernel<<<(tWp + 255) / 256, 256>>>(proj_w, Wp, tWp, DIM, 1);
    }

    // 1) QKV GEMM (HMMA bf16x3)
    hgemm_bias_kernel<<<dim3(QKV_DIM / 128, SEQ / 128), 256>>>(
        Ah, Wq, qkv_b, qkv_ptr, SEQ, QKV_DIM, K3);

    // 2) RoPE
    {
        int total = SEQ * 2 * HEADS * (HEAD_DIM / 2);
        rope_kernel<<<(total + 255) / 256, 256>>>(rotary);
    }

    // 3) Tensor-core flash attention
    {
        cudaFuncSetAttribute(fattn_kernel,
                             cudaFuncAttributeMaxDynamicSharedMemorySize, FA_SMEM);
        fattn_kernel<<<dim3(SEQ / AQ, HEADS), 256, FA_SMEM>>>(cu, ncu);
    }

    // 4) Decompose attention output, proj GEMM
    {
        int tA = SEQ * DIM;
        decomp_kernel<<<(tA + 255) / 256, 256>>>(attn_ptr, At, tA, DIM, 2);
    }
    hgemm_bias_kernel<<<dim3(DIM / 128, SEQ / 128), 256>>>(
        At, Wp, proj_b, out, SEQ, DIM, K3);
}

// round 6
// speedup vs baseline: 2.8052x; 1.1877x over previous
#include <cuda_runtime.h>
#include <cuda_bf16.h>
#include <math.h>
#include <stdint.h>

#define SEQ      2048
#define DIM      1280
#define HEADS    16
#define HEAD_DIM 80
#define QKV_DIM  3840

// ---------------------------------------------------------------------------
// Scratch
// ---------------------------------------------------------------------------
__device__ float g_qkv[SEQ * QKV_DIM];
__device__ float g_attn[SEQ * DIM];
__device__ __nv_bfloat16 g_hid_h[SEQ * DIM],     g_hid_l[SEQ * DIM];
__device__ __nv_bfloat16 g_wq_h[QKV_DIM * DIM],  g_wq_l[QKV_DIM * DIM];
__device__ __nv_bfloat16 g_wp_h[DIM * DIM],      g_wp_l[DIM * DIM];
__device__ __nv_bfloat16 g_at_h[SEQ * DIM],      g_at_l[SEQ * DIM];

// ---------------------------------------------------------------------------
// PTX helpers (non-'a' features only)
// ---------------------------------------------------------------------------
#define CP_ASYNC16(dst, src) \
    asm volatile("cp.async.cg.shared.global [%0], [%1], 16;" :: "r"(dst), "l"(src))
#define CP_COMMIT() asm volatile("cp.async.commit_group;")
#define CP_WAIT0()  asm volatile("cp.async.wait_group 0;")

#define LDSM_X4(r0,r1,r2,r3,addr) \
    asm volatile("ldmatrix.sync.aligned.m8n8.x4.shared.b16 {%0,%1,%2,%3}, [%4];" \
        : "=r"(r0),"=r"(r1),"=r"(r2),"=r"(r3) : "r"(addr))
#define LDSM_X2(r0,r1,addr) \
    asm volatile("ldmatrix.sync.aligned.m8n8.x2.shared.b16 {%0,%1}, [%2];" \
        : "=r"(r0),"=r"(r1) : "r"(addr))

#define MMA16816(c0,c1,c2,c3,a0,a1,a2,a3,b0,b1) \
    asm volatile("mma.sync.aligned.m16n8k16.row.col.f32.bf16.bf16.f32 " \
        "{%0,%1,%2,%3}, {%4,%5,%6,%7}, {%8,%9}, {%0,%1,%2,%3};" \
        : "+f"(c0),"+f"(c1),"+f"(c2),"+f"(c3) \
        : "r"(a0),"r"(a1),"r"(a2),"r"(a3),"r"(b0),"r"(b1))

__device__ __forceinline__ uint32_t smem_u32(const void* p) {
    return (uint32_t)__cvta_generic_to_shared(p);
}
__device__ __forceinline__ uint32_t pack_bf2(float a, float b) {
    __nv_bfloat162 v = __float22bfloat162_rn(make_float2(a, b));
    return *(uint32_t*)&v;
}

// ---------------------------------------------------------------------------
// Split-precision bf16 HGEMM (TN): C = A @ B^T + bias, fp32 accum.
// A,B given as separate hi/lo bf16 planes [rows][K]. 3-term:
//   C = Ah·Bh + Ah·Bl + Al·Bh
// 128x128 block, KBLK=32, 8 warps (2x4), warp tile 64x32, double-buffered.
// Dynamic smem: 2 stages x 4 planes x 128 x KPAD bf16 = 80 KB.
// ---------------------------------------------------------------------------
#define KBLK 32
#define KPAD 40
#define PLANE_B (128 * KPAD * 2)          // 10240 bytes per plane
#define STAGE_B (4 * PLANE_B)             // 40960 bytes per stage
#define HG_SMEM (2 * STAGE_B)

__global__ void __launch_bounds__(256, 2) hgemm_split_kernel(
    const __nv_bfloat16* __restrict__ Ah_, const __nv_bfloat16* __restrict__ Al_,
    const __nv_bfloat16* __restrict__ Bh_, const __nv_bfloat16* __restrict__ Bl_,
    const float* __restrict__ bias, float* __restrict__ C,
    int M, int N, int K)
{
    extern __shared__ char smraw[];
    const uint32_t sb = smem_u32(smraw);

    const int tid = threadIdx.x;
    const int ln  = tid & 31;
    const int wid = tid >> 5;
    const int wm  = wid & 1;
    const int wn  = wid >> 1;
    const int m0  = blockIdx.y * 128;
    const int n0  = blockIdx.x * 128;

    // loader mapping: per plane 512 x 16B chunks, 2 per thread
    const int r0c = tid >> 2;             // chunk set 0 row (0..63)
    const int r1c = (tid + 256) >> 2;     // chunk set 1 row (64..127)
    const int cc  = (tid & 3) * 8;        // bf16 col

    const __nv_bfloat16* gp[4];
    gp[0] = Ah_ + (size_t)m0 * K;  gp[1] = Al_ + (size_t)m0 * K;
    gp[2] = Bh_ + (size_t)n0 * K;  gp[3] = Bl_ + (size_t)n0 * K;

    auto load_stage = [&](int kt, int s) {
        const uint32_t stb = sb + s * STAGE_B;
        #pragma unroll
        for (int p = 0; p < 4; p++) {
            const uint32_t pb = stb + p * PLANE_B;
            CP_ASYNC16(pb + (uint32_t)(r0c * KPAD + cc) * 2,
                       gp[p] + (size_t)r0c * K + kt + cc);
            CP_ASYNC16(pb + (uint32_t)(r1c * KPAD + cc) * 2,
                       gp[p] + (size_t)r1c * K + kt + cc);
        }
        CP_COMMIT();
    };

    float acc[4][4][4];
    #pragma unroll
    for (int mi = 0; mi < 4; mi++)
        #pragma unroll
        for (int ni = 0; ni < 4; ni++)
            #pragma unroll
            for (int c = 0; c < 4; c++) acc[mi][ni][c] = 0.f;

    load_stage(0, 0);
    CP_WAIT0();
    __syncthreads();

    const int a_row = (ln & 15);
    const int a_kof = (ln < 16) ? 0 : 8;
    const int b_row = (ln & 7);
    const int b_kof = (ln & 8);

    int buf = 0;
    for (int kt = 0; kt < K; kt += KBLK) {
        const bool hasNext = (kt + KBLK) < K;
        if (hasNext) load_stage(kt + KBLK, buf ^ 1);

        const uint32_t stb = sb + buf * STAGE_B;
        const uint32_t pAh = stb;
        const uint32_t pAl = stb + PLANE_B;
        const uint32_t pBh = stb + 2 * PLANE_B;
        const uint32_t pBl = stb + 3 * PLANE_B;

        #pragma unroll
        for (int ks = 0; ks < 2; ks++) {
            const int k0 = ks * 16;
            uint32_t ah[4][4], al[4][4];
            #pragma unroll
            for (int mi = 0; mi < 4; mi++) {
                uint32_t off = (uint32_t)((wm * 64 + mi * 16 + a_row) * KPAD
                                          + k0 + a_kof) * 2;
                LDSM_X4(ah[mi][0], ah[mi][1], ah[mi][2], ah[mi][3], pAh + off);
                LDSM_X4(al[mi][0], al[mi][1], al[mi][2], al[mi][3], pAl + off);
            }
            #pragma unroll
            for (int ni = 0; ni < 4; ni++) {
                uint32_t off = (uint32_t)((wn * 32 + ni * 8 + b_row) * KPAD
                                          + k0 + b_kof) * 2;
                uint32_t bh0, bh1, bl0, bl1;
                LDSM_X2(bh0, bh1, pBh + off);
                LDSM_X2(bl0, bl1, pBl + off);
                #pragma unroll
                for (int mi = 0; mi < 4; mi++) {
                    MMA16816(acc[mi][ni][0], acc[mi][ni][1],
                             acc[mi][ni][2], acc[mi][ni][3],
                             ah[mi][0], ah[mi][1], ah[mi][2], ah[mi][3], bh0, bh1);
                    MMA16816(acc[mi][ni][0], acc[mi][ni][1],
                             acc[mi][ni][2], acc[mi][ni][3],
                             ah[mi][0], ah[mi][1], ah[mi][2], ah[mi][3], bl0, bl1);
                    MMA16816(acc[mi][ni][0], acc[mi][ni][1],
                             acc[mi][ni][2], acc[mi][ni][3],
                             al[mi][0], al[mi][1], al[mi][2], al[mi][3], bh0, bh1);
                }
            }
        }

        if (hasNext) {
            CP_WAIT0();
            __syncthreads();
            buf ^= 1;
        }
    }

    const int crow = ln >> 2;
    const int ccol = (ln & 3) * 2;
    #pragma unroll
    for (int mi = 0; mi < 4; mi++) {
        #pragma unroll
        for (int ni = 0; ni < 4; ni++) {
            int col = n0 + wn * 32 + ni * 8 + ccol;
            float b0 = bias[col], b1 = bias[col + 1];
            int r0 = m0 + wm * 64 + mi * 16 + crow;
            float2 v0 = make_float2(acc[mi][ni][0] + b0, acc[mi][ni][1] + b1);
            float2 v1 = make_float2(acc[mi][ni][2] + b0, acc[mi][ni][3] + b1);
            *(float2*)(C + (size_t)r0 * N + col)       = v0;
            *(float2*)(C + (size_t)(r0 + 8) * N + col) = v1;
        }
    }
}

// ---------------------------------------------------------------------------
// Decompose fp32 -> separate bf16 hi/lo planes
// ---------------------------------------------------------------------------
__global__ void __launch_bounds__(256) decomp2_kernel(
    const float* __restrict__ in, __nv_bfloat16* __restrict__ hi_,
    __nv_bfloat16* __restrict__ lo_, int total)
{
    int idx = blockIdx.x * blockDim.x + threadIdx.x;
    if (idx >= total) return;
    float x = in[idx];
    __nv_bfloat16 hi = __float2bfloat16(x);
    hi_[idx] = hi;
    lo_[idx] = __float2bfloat16(x - __bfloat162float(hi));
}

// ---------------------------------------------------------------------------
// RoPE in-place on q, k
// ---------------------------------------------------------------------------
__global__ void __launch_bounds__(256) rope_kernel(const float* __restrict__ rot)
{
    int t = blockIdx.x * blockDim.x + threadIdx.x;
    const int total = SEQ * 2 * HEADS * (HEAD_DIM / 2);
    if (t >= total) return;
    int d2   = t % 40;
    int h    = (t / 40) % HEADS;
    int part = (t / (40 * HEADS)) % 2;
    int s    = t / (40 * HEADS * 2);
    float f = rot[s * 40 + d2];
    float si, co;
    sincosf(f, &si, &co);
    size_t base = (size_t)s * QKV_DIM + (size_t)part * DIM + h * HEAD_DIM;
    float x1 = g_qkv[base + d2];
    float x2 = g_qkv[base + 40 + d2];
    g_qkv[base + d2]      = x1 * co - x2 * si;
    g_qkv[base + 40 + d2] = x2 * co + x1 * si;
}

// ---------------------------------------------------------------------------
// Tensor-core flash attention, bf16 3-term split, segment-masked. (round-5)
// ---------------------------------------------------------------------------
#define AQ   128
#define AK   64
#define QSTR 88
#define VSTR 72
#define FA_SMEM ((2*AQ*QSTR + 2*AK*QSTR + 2*HEAD_DIM*VSTR) * 2 + (AQ + AK + 4) * 4)

__global__ void __launch_bounds__(256) fattn_kernel(const int* __restrict__ cu, int ncu)
{
    extern __shared__ char smraw[];
    __nv_bfloat16* Qh = (__nv_bfloat16*)smraw;
    __nv_bfloat16* Ql = Qh + AQ * QSTR;
    __nv_bfloat16* Kh = Ql + AQ * QSTR;
    __nv_bfloat16* Kl = Kh + AK * QSTR;
    __nv_bfloat16* Vh = Kl + AK * QSTR;
    __nv_bfloat16* Vl = Vh + HEAD_DIM * VSTR;
    int* segq  = (int*)(Vl + HEAD_DIM * VSTR);
    int* segk  = segq + AQ;
    int* range = segk + AK;

    const int tid = threadIdx.x;
    const int w   = tid >> 5;
    const int ln  = tid & 31;
    const int head  = blockIdx.y;
    const int qbase = blockIdx.x * AQ;
    const float scale = rsqrtf((float)HEAD_DIM);

    #pragma unroll
    for (int i = 0; i < 40; i++) {
        int idx = tid + i * 256;
        int r = idx / HEAD_DIM, d = idx - r * HEAD_DIM;
        float v = g_qkv[(size_t)(qbase + r) * QKV_DIM + head * HEAD_DIM + d] * scale;
        __nv_bfloat16 hi = __float2bfloat16(v);
        Qh[r * QSTR + d] = hi;
        Ql[r * QSTR + d] = __float2bfloat16(v - __bfloat162float(hi));
    }
    if (tid < AQ) {
        int i = qbase + tid;
        int s = 0;
        for (int j = 1; j < ncu; j++) s += (cu[j] <= i);
        segq[tid] = s;
    }
    __syncthreads();
    if (tid == 0) {
        int smin = segq[0], smax = segq[0];
        for (int r = 1; r < AQ; r++) { smin = min(smin, segq[r]); smax = max(smax, segq[r]); }
        range[0] = cu[smin];
        range[1] = cu[smax + 1];
    }
    __syncthreads();
    const int lo = range[0], hi_ = range[1];

    const int qr = ln >> 2;
    const int kq = (ln & 3) * 2;
    const int row0 = w * 16 + qr;
    const int row1 = row0 + 8;
    const int sq0 = segq[row0], sq1 = segq[row1];

    float m0 = -1e30f, m1 = -1e30f, l0 = 0.f, l1 = 0.f;
    float acc[10][4];
    #pragma unroll
    for (int n = 0; n < 10; n++)
        #pragma unroll
        for (int c = 0; c < 4; c++) acc[n][c] = 0.f;

    const int a_row = (ln & 15);
    const int a_kof = (ln < 16) ? 0 : 8;
    const int b_row = (ln & 7);
    const int b_kof = (ln & 8);

    for (int kt = lo; kt < hi_; kt += AK) {
        __syncthreads();
        #pragma unroll
        for (int i = 0; i < 20; i++) {
            int idx = tid + i * 256;
            int r = idx / HEAD_DIM, d = idx - r * HEAD_DIM;
            int key = kt + r;
            float kv = 0.f, vv = 0.f;
            if (key < hi_) {
                size_t base = (size_t)key * QKV_DIM + head * HEAD_DIM + d;
                kv = g_qkv[base + DIM];
                vv = g_qkv[base + 2 * DIM];
            }
            __nv_bfloat16 kh = __float2bfloat16(kv);
            Kh[r * QSTR + d] = kh;
            Kl[r * QSTR + d] = __float2bfloat16(kv - __bfloat162float(kh));
            __nv_bfloat16 vh = __float2bfloat16(vv);
            Vh[d * VSTR + r] = vh;
            Vl[d * VSTR + r] = __float2bfloat16(vv - __bfloat162float(vh));
        }
        if (tid < AK) {
            int key = kt + tid;
            int s = -1;
            if (key < hi_) {
                s = 0;
                for (int j = 1; j < ncu; j++) s += (cu[j] <= key);
            }
            segk[tid] = s;
        }
        __syncthreads();

        float S[8][4];
        #pragma unroll
        for (int j = 0; j < 8; j++)
            #pragma unroll
            for (int c = 0; c < 4; c++) S[j][c] = 0.f;

        #pragma unroll
        for (int kc = 0; kc < 5; kc++) {
            uint32_t ah[4], al[4];
            uint32_t qoff = (uint32_t)((w * 16 + a_row) * QSTR + kc * 16 + a_kof) * 2;
            LDSM_X4(ah[0], ah[1], ah[2], ah[3], smem_u32(Qh) + qoff);
            LDSM_X4(al[0], al[1], al[2], al[3], smem_u32(Ql) + qoff);
            #pragma unroll
            for (int j = 0; j < 8; j++) {
                uint32_t bh[2], bl[2];
                uint32_t koff = (uint32_t)((j * 8 + b_row) * QSTR + kc * 16 + b_kof) * 2;
                LDSM_X2(bh[0], bh[1], smem_u32(Kh) + koff);
                LDSM_X2(bl[0], bl[1], smem_u32(Kl) + koff);
                MMA16816(S[j][0], S[j][1], S[j][2], S[j][3],
                         ah[0], ah[1], ah[2], ah[3], bh[0], bh[1]);
                MMA16816(S[j][0], S[j][1], S[j][2], S[j][3],
                         ah[0], ah[1], ah[2], ah[3], bl[0], bl[1]);
                MMA16816(S[j][0], S[j][1], S[j][2], S[j][3],
                         al[0], al[1], al[2], al[3], bh[0], bh[1]);
            }
        }

        float mt0 = -1e30f, mt1 = -1e30f;
        #pragma unroll
        for (int j = 0; j < 8; j++) {
            int k0 = j * 8 + kq;
            int sk0 = segk[k0], sk1 = segk[k0 + 1];
            mt0 = fmaxf(mt0, (sk0 == sq0) ? S[j][0] : -1e30f);
            mt0 = fmaxf(mt0, (sk1 == sq0) ? S[j][1] : -1e30f);
            mt1 = fmaxf(mt1, (sk0 == sq1) ? S[j][2] : -1e30f);
            mt1 = fmaxf(mt1, (sk1 == sq1) ? S[j][3] : -1e30f);
        }
        #pragma unroll
        for (int msk = 1; msk <= 2; msk <<= 1) {
            mt0 = fmaxf(mt0, __shfl_xor_sync(0xffffffffu, mt0, msk));
            mt1 = fmaxf(mt1, __shfl_xor_sync(0xffffffffu, mt1, msk));
        }
        float mn0 = fmaxf(m0, mt0), mn1 = fmaxf(m1, mt1);
        float alpha0 = __expf(m0 - mn0), alpha1 = __expf(m1 - mn1);
        float rs0 = 0.f, rs1 = 0.f;
        #pragma unroll
        for (int j = 0; j < 8; j++) {
            int k0 = j * 8 + kq;
            int sk0 = segk[k0], sk1 = segk[k0 + 1];
            float p0 = (sk0 == sq0) ? __expf(S[j][0] - mn0) : 0.f;
            float p1 = (sk1 == sq0) ? __expf(S[j][1] - mn0) : 0.f;
            float p2 = (sk0 == sq1) ? __expf(S[j][2] - mn1) : 0.f;
            float p3 = (sk1 == sq1) ? __expf(S[j][3] - mn1) : 0.f;
            S[j][0] = p0; S[j][1] = p1; S[j][2] = p2; S[j][3] = p3;
            rs0 += p0 + p1;
            rs1 += p2 + p3;
        }
        #pragma unroll
        for (int msk = 1; msk <= 2; msk <<= 1) {
            rs0 += __shfl_xor_sync(0xffffffffu, rs0, msk);
            rs1 += __shfl_xor_sync(0xffffffffu, rs1, msk);
        }
        l0 = l0 * alpha0 + rs0;
        l1 = l1 * alpha1 + rs1;
        m0 = mn0; m1 = mn1;
        #pragma unroll
        for (int n = 0; n < 10; n++) {
            acc[n][0] *= alpha0; acc[n][1] *= alpha0;
            acc[n][2] *= alpha1; acc[n][3] *= alpha1;
        }

        #pragma unroll
        for (int jc = 0; jc < 4; jc++) {
            float h00 = __bfloat162float(__float2bfloat16(S[2*jc][0]));
            float h01 = __bfloat162float(__float2bfloat16(S[2*jc][1]));
            float h02 = __bfloat162float(__float2bfloat16(S[2*jc][2]));
            float h03 = __bfloat162float(__float2bfloat16(S[2*jc][3]));
            float h10 = __bfloat162float(__float2bfloat16(S[2*jc+1][0]));
            float h11 = __bfloat162float(__float2bfloat16(S[2*jc+1][1]));
            float h12 = __bfloat162float(__float2bfloat16(S[2*jc+1][2]));
            float h13 = __bfloat162float(__float2bfloat16(S[2*jc+1][3]));
            uint32_t aPh[4], aPl[4];
            aPh[0] = pack_bf2(h00, h01);
            aPh[1] = pack_bf2(h02, h03);
            aPh[2] = pack_bf2(h10, h11);
            aPh[3] = pack_bf2(h12, h13);
            aPl[0] = pack_bf2(S[2*jc][0] - h00, S[2*jc][1] - h01);
            aPl[1] = pack_bf2(S[2*jc][2] - h02, S[2*jc][3] - h03);
            aPl[2] = pack_bf2(S[2*jc+1][0] - h10, S[2*jc+1][1] - h11);
            aPl[3] = pack_bf2(S[2*jc+1][2] - h12, S[2*jc+1][3] - h13);

            #pragma unroll
            for (int n = 0; n < 10; n++) {
                uint32_t bh[2], bl[2];
                uint32_t voff = (uint32_t)((n * 8 + b_row) * VSTR + jc * 16 + b_kof) * 2;
                LDSM_X2(bh[0], bh[1], smem_u32(Vh) + voff);
                LDSM_X2(bl[0], bl[1], smem_u32(Vl) + voff);
                MMA16816(acc[n][0], acc[n][1], acc[n][2], acc[n][3],
                         aPh[0], aPh[1], aPh[2], aPh[3], bh[0], bh[1]);
                MMA16816(acc[n][0], acc[n][1], acc[n][2], acc[n][3],
                         aPh[0], aPh[1], aPh[2], aPh[3], bl[0], bl[1]);
                MMA16816(acc[n][0], acc[n][1], acc[n][2], acc[n][3],
                         aPl[0], aPl[1], aPl[2], aPl[3], bh[0], bh[1]);
            }
        }
    }

    float il0 = (l0 > 0.f) ? (1.f / l0) : 0.f;
    float il1 = (l1 > 0.f) ? (1.f / l1) : 0.f;
    #pragma unroll
    for (int n = 0; n < 10; n++) {
        int d = n * 8 + kq;
        size_t o0 = (size_t)(qbase + row0) * DIM + head * HEAD_DIM + d;
        size_t o1 = (size_t)(qbase + row1) * DIM + head * HEAD_DIM + d;
        g_attn[o0]     = acc[n][0] * il0;
        g_attn[o0 + 1] = acc[n][1] * il0;
        g_attn[o1]     = acc[n][2] * il1;
        g_attn[o1 + 1] = acc[n][3] * il1;
    }
}

// ---------------------------------------------------------------------------
extern "C" void kernel_launch(void* const* d_in, const int* in_sizes, int n_in,
                              void* d_out, int out_size)
{
    const float* hidden = (const float*)d_in[0];
    const float* rotary = (const float*)d_in[1];
    const int*   cu     = (const int*)d_in[2];
    const float* qkv_w  = (const float*)d_in[3];
    const float* qkv_b  = (const float*)d_in[4];
    const float* proj_w = (const float*)d_in[5];
    const float* proj_b = (const float*)d_in[6];
    float* out = (float*)d_out;
    int ncu = in_sizes[2];

    float *qkv_ptr, *attn_ptr;
    __nv_bfloat16 *hidH, *hidL, *wqH, *wqL, *wpH, *wpL, *atH, *atL;
    cudaGetSymbolAddress((void**)&qkv_ptr, g_qkv);
    cudaGetSymbolAddress((void**)&attn_ptr, g_attn);
    cudaGetSymbolAddress((void**)&hidH, g_hid_h);
    cudaGetSymbolAddress((void**)&hidL, g_hid_l);
    cudaGetSymbolAddress((void**)&wqH, g_wq_h);
    cudaGetSymbolAddress((void**)&wqL, g_wq_l);
    cudaGetSymbolAddress((void**)&wpH, g_wp_h);
    cudaGetSymbolAddress((void**)&wpL, g_wp_l);
    cudaGetSymbolAddress((void**)&atH, g_at_h);
    cudaGetSymbolAddress((void**)&atL, g_at_l);

    cudaFuncSetAttribute(hgemm_split_kernel,
                         cudaFuncAttributeMaxDynamicSharedMemorySize, HG_SMEM);

    // 0) Decompose inputs
    decomp2_kernel<<<(SEQ * DIM + 255) / 256, 256>>>(hidden, hidH, hidL, SEQ * DIM);
    decomp2_kernel<<<(QKV_DIM * DIM + 255) / 256, 256>>>(qkv_w, wqH, wqL, QKV_DIM * DIM);
    decomp2_kernel<<<(DIM * DIM + 255) / 256, 256>>>(proj_w, wpH, wpL, DIM * DIM);

    // 1) QKV GEMM
    hgemm_split_kernel<<<dim3(QKV_DIM / 128, SEQ / 128), 256, HG_SMEM>>>(
        hidH, hidL, wqH, wqL, qkv_b, qkv_ptr, SEQ, QKV_DIM, DIM);

    // 2) RoPE
    {
        int total = SEQ * 2 * HEADS * (HEAD_DIM / 2);
        rope_kernel<<<(total + 255) / 256, 256>>>(rotary);
    }

    // 3) Flash attention (HMMA)
    {
        cudaFuncSetAttribute(fattn_kernel,
                             cudaFuncAttributeMaxDynamicSharedMemorySize, FA_SMEM);
        fattn_kernel<<<dim3(SEQ / AQ, HEADS), 256, FA_SMEM>>>(cu, ncu);
    }

    // 4) Decompose attention output + proj GEMM
    decomp2_kernel<<<(SEQ * DIM + 255) / 256, 256>>>(attn_ptr, atH, atL, SEQ * DIM);
    hgemm_split_kernel<<<dim3(DIM / 128, SEQ / 128), 256, HG_SMEM>>>(
        atH, atL, wpH, wpL, proj_b, out, SEQ, DIM, DIM);
}

// round 7
// speedup vs baseline: 2.8592x; 1.0193x over previous
#include <cuda_runtime.h>
#include <cuda_bf16.h>
#include <math.h>
#include <stdint.h>

#define SEQ      2048
#define DIM      1280
#define HEADS    16
#define HEAD_DIM 80
#define QKV_DIM  3840

// ---------------------------------------------------------------------------
// Scratch
// ---------------------------------------------------------------------------
__device__ float g_qkv[SEQ * QKV_DIM];
__device__ __nv_bfloat16 g_hid_h[SEQ * DIM],     g_hid_l[SEQ * DIM];
__device__ __nv_bfloat16 g_wq_h[QKV_DIM * DIM],  g_wq_l[QKV_DIM * DIM];
__device__ __nv_bfloat16 g_wp_h[DIM * DIM],      g_wp_l[DIM * DIM];
__device__ __nv_bfloat16 g_at_h[SEQ * DIM],      g_at_l[SEQ * DIM];

// ---------------------------------------------------------------------------
// PTX helpers (non-'a' features only)
// ---------------------------------------------------------------------------
#define CP_ASYNC16(dst, src) \
    asm volatile("cp.async.cg.shared.global [%0], [%1], 16;" :: "r"(dst), "l"(src))
#define CP_COMMIT() asm volatile("cp.async.commit_group;")
#define CP_WAIT0()  asm volatile("cp.async.wait_group 0;")

#define LDSM_X4(r0,r1,r2,r3,addr) \
    asm volatile("ldmatrix.sync.aligned.m8n8.x4.shared.b16 {%0,%1,%2,%3}, [%4];" \
        : "=r"(r0),"=r"(r1),"=r"(r2),"=r"(r3) : "r"(addr))
#define LDSM_X2(r0,r1,addr) \
    asm volatile("ldmatrix.sync.aligned.m8n8.x2.shared.b16 {%0,%1}, [%2];" \
        : "=r"(r0),"=r"(r1) : "r"(addr))

#define MMA16816(c0,c1,c2,c3,a0,a1,a2,a3,b0,b1) \
    asm volatile("mma.sync.aligned.m16n8k16.row.col.f32.bf16.bf16.f32 " \
        "{%0,%1,%2,%3}, {%4,%5,%6,%7}, {%8,%9}, {%0,%1,%2,%3};" \
        : "+f"(c0),"+f"(c1),"+f"(c2),"+f"(c3) \
        : "r"(a0),"r"(a1),"r"(a2),"r"(a3),"r"(b0),"r"(b1))

__device__ __forceinline__ uint32_t smem_u32(const void* p) {
    return (uint32_t)__cvta_generic_to_shared(p);
}
__device__ __forceinline__ uint32_t pack_bf2(float a, float b) {
    __nv_bfloat162 v = __float22bfloat162_rn(make_float2(a, b));
    return *(uint32_t*)&v;
}

// ---------------------------------------------------------------------------
// Split-precision bf16 HGEMM (TN): C = A @ B^T + bias, fp32 accum.
// C = Ah·Bh + Ah·Bl + Al·Bh, term-major MMA issue (same-acc gap = 8 MMAs).
// ---------------------------------------------------------------------------
#define KBLK 32
#define KPAD 40
#define PLANE_B (128 * KPAD * 2)
#define STAGE_B (4 * PLANE_B)
#define HG_SMEM (2 * STAGE_B)

__global__ void __launch_bounds__(256, 2) hgemm_split_kernel(
    const __nv_bfloat16* __restrict__ Ah_, const __nv_bfloat16* __restrict__ Al_,
    const __nv_bfloat16* __restrict__ Bh_, const __nv_bfloat16* __restrict__ Bl_,
    const float* __restrict__ bias, float* __restrict__ C,
    int M, int N, int K)
{
    extern __shared__ char smraw[];
    const uint32_t sb = smem_u32(smraw);

    const int tid = threadIdx.x;
    const int ln  = tid & 31;
    const int wid = tid >> 5;
    const int wm  = wid & 1;
    const int wn  = wid >> 1;
    const int m0  = blockIdx.y * 128;
    const int n0  = blockIdx.x * 128;

    const int r0c = tid >> 2;
    const int r1c = (tid + 256) >> 2;
    const int cc  = (tid & 3) * 8;

    const __nv_bfloat16* gp[4];
    gp[0] = Ah_ + (size_t)m0 * K;  gp[1] = Al_ + (size_t)m0 * K;
    gp[2] = Bh_ + (size_t)n0 * K;  gp[3] = Bl_ + (size_t)n0 * K;

    auto load_stage = [&](int kt, int s) {
        const uint32_t stb = sb + s * STAGE_B;
        #pragma unroll
        for (int p = 0; p < 4; p++) {
            const uint32_t pb = stb + p * PLANE_B;
            CP_ASYNC16(pb + (uint32_t)(r0c * KPAD + cc) * 2,
                       gp[p] + (size_t)r0c * K + kt + cc);
            CP_ASYNC16(pb + (uint32_t)(r1c * KPAD + cc) * 2,
                       gp[p] + (size_t)r1c * K + kt + cc);
        }
        CP_COMMIT();
    };

    float acc[4][4][4];
    #pragma unroll
    for (int mi = 0; mi < 4; mi++)
        #pragma unroll
        for (int ni = 0; ni < 4; ni++)
            #pragma unroll
            for (int c = 0; c < 4; c++) acc[mi][ni][c] = 0.f;

    load_stage(0, 0);
    CP_WAIT0();
    __syncthreads();

    const int a_row = (ln & 15);
    const int a_kof = (ln < 16) ? 0 : 8;
    const int b_row = (ln & 7);
    const int b_kof = (ln & 8);

    int buf = 0;
    for (int kt = 0; kt < K; kt += KBLK) {
        const bool hasNext = (kt + KBLK) < K;
        if (hasNext) load_stage(kt + KBLK, buf ^ 1);

        const uint32_t stb = sb + buf * STAGE_B;
        const uint32_t pAh = stb;
        const uint32_t pAl = stb + PLANE_B;
        const uint32_t pBh = stb + 2 * PLANE_B;
        const uint32_t pBl = stb + 3 * PLANE_B;

        #pragma unroll
        for (int ks = 0; ks < 2; ks++) {
            const int k0 = ks * 16;
            uint32_t ah[4][4], al[4][4];
            #pragma unroll
            for (int mi = 0; mi < 4; mi++) {
                uint32_t off = (uint32_t)((wm * 64 + mi * 16 + a_row) * KPAD
                                          + k0 + a_kof) * 2;
                LDSM_X4(ah[mi][0], ah[mi][1], ah[mi][2], ah[mi][3], pAh + off);
                LDSM_X4(al[mi][0], al[mi][1], al[mi][2], al[mi][3], pAl + off);
            }
            #pragma unroll
            for (int np = 0; np < 2; np++) {
                uint32_t bh[2][2], bl[2][2];
                #pragma unroll
                for (int q = 0; q < 2; q++) {
                    uint32_t off = (uint32_t)((wn * 32 + (np * 2 + q) * 8 + b_row) * KPAD
                                              + k0 + b_kof) * 2;
                    LDSM_X2(bh[q][0], bh[q][1], pBh + off);
                    LDSM_X2(bl[q][0], bl[q][1], pBl + off);
                }
                // term-major: same-acc dependency gap = 8 MMAs
                #pragma unroll
                for (int q = 0; q < 2; q++)
                    #pragma unroll
                    for (int mi = 0; mi < 4; mi++) {
                        int ni = np * 2 + q;
                        MMA16816(acc[mi][ni][0], acc[mi][ni][1],
                                 acc[mi][ni][2], acc[mi][ni][3],
                                 ah[mi][0], ah[mi][1], ah[mi][2], ah[mi][3],
                                 bh[q][0], bh[q][1]);
                    }
                #pragma unroll
                for (int q = 0; q < 2; q++)
                    #pragma unroll
                    for (int mi = 0; mi < 4; mi++) {
                        int ni = np * 2 + q;
                        MMA16816(acc[mi][ni][0], acc[mi][ni][1],
                                 acc[mi][ni][2], acc[mi][ni][3],
                                 ah[mi][0], ah[mi][1], ah[mi][2], ah[mi][3],
                                 bl[q][0], bl[q][1]);
                    }
                #pragma unroll
                for (int q = 0; q < 2; q++)
                    #pragma unroll
                    for (int mi = 0; mi < 4; mi++) {
                        int ni = np * 2 + q;
                        MMA16816(acc[mi][ni][0], acc[mi][ni][1],
                                 acc[mi][ni][2], acc[mi][ni][3],
                                 al[mi][0], al[mi][1], al[mi][2], al[mi][3],
                                 bh[q][0], bh[q][1]);
                    }
            }
        }

        if (hasNext) {
            CP_WAIT0();
            __syncthreads();
            buf ^= 1;
        }
    }

    const int crow = ln >> 2;
    const int ccol = (ln & 3) * 2;
    #pragma unroll
    for (int mi = 0; mi < 4; mi++) {
        #pragma unroll
        for (int ni = 0; ni < 4; ni++) {
            int col = n0 + wn * 32 + ni * 8 + ccol;
            float b0 = bias[col], b1 = bias[col + 1];
            int r0 = m0 + wm * 64 + mi * 16 + crow;
            float2 v0 = make_float2(acc[mi][ni][0] + b0, acc[mi][ni][1] + b1);
            float2 v1 = make_float2(acc[mi][ni][2] + b0, acc[mi][ni][3] + b1);
            *(float2*)(C + (size_t)r0 * N + col)       = v0;
            *(float2*)(C + (size_t)(r0 + 8) * N + col) = v1;
        }
    }
}

// ---------------------------------------------------------------------------
// Vectorized decompose: fp32 -> separate bf16 hi/lo planes (float4 granular)
// ---------------------------------------------------------------------------
__global__ void __launch_bounds__(256) decomp4_kernel(
    const float4* __restrict__ in, uint32_t* __restrict__ hi2,
    uint32_t* __restrict__ lo2, int total4)
{
    int idx = blockIdx.x * blockDim.x + threadIdx.x;
    if (idx >= total4) return;
    float4 v = in[idx];
    __nv_bfloat16 h0 = __float2bfloat16(v.x);
    __nv_bfloat16 h1 = __float2bfloat16(v.y);
    __nv_bfloat16 h2 = __float2bfloat16(v.z);
    __nv_bfloat16 h3 = __float2bfloat16(v.w);
    float l0 = v.x - __bfloat162float(h0);
    float l1 = v.y - __bfloat162float(h1);
    float l2 = v.z - __bfloat162float(h2);
    float l3 = v.w - __bfloat162float(h3);
    __nv_bfloat162 hA = make_bfloat162(h0, h1), hB = make_bfloat162(h2, h3);
    hi2[idx * 2]     = *(uint32_t*)&hA;
    hi2[idx * 2 + 1] = *(uint32_t*)&hB;
    lo2[idx * 2]     = pack_bf2(l0, l1);
    lo2[idx * 2 + 1] = pack_bf2(l2, l3);
}

// ---------------------------------------------------------------------------
// RoPE in-place on q, k
// ---------------------------------------------------------------------------
__global__ void __launch_bounds__(256) rope_kernel(const float* __restrict__ rot)
{
    int t = blockIdx.x * blockDim.x + threadIdx.x;
    const int total = SEQ * 2 * HEADS * (HEAD_DIM / 2);
    if (t >= total) return;
    int d2   = t % 40;
    int h    = (t / 40) % HEADS;
    int part = (t / (40 * HEADS)) % 2;
    int s    = t / (40 * HEADS * 2);
    float f = rot[s * 40 + d2];
    float si, co;
    sincosf(f, &si, &co);
    size_t base = (size_t)s * QKV_DIM + (size_t)part * DIM + h * HEAD_DIM;
    float x1 = g_qkv[base + d2];
    float x2 = g_qkv[base + 40 + d2];
    g_qkv[base + d2]      = x1 * co - x2 * si;
    g_qkv[base + 40 + d2] = x2 * co + x1 * si;
}

// ---------------------------------------------------------------------------
// Tensor-core flash attention, bf16 3-term split, segment-masked.
// Term-major MMA issue; epilogue fuses hi/lo decomposition of the output.
// ---------------------------------------------------------------------------
#define AQ   128
#define AK   64
#define QSTR 88
#define VSTR 72
#define FA_SMEM ((2*AQ*QSTR + 2*AK*QSTR + 2*HEAD_DIM*VSTR) * 2 + (AQ + AK + 4) * 4)

__global__ void __launch_bounds__(256) fattn_kernel(const int* __restrict__ cu, int ncu)
{
    extern __shared__ char smraw[];
    __nv_bfloat16* Qh = (__nv_bfloat16*)smraw;
    __nv_bfloat16* Ql = Qh + AQ * QSTR;
    __nv_bfloat16* Kh = Ql + AQ * QSTR;
    __nv_bfloat16* Kl = Kh + AK * QSTR;
    __nv_bfloat16* Vh = Kl + AK * QSTR;
    __nv_bfloat16* Vl = Vh + HEAD_DIM * VSTR;
    int* segq  = (int*)(Vl + HEAD_DIM * VSTR);
    int* segk  = segq + AQ;
    int* range = segk + AK;

    const int tid = threadIdx.x;
    const int w   = tid >> 5;
    const int ln  = tid & 31;
    const int head  = blockIdx.y;
    const int qbase = blockIdx.x * AQ;
    const float scale = rsqrtf((float)HEAD_DIM);

    #pragma unroll
    for (int i = 0; i < 40; i++) {
        int idx = tid + i * 256;
        int r = idx / HEAD_DIM, d = idx - r * HEAD_DIM;
        float v = g_qkv[(size_t)(qbase + r) * QKV_DIM + head * HEAD_DIM + d] * scale;
        __nv_bfloat16 hi = __float2bfloat16(v);
        Qh[r * QSTR + d] = hi;
        Ql[r * QSTR + d] = __float2bfloat16(v - __bfloat162float(hi));
    }
    if (tid < AQ) {
        int i = qbase + tid;
        int s = 0;
        for (int j = 1; j < ncu; j++) s += (cu[j] <= i);
        segq[tid] = s;
    }
    __syncthreads();
    if (tid == 0) {
        int smin = segq[0], smax = segq[0];
        for (int r = 1; r < AQ; r++) { smin = min(smin, segq[r]); smax = max(smax, segq[r]); }
        range[0] = cu[smin];
        range[1] = cu[smax + 1];
    }
    __syncthreads();
    const int lo = range[0], hi_ = range[1];

    const int qr = ln >> 2;
    const int kq = (ln & 3) * 2;
    const int row0 = w * 16 + qr;
    const int row1 = row0 + 8;
    const int sq0 = segq[row0], sq1 = segq[row1];

    float m0 = -1e30f, m1 = -1e30f, l0 = 0.f, l1 = 0.f;
    float acc[10][4];
    #pragma unroll
    for (int n = 0; n < 10; n++)
        #pragma unroll
        for (int c = 0; c < 4; c++) acc[n][c] = 0.f;

    const int a_row = (ln & 15);
    const int a_kof = (ln < 16) ? 0 : 8;
    const int b_row = (ln & 7);
    const int b_kof = (ln & 8);

    for (int kt = lo; kt < hi_; kt += AK) {
        __syncthreads();
        #pragma unroll
        for (int i = 0; i < 20; i++) {
            int idx = tid + i * 256;
            int r = idx / HEAD_DIM, d = idx - r * HEAD_DIM;
            int key = kt + r;
            float kv = 0.f, vv = 0.f;
            if (key < hi_) {
                size_t base = (size_t)key * QKV_DIM + head * HEAD_DIM + d;
                kv = g_qkv[base + DIM];
                vv = g_qkv[base + 2 * DIM];
            }
            __nv_bfloat16 kh = __float2bfloat16(kv);
            Kh[r * QSTR + d] = kh;
            Kl[r * QSTR + d] = __float2bfloat16(kv - __bfloat162float(kh));
            __nv_bfloat16 vh = __float2bfloat16(vv);
            Vh[d * VSTR + r] = vh;
            Vl[d * VSTR + r] = __float2bfloat16(vv - __bfloat162float(vh));
        }
        if (tid < AK) {
            int key = kt + tid;
            int s = -1;
            if (key < hi_) {
                s = 0;
                for (int j = 1; j < ncu; j++) s += (cu[j] <= key);
            }
            segk[tid] = s;
        }
        __syncthreads();

        float S[8][4];
        #pragma unroll
        for (int j = 0; j < 8; j++)
            #pragma unroll
            for (int c = 0; c < 4; c++) S[j][c] = 0.f;

        #pragma unroll
        for (int kc = 0; kc < 5; kc++) {
            uint32_t ah[4], al[4];
            uint32_t qoff = (uint32_t)((w * 16 + a_row) * QSTR + kc * 16 + a_kof) * 2;
            LDSM_X4(ah[0], ah[1], ah[2], ah[3], smem_u32(Qh) + qoff);
            LDSM_X4(al[0], al[1], al[2], al[3], smem_u32(Ql) + qoff);
            #pragma unroll
            for (int jg = 0; jg < 2; jg++) {
                uint32_t bh[4][2], bl[4][2];
                #pragma unroll
                for (int q = 0; q < 4; q++) {
                    uint32_t koff = (uint32_t)(((jg * 4 + q) * 8 + b_row) * QSTR
                                               + kc * 16 + b_kof) * 2;
                    LDSM_X2(bh[q][0], bh[q][1], smem_u32(Kh) + koff);
                    LDSM_X2(bl[q][0], bl[q][1], smem_u32(Kl) + koff);
                }
                // term-major: same-acc gap = 4
                #pragma unroll
                for (int q = 0; q < 4; q++) {
                    int j = jg * 4 + q;
                    MMA16816(S[j][0], S[j][1], S[j][2], S[j][3],
                             ah[0], ah[1], ah[2], ah[3], bh[q][0], bh[q][1]);
                }
                #pragma unroll
                for (int q = 0; q < 4; q++) {
                    int j = jg * 4 + q;
                    MMA16816(S[j][0], S[j][1], S[j][2], S[j][3],
                             ah[0], ah[1], ah[2], ah[3], bl[q][0], bl[q][1]);
                }
                #pragma unroll
                for (int q = 0; q < 4; q++) {
                    int j = jg * 4 + q;
                    MMA16816(S[j][0], S[j][1], S[j][2], S[j][3],
                             al[0], al[1], al[2], al[3], bh[q][0], bh[q][1]);
                }
            }
        }

        float mt0 = -1e30f, mt1 = -1e30f;
        #pragma unroll
        for (int j = 0; j < 8; j++) {
            int k0 = j * 8 + kq;
            int sk0 = segk[k0], sk1 = segk[k0 + 1];
            mt0 = fmaxf(mt0, (sk0 == sq0) ? S[j][0] : -1e30f);
            mt0 = fmaxf(mt0, (sk1 == sq0) ? S[j][1] : -1e30f);
            mt1 = fmaxf(mt1, (sk0 == sq1) ? S[j][2] : -1e30f);
            mt1 = fmaxf(mt1, (sk1 == sq1) ? S[j][3] : -1e30f);
        }
        #pragma unroll
        for (int msk = 1; msk <= 2; msk <<= 1) {
            mt0 = fmaxf(mt0, __shfl_xor_sync(0xffffffffu, mt0, msk));
            mt1 = fmaxf(mt1, __shfl_xor_sync(0xffffffffu, mt1, msk));
        }
        float mn0 = fmaxf(m0, mt0), mn1 = fmaxf(m1, mt1);
        float alpha0 = __expf(m0 - mn0), alpha1 = __expf(m1 - mn1);
        float rs0 = 0.f, rs1 = 0.f;
        #pragma unroll
        for (int j = 0; j < 8; j++) {
            int k0 = j * 8 + kq;
            int sk0 = segk[k0], sk1 = segk[k0 + 1];
            float p0 = (sk0 == sq0) ? __expf(S[j][0] - mn0) : 0.f;
            float p1 = (sk1 == sq0) ? __expf(S[j][1] - mn0) : 0.f;
            float p2 = (sk0 == sq1) ? __expf(S[j][2] - mn1) : 0.f;
            float p3 = (sk1 == sq1) ? __expf(S[j][3] - mn1) : 0.f;
            S[j][0] = p0; S[j][1] = p1; S[j][2] = p2; S[j][3] = p3;
            rs0 += p0 + p1;
            rs1 += p2 + p3;
        }
        #pragma unroll
        for (int msk = 1; msk <= 2; msk <<= 1) {
            rs0 += __shfl_xor_sync(0xffffffffu, rs0, msk);
            rs1 += __shfl_xor_sync(0xffffffffu, rs1, msk);
        }
        l0 = l0 * alpha0 + rs0;
        l1 = l1 * alpha1 + rs1;
        m0 = mn0; m1 = mn1;
        #pragma unroll
        for (int n = 0; n < 10; n++) {
            acc[n][0] *= alpha0; acc[n][1] *= alpha0;
            acc[n][2] *= alpha1; acc[n][3] *= alpha1;
        }

        #pragma unroll
        for (int jc = 0; jc < 4; jc++) {
            float h00 = __bfloat162float(__float2bfloat16(S[2*jc][0]));
            float h01 = __bfloat162float(__float2bfloat16(S[2*jc][1]));
            float h02 = __bfloat162float(__float2bfloat16(S[2*jc][2]));
            float h03 = __bfloat162float(__float2bfloat16(S[2*jc][3]));
            float h10 = __bfloat162float(__float2bfloat16(S[2*jc+1][0]));
            float h11 = __bfloat162float(__float2bfloat16(S[2*jc+1][1]));
            float h12 = __bfloat162float(__float2bfloat16(S[2*jc+1][2]));
            float h13 = __bfloat162float(__float2bfloat16(S[2*jc+1][3]));
            uint32_t aPh[4], aPl[4];
            aPh[0] = pack_bf2(h00, h01);
            aPh[1] = pack_bf2(h02, h03);
            aPh[2] = pack_bf2(h10, h11);
            aPh[3] = pack_bf2(h12, h13);
            aPl[0] = pack_bf2(S[2*jc][0] - h00, S[2*jc][1] - h01);
            aPl[1] = pack_bf2(S[2*jc][2] - h02, S[2*jc][3] - h03);
            aPl[2] = pack_bf2(S[2*jc+1][0] - h10, S[2*jc+1][1] - h11);
            aPl[3] = pack_bf2(S[2*jc+1][2] - h12, S[2*jc+1][3] - h13);

            #pragma unroll
            for (int ng = 0; ng < 3; ng++) {
                const int gs = ng * 4;
                const int gn = (ng == 2) ? 2 : 4;
                uint32_t bh[4][2], bl[4][2];
                #pragma unroll
                for (int q = 0; q < 4; q++) {
                    if (q < gn) {
                        uint32_t voff = (uint32_t)(((gs + q) * 8 + b_row) * VSTR
                                                   + jc * 16 + b_kof) * 2;
                        LDSM_X2(bh[q][0], bh[q][1], smem_u32(Vh) + voff);
                        LDSM_X2(bl[q][0], bl[q][1], smem_u32(Vl) + voff);
                    }
                }
                #pragma unroll
                for (int q = 0; q < 4; q++)
                    if (q < gn)
                        MMA16816(acc[gs+q][0], acc[gs+q][1], acc[gs+q][2], acc[gs+q][3],
                                 aPh[0], aPh[1], aPh[2], aPh[3], bh[q][0], bh[q][1]);
                #pragma unroll
                for (int q = 0; q < 4; q++)
                    if (q < gn)
                        MMA16816(acc[gs+q][0], acc[gs+q][1], acc[gs+q][2], acc[gs+q][3],
                                 aPh[0], aPh[1], aPh[2], aPh[3], bl[q][0], bl[q][1]);
                #pragma unroll
                for (int q = 0; q < 4; q++)
                    if (q < gn)
                        MMA16816(acc[gs+q][0], acc[gs+q][1], acc[gs+q][2], acc[gs+q][3],
                                 aPl[0], aPl[1], aPl[2], aPl[3], bh[q][0], bh[q][1]);
            }
        }
    }

    // Epilogue: normalize + fused hi/lo decomposition
    float il0 = (l0 > 0.f) ? (1.f / l0) : 0.f;
    float il1 = (l1 > 0.f) ? (1.f / l1) : 0.f;
    #pragma unroll
    for (int n = 0; n < 10; n++) {
        int d = n * 8 + kq;
        size_t o0 = (size_t)(qbase + row0) * DIM + head * HEAD_DIM + d;
        size_t o1 = (size_t)(qbase + row1) * DIM + head * HEAD_DIM + d;
        float v00 = acc[n][0] * il0, v01 = acc[n][1] * il0;
        float v10 = acc[n][2] * il1, v11 = acc[n][3] * il1;
        __nv_bfloat16 h00 = __float2bfloat16(v00);
        __nv_bfloat16 h01 = __float2bfloat16(v01);
        __nv_bfloat16 h10 = __float2bfloat16(v10);
        __nv_bfloat16 h11 = __float2bfloat16(v11);
        g_at_h[o0]     = h00;
        g_at_h[o0 + 1] = h01;
        g_at_h[o1]     = h10;
        g_at_h[o1 + 1] = h11;
        g_at_l[o0]     = __float2bfloat16(v00 - __bfloat162float(h00));
        g_at_l[o0 + 1] = __float2bfloat16(v01 - __bfloat162float(h01));
        g_at_l[o1]     = __float2bfloat16(v10 - __bfloat162float(h10));
        g_at_l[o1 + 1] = __float2bfloat16(v11 - __bfloat162float(h11));
    }
}

// ---------------------------------------------------------------------------
extern "C" void kernel_launch(void* const* d_in, const int* in_sizes, int n_in,
                              void* d_out, int out_size)
{
    const float* hidden = (const float*)d_in[0];
    const float* rotary = (const float*)d_in[1];
    const int*   cu     = (const int*)d_in[2];
    const float* qkv_w  = (const float*)d_in[3];
    const float* qkv_b  = (const float*)d_in[4];
    const float* proj_w = (const float*)d_in[5];
    const float* proj_b = (const float*)d_in[6];
    float* out = (float*)d_out;
    int ncu = in_sizes[2];

    float *qkv_ptr;
    __nv_bfloat16 *hidH, *hidL, *wqH, *wqL, *wpH, *wpL, *atH, *atL;
    cudaGetSymbolAddress((void**)&qkv_ptr, g_qkv);
    cudaGetSymbolAddress((void**)&hidH, g_hid_h);
    cudaGetSymbolAddress((void**)&hidL, g_hid_l);
    cudaGetSymbolAddress((void**)&wqH, g_wq_h);
    cudaGetSymbolAddress((void**)&wqL, g_wq_l);
    cudaGetSymbolAddress((void**)&wpH, g_wp_h);
    cudaGetSymbolAddress((void**)&wpL, g_wp_l);
    cudaGetSymbolAddress((void**)&atH, g_at_h);
    cudaGetSymbolAddress((void**)&atL, g_at_l);

    cudaFuncSetAttribute(hgemm_split_kernel,
                         cudaFuncAttributeMaxDynamicSharedMemorySize, HG_SMEM);

    // 0) Decompose inputs (vectorized)
    decomp4_kernel<<<(SEQ * DIM / 4 + 255) / 256, 256>>>(
        (const float4*)hidden, (uint32_t*)hidH, (uint32_t*)hidL, SEQ * DIM / 4);
    decomp4_kernel<<<(QKV_DIM * DIM / 4 + 255) / 256, 256>>>(
        (const float4*)qkv_w, (uint32_t*)wqH, (uint32_t*)wqL, QKV_DIM * DIM / 4);
    decomp4_kernel<<<(DIM * DIM / 4 + 255) / 256, 256>>>(
        (const float4*)proj_w, (uint32_t*)wpH, (uint32_t*)wpL, DIM * DIM / 4);

    // 1) QKV GEMM
    hgemm_split_kernel<<<dim3(QKV_DIM / 128, SEQ / 128), 256, HG_SMEM>>>(
        hidH, hidL, wqH, wqL, qkv_b, qkv_ptr, SEQ, QKV_DIM, DIM);

    // 2) RoPE
    {
        int total = SEQ * 2 * HEADS * (HEAD_DIM / 2);
        rope_kernel<<<(total + 255) / 256, 256>>>(rotary);
    }

    // 3) Flash attention (HMMA, fused output decomposition)
    {
        cudaFuncSetAttribute(fattn_kernel,
                             cudaFuncAttributeMaxDynamicSharedMemorySize, FA_SMEM);
        fattn_kernel<<<dim3(SEQ / AQ, HEADS), 256, FA_SMEM>>>(cu, ncu);
    }

    // 4) proj GEMM (reads fused hi/lo planes)
    hgemm_split_kernel<<<dim3(DIM / 128, SEQ / 128), 256, HG_SMEM>>>(
        atH, atL, wpH, wpL, proj_b, out, SEQ, DIM, DIM);
}

// round 8
// speedup vs baseline: 2.9284x; 1.0242x over previous
#include <cuda_runtime.h>
#include <cuda_bf16.h>
#include <math.h>
#include <stdint.h>

#define SEQ      2048
#define DIM      1280
#define HEADS    16
#define HEAD_DIM 80
#define QKV_DIM  3840

// ---------------------------------------------------------------------------
// Scratch
// ---------------------------------------------------------------------------
__device__ float g_qkv[SEQ * QKV_DIM];
__device__ __nv_bfloat16 g_hid_h[SEQ * DIM],     g_hid_l[SEQ * DIM];
__device__ __nv_bfloat16 g_wq_h[QKV_DIM * DIM],  g_wq_l[QKV_DIM * DIM];
__device__ __nv_bfloat16 g_wp_h[DIM * DIM],      g_wp_l[DIM * DIM];
__device__ __nv_bfloat16 g_at_h[SEQ * DIM],      g_at_l[SEQ * DIM];

// ---------------------------------------------------------------------------
// PTX helpers
// ---------------------------------------------------------------------------
#define CP_ASYNC16(dst, src) \
    asm volatile("cp.async.cg.shared.global [%0], [%1], 16;" :: "r"(dst), "l"(src))
#define CP_COMMIT() asm volatile("cp.async.commit_group;")
#define CP_WAIT0()  asm volatile("cp.async.wait_group 0;")

#define LDSM_X4(r0,r1,r2,r3,addr) \
    asm volatile("ldmatrix.sync.aligned.m8n8.x4.shared.b16 {%0,%1,%2,%3}, [%4];" \
        : "=r"(r0),"=r"(r1),"=r"(r2),"=r"(r3) : "r"(addr))
#define LDSM_X2(r0,r1,addr) \
    asm volatile("ldmatrix.sync.aligned.m8n8.x2.shared.b16 {%0,%1}, [%2];" \
        : "=r"(r0),"=r"(r1) : "r"(addr))

#define MMA16816(c0,c1,c2,c3,a0,a1,a2,a3,b0,b1) \
    asm volatile("mma.sync.aligned.m16n8k16.row.col.f32.bf16.bf16.f32 " \
        "{%0,%1,%2,%3}, {%4,%5,%6,%7}, {%8,%9}, {%0,%1,%2,%3};" \
        : "+f"(c0),"+f"(c1),"+f"(c2),"+f"(c3) \
        : "r"(a0),"r"(a1),"r"(a2),"r"(a3),"r"(b0),"r"(b1))

__device__ __forceinline__ uint32_t smem_u32(const void* p) {
    return (uint32_t)__cvta_generic_to_shared(p);
}
__device__ __forceinline__ uint32_t pack_bf2(float a, float b) {
    __nv_bfloat162 v = __float22bfloat162_rn(make_float2(a, b));
    return *(uint32_t*)&v;
}

// ---------------------------------------------------------------------------
// Split-precision bf16 HGEMM (TN): C = A @ B^T + bias, fp32 accum.
// C = Ah·Bh + Ah·Bl + Al·Bh.
// Block tile 128x64, 8 warps (4x2), warp tile 32x32, KBLK=32 double-buffered.
// ~78 regs/thread -> 3 CTAs/SM (24 warps/SM) for latency hiding.
// ---------------------------------------------------------------------------
#define KBLK 32
#define KPAD 40
#define APLANE_B (128 * KPAD * 2)      // 10240
#define BPLANE_B (64 * KPAD * 2)       // 5120
#define STAGE_B (2 * APLANE_B + 2 * BPLANE_B)   // 30720
#define HG_SMEM (2 * STAGE_B)                   // 61440

__global__ void __launch_bounds__(256, 3) hgemm_split_kernel(
    const __nv_bfloat16* __restrict__ Ah_, const __nv_bfloat16* __restrict__ Al_,
    const __nv_bfloat16* __restrict__ Bh_, const __nv_bfloat16* __restrict__ Bl_,
    const float* __restrict__ bias, float* __restrict__ C,
    int M, int N, int K)
{
    extern __shared__ char smraw[];
    const uint32_t sb = smem_u32(smraw);

    const int tid = threadIdx.x;
    const int ln  = tid & 31;
    const int wid = tid >> 5;
    const int wm  = wid >> 1;     // 0..3 (m quadrant, 32 rows)
    const int wn  = wid & 1;      // 0..1 (n half, 32 cols)
    const int m0  = blockIdx.y * 128;
    const int n0  = blockIdx.x * 64;

    const __nv_bfloat16* gA[2] = { Ah_ + (size_t)m0 * K, Al_ + (size_t)m0 * K };
    const __nv_bfloat16* gB[2] = { Bh_ + (size_t)n0 * K, Bl_ + (size_t)n0 * K };

    // A: 512 chunks/plane (2/thread), B: 256 chunks/plane (1/thread)
    const int arow0 = tid >> 2;           // 0..63
    const int arow1 = (tid + 256) >> 2;   // 64..127
    const int brow  = tid >> 2;           // 0..63
    const int kc16  = (tid & 3) * 8;      // bf16 col of 16B chunk

    auto load_stage = [&](int kt, int s) {
        const uint32_t stb = sb + s * STAGE_B;
        #pragma unroll
        for (int p = 0; p < 2; p++) {
            const uint32_t pa = stb + p * APLANE_B;
            CP_ASYNC16(pa + (uint32_t)(arow0 * KPAD + kc16) * 2,
                       gA[p] + (size_t)arow0 * K + kt + kc16);
            CP_ASYNC16(pa + (uint32_t)(arow1 * KPAD + kc16) * 2,
                       gA[p] + (size_t)arow1 * K + kt + kc16);
        }
        #pragma unroll
        for (int p = 0; p < 2; p++) {
            const uint32_t pb = stb + 2 * APLANE_B + p * BPLANE_B;
            CP_ASYNC16(pb + (uint32_t)(brow * KPAD + kc16) * 2,
                       gB[p] + (size_t)brow * K + kt + kc16);
        }
        CP_COMMIT();
    };

    float acc[2][4][4];
    #pragma unroll
    for (int mi = 0; mi < 2; mi++)
        #pragma unroll
        for (int ni = 0; ni < 4; ni++)
            #pragma unroll
            for (int c = 0; c < 4; c++) acc[mi][ni][c] = 0.f;

    load_stage(0, 0);
    CP_WAIT0();
    __syncthreads();

    const int a_row = (ln & 15);
    const int a_kof = (ln < 16) ? 0 : 8;
    const int b_row = (ln & 7);
    const int b_kof = (ln & 8);

    int buf = 0;
    for (int kt = 0; kt < K; kt += KBLK) {
        const bool hasNext = (kt + KBLK) < K;
        if (hasNext) load_stage(kt + KBLK, buf ^ 1);

        const uint32_t stb = sb + buf * STAGE_B;
        const uint32_t pAh = stb;
        const uint32_t pAl = stb + APLANE_B;
        const uint32_t pBh = stb + 2 * APLANE_B;
        const uint32_t pBl = stb + 2 * APLANE_B + BPLANE_B;

        #pragma unroll
        for (int ks = 0; ks < 2; ks++) {
            const int k0 = ks * 16;
            uint32_t ah[2][4], al[2][4];
            #pragma unroll
            for (int mi = 0; mi < 2; mi++) {
                uint32_t off = (uint32_t)((wm * 32 + mi * 16 + a_row) * KPAD
                                          + k0 + a_kof) * 2;
                LDSM_X4(ah[mi][0], ah[mi][1], ah[mi][2], ah[mi][3], pAh + off);
                LDSM_X4(al[mi][0], al[mi][1], al[mi][2], al[mi][3], pAl + off);
            }
            uint32_t bh[4][2], bl[4][2];
            #pragma unroll
            for (int ni = 0; ni < 4; ni++) {
                uint32_t off = (uint32_t)((wn * 32 + ni * 8 + b_row) * KPAD
                                          + k0 + b_kof) * 2;
                LDSM_X2(bh[ni][0], bh[ni][1], pBh + off);
                LDSM_X2(bl[ni][0], bl[ni][1], pBl + off);
            }
            #pragma unroll
            for (int ni = 0; ni < 4; ni++)
                #pragma unroll
                for (int mi = 0; mi < 2; mi++)
                    MMA16816(acc[mi][ni][0], acc[mi][ni][1],
                             acc[mi][ni][2], acc[mi][ni][3],
                             ah[mi][0], ah[mi][1], ah[mi][2], ah[mi][3],
                             bh[ni][0], bh[ni][1]);
            #pragma unroll
            for (int ni = 0; ni < 4; ni++)
                #pragma unroll
                for (int mi = 0; mi < 2; mi++)
                    MMA16816(acc[mi][ni][0], acc[mi][ni][1],
                             acc[mi][ni][2], acc[mi][ni][3],
                             ah[mi][0], ah[mi][1], ah[mi][2], ah[mi][3],
                             bl[ni][0], bl[ni][1]);
            #pragma unroll
            for (int ni = 0; ni < 4; ni++)
                #pragma unroll
                for (int mi = 0; mi < 2; mi++)
                    MMA16816(acc[mi][ni][0], acc[mi][ni][1],
                             acc[mi][ni][2], acc[mi][ni][3],
                             al[mi][0], al[mi][1], al[mi][2], al[mi][3],
                             bh[ni][0], bh[ni][1]);
        }

        if (hasNext) {
            CP_WAIT0();
            __syncthreads();
            buf ^= 1;
        }
    }

    const int crow = ln >> 2;
    const int ccol = (ln & 3) * 2;
    #pragma unroll
    for (int mi = 0; mi < 2; mi++) {
        #pragma unroll
        for (int ni = 0; ni < 4; ni++) {
            int col = n0 + wn * 32 + ni * 8 + ccol;
            float b0 = bias[col], b1 = bias[col + 1];
            int r0 = m0 + wm * 32 + mi * 16 + crow;
            float2 v0 = make_float2(acc[mi][ni][0] + b0, acc[mi][ni][1] + b1);
            float2 v1 = make_float2(acc[mi][ni][2] + b0, acc[mi][ni][3] + b1);
            *(float2*)(C + (size_t)r0 * N + col)       = v0;
            *(float2*)(C + (size_t)(r0 + 8) * N + col) = v1;
        }
    }
}

// ---------------------------------------------------------------------------
// Vectorized decompose: fp32 -> separate bf16 hi/lo planes
// ---------------------------------------------------------------------------
__global__ void __launch_bounds__(256) decomp4_kernel(
    const float4* __restrict__ in, uint32_t* __restrict__ hi2,
    uint32_t* __restrict__ lo2, int total4)
{
    int idx = blockIdx.x * blockDim.x + threadIdx.x;
    if (idx >= total4) return;
    float4 v = in[idx];
    __nv_bfloat16 h0 = __float2bfloat16(v.x);
    __nv_bfloat16 h1 = __float2bfloat16(v.y);
    __nv_bfloat16 h2 = __float2bfloat16(v.z);
    __nv_bfloat16 h3 = __float2bfloat16(v.w);
    float l0 = v.x - __bfloat162float(h0);
    float l1 = v.y - __bfloat162float(h1);
    float l2 = v.z - __bfloat162float(h2);
    float l3 = v.w - __bfloat162float(h3);
    __nv_bfloat162 hA = make_bfloat162(h0, h1), hB = make_bfloat162(h2, h3);
    hi2[idx * 2]     = *(uint32_t*)&hA;
    hi2[idx * 2 + 1] = *(uint32_t*)&hB;
    lo2[idx * 2]     = pack_bf2(l0, l1);
    lo2[idx * 2 + 1] = pack_bf2(l2, l3);
}

// ---------------------------------------------------------------------------
// RoPE in-place on q, k
// ---------------------------------------------------------------------------
__global__ void __launch_bounds__(256) rope_kernel(const float* __restrict__ rot)
{
    int t = blockIdx.x * blockDim.x + threadIdx.x;
    const int total = SEQ * 2 * HEADS * (HEAD_DIM / 2);
    if (t >= total) return;
    int d2   = t % 40;
    int h    = (t / 40) % HEADS;
    int part = (t / (40 * HEADS)) % 2;
    int s    = t / (40 * HEADS * 2);
    float f = rot[s * 40 + d2];
    float si, co;
    sincosf(f, &si, &co);
    size_t base = (size_t)s * QKV_DIM + (size_t)part * DIM + h * HEAD_DIM;
    float x1 = g_qkv[base + d2];
    float x2 = g_qkv[base + 40 + d2];
    g_qkv[base + d2]      = x1 * co - x2 * si;
    g_qkv[base + 40 + d2] = x2 * co + x1 * si;
}

// ---------------------------------------------------------------------------
// Tensor-core flash attention (round-7, fused output decomposition)
// ---------------------------------------------------------------------------
#define AQ   128
#define AK   64
#define QSTR 88
#define VSTR 72
#define FA_SMEM ((2*AQ*QSTR + 2*AK*QSTR + 2*HEAD_DIM*VSTR) * 2 + (AQ + AK + 4) * 4)

__global__ void __launch_bounds__(256) fattn_kernel(const int* __restrict__ cu, int ncu)
{
    extern __shared__ char smraw[];
    __nv_bfloat16* Qh = (__nv_bfloat16*)smraw;
    __nv_bfloat16* Ql = Qh + AQ * QSTR;
    __nv_bfloat16* Kh = Ql + AQ * QSTR;
    __nv_bfloat16* Kl = Kh + AK * QSTR;
    __nv_bfloat16* Vh = Kl + AK * QSTR;
    __nv_bfloat16* Vl = Vh + HEAD_DIM * VSTR;
    int* segq  = (int*)(Vl + HEAD_DIM * VSTR);
    int* segk  = segq + AQ;
    int* range = segk + AK;

    const int tid = threadIdx.x;
    const int w   = tid >> 5;
    const int ln  = tid & 31;
    const int head  = blockIdx.y;
    const int qbase = blockIdx.x * AQ;
    const float scale = rsqrtf((float)HEAD_DIM);

    #pragma unroll
    for (int i = 0; i < 40; i++) {
        int idx = tid + i * 256;
        int r = idx / HEAD_DIM, d = idx - r * HEAD_DIM;
        float v = g_qkv[(size_t)(qbase + r) * QKV_DIM + head * HEAD_DIM + d] * scale;
        __nv_bfloat16 hi = __float2bfloat16(v);
        Qh[r * QSTR + d] = hi;
        Ql[r * QSTR + d] = __float2bfloat16(v - __bfloat162float(hi));
    }
    if (tid < AQ) {
        int i = qbase + tid;
        int s = 0;
        for (int j = 1; j < ncu; j++) s += (cu[j] <= i);
        segq[tid] = s;
    }
    __syncthreads();
    if (tid == 0) {
        int smin = segq[0], smax = segq[0];
        for (int r = 1; r < AQ; r++) { smin = min(smin, segq[r]); smax = max(smax, segq[r]); }
        range[0] = cu[smin];
        range[1] = cu[smax + 1];
    }
    __syncthreads();
    const int lo = range[0], hi_ = range[1];

    const int qr = ln >> 2;
    const int kq = (ln & 3) * 2;
    const int row0 = w * 16 + qr;
    const int row1 = row0 + 8;
    const int sq0 = segq[row0], sq1 = segq[row1];

    float m0 = -1e30f, m1 = -1e30f, l0 = 0.f, l1 = 0.f;
    float acc[10][4];
    #pragma unroll
    for (int n = 0; n < 10; n++)
        #pragma unroll
        for (int c = 0; c < 4; c++) acc[n][c] = 0.f;

    const int a_row = (ln & 15);
    const int a_kof = (ln < 16) ? 0 : 8;
    const int b_row = (ln & 7);
    const int b_kof = (ln & 8);

    for (int kt = lo; kt < hi_; kt += AK) {
        __syncthreads();
        #pragma unroll
        for (int i = 0; i < 20; i++) {
            int idx = tid + i * 256;
            int r = idx / HEAD_DIM, d = idx - r * HEAD_DIM;
            int key = kt + r;
            float kv = 0.f, vv = 0.f;
            if (key < hi_) {
                size_t base = (size_t)key * QKV_DIM + head * HEAD_DIM + d;
                kv = g_qkv[base + DIM];
                vv = g_qkv[base + 2 * DIM];
            }
            __nv_bfloat16 kh = __float2bfloat16(kv);
            Kh[r * QSTR + d] = kh;
            Kl[r * QSTR + d] = __float2bfloat16(kv - __bfloat162float(kh));
            __nv_bfloat16 vh = __float2bfloat16(vv);
            Vh[d * VSTR + r] = vh;
            Vl[d * VSTR + r] = __float2bfloat16(vv - __bfloat162float(vh));
        }
        if (tid < AK) {
            int key = kt + tid;
            int s = -1;
            if (key < hi_) {
                s = 0;
                for (int j = 1; j < ncu; j++) s += (cu[j] <= key);
            }
            segk[tid] = s;
        }
        __syncthreads();

        float S[8][4];
        #pragma unroll
        for (int j = 0; j < 8; j++)
            #pragma unroll
            for (int c = 0; c < 4; c++) S[j][c] = 0.f;

        #pragma unroll
        for (int kc = 0; kc < 5; kc++) {
            uint32_t ah[4], al[4];
            uint32_t qoff = (uint32_t)((w * 16 + a_row) * QSTR + kc * 16 + a_kof) * 2;
            LDSM_X4(ah[0], ah[1], ah[2], ah[3], smem_u32(Qh) + qoff);
            LDSM_X4(al[0], al[1], al[2], al[3], smem_u32(Ql) + qoff);
            #pragma unroll
            for (int jg = 0; jg < 2; jg++) {
                uint32_t bh[4][2], bl[4][2];
                #pragma unroll
                for (int q = 0; q < 4; q++) {
                    uint32_t koff = (uint32_t)(((jg * 4 + q) * 8 + b_row) * QSTR
                                               + kc * 16 + b_kof) * 2;
                    LDSM_X2(bh[q][0], bh[q][1], smem_u32(Kh) + koff);
                    LDSM_X2(bl[q][0], bl[q][1], smem_u32(Kl) + koff);
                }
                #pragma unroll
                for (int q = 0; q < 4; q++) {
                    int j = jg * 4 + q;
                    MMA16816(S[j][0], S[j][1], S[j][2], S[j][3],
                             ah[0], ah[1], ah[2], ah[3], bh[q][0], bh[q][1]);
                }
                #pragma unroll
                for (int q = 0; q < 4; q++) {
                    int j = jg * 4 + q;
                    MMA16816(S[j][0], S[j][1], S[j][2], S[j][3],
                             ah[0], ah[1], ah[2], ah[3], bl[q][0], bl[q][1]);
                }
                #pragma unroll
                for (int q = 0; q < 4; q++) {
                    int j = jg * 4 + q;
                    MMA16816(S[j][0], S[j][1], S[j][2], S[j][3],
                             al[0], al[1], al[2], al[3], bh[q][0], bh[q][1]);
                }
            }
        }

        float mt0 = -1e30f, mt1 = -1e30f;
        #pragma unroll
        for (int j = 0; j < 8; j++) {
            int k0 = j * 8 + kq;
            int sk0 = segk[k0], sk1 = segk[k0 + 1];
            mt0 = fmaxf(mt0, (sk0 == sq0) ? S[j][0] : -1e30f);
            mt0 = fmaxf(mt0, (sk1 == sq0) ? S[j][1] : -1e30f);
            mt1 = fmaxf(mt1, (sk0 == sq1) ? S[j][2] : -1e30f);
            mt1 = fmaxf(mt1, (sk1 == sq1) ? S[j][3] : -1e30f);
        }
        #pragma unroll
        for (int msk = 1; msk <= 2; msk <<= 1) {
            mt0 = fmaxf(mt0, __shfl_xor_sync(0xffffffffu, mt0, msk));
            mt1 = fmaxf(mt1, __shfl_xor_sync(0xffffffffu, mt1, msk));
        }
        float mn0 = fmaxf(m0, mt0), mn1 = fmaxf(m1, mt1);
        float alpha0 = __expf(m0 - mn0), alpha1 = __expf(m1 - mn1);
        float rs0 = 0.f, rs1 = 0.f;
        #pragma unroll
        for (int j = 0; j < 8; j++) {
            int k0 = j * 8 + kq;
            int sk0 = segk[k0], sk1 = segk[k0 + 1];
            float p0 = (sk0 == sq0) ? __expf(S[j][0] - mn0) : 0.f;
            float p1 = (sk1 == sq0) ? __expf(S[j][1] - mn0) : 0.f;
            float p2 = (sk0 == sq1) ? __expf(S[j][2] - mn1) : 0.f;
            float p3 = (sk1 == sq1) ? __expf(S[j][3] - mn1) : 0.f;
            S[j][0] = p0; S[j][1] = p1; S[j][2] = p2; S[j][3] = p3;
            rs0 += p0 + p1;
            rs1 += p2 + p3;
        }
        #pragma unroll
        for (int msk = 1; msk <= 2; msk <<= 1) {
            rs0 += __shfl_xor_sync(0xffffffffu, rs0, msk);
            rs1 += __shfl_xor_sync(0xffffffffu, rs1, msk);
        }
        l0 = l0 * alpha0 + rs0;
        l1 = l1 * alpha1 + rs1;
        m0 = mn0; m1 = mn1;
        #pragma unroll
        for (int n = 0; n < 10; n++) {
            acc[n][0] *= alpha0; acc[n][1] *= alpha0;
            acc[n][2] *= alpha1; acc[n][3] *= alpha1;
        }

        #pragma unroll
        for (int jc = 0; jc < 4; jc++) {
            float h00 = __bfloat162float(__float2bfloat16(S[2*jc][0]));
            float h01 = __bfloat162float(__float2bfloat16(S[2*jc][1]));
            float h02 = __bfloat162float(__float2bfloat16(S[2*jc][2]));
            float h03 = __bfloat162float(__float2bfloat16(S[2*jc][3]));
            float h10 = __bfloat162float(__float2bfloat16(S[2*jc+1][0]));
            float h11 = __bfloat162float(__float2bfloat16(S[2*jc+1][1]));
            float h12 = __bfloat162float(__float2bfloat16(S[2*jc+1][2]));
            float h13 = __bfloat162float(__float2bfloat16(S[2*jc+1][3]));
            uint32_t aPh[4], aPl[4];
            aPh[0] = pack_bf2(h00, h01);
            aPh[1] = pack_bf2(h02, h03);
            aPh[2] = pack_bf2(h10, h11);
            aPh[3] = pack_bf2(h12, h13);
            aPl[0] = pack_bf2(S[2*jc][0] - h00, S[2*jc][1] - h01);
            aPl[1] = pack_bf2(S[2*jc][2] - h02, S[2*jc][3] - h03);
            aPl[2] = pack_bf2(S[2*jc+1][0] - h10, S[2*jc+1][1] - h11);
            aPl[3] = pack_bf2(S[2*jc+1][2] - h12, S[2*jc+1][3] - h13);

            #pragma unroll
            for (int ng = 0; ng < 3; ng++) {
                const int gs = ng * 4;
                const int gn = (ng == 2) ? 2 : 4;
                uint32_t bh[4][2], bl[4][2];
                #pragma unroll
                for (int q = 0; q < 4; q++) {
                    if (q < gn) {
                        uint32_t voff = (uint32_t)(((gs + q) * 8 + b_row) * VSTR
                                                   + jc * 16 + b_kof) * 2;
                        LDSM_X2(bh[q][0], bh[q][1], smem_u32(Vh) + voff);
                        LDSM_X2(bl[q][0], bl[q][1], smem_u32(Vl) + voff);
                    }
                }
                #pragma unroll
                for (int q = 0; q < 4; q++)
                    if (q < gn)
                        MMA16816(acc[gs+q][0], acc[gs+q][1], acc[gs+q][2], acc[gs+q][3],
                                 aPh[0], aPh[1], aPh[2], aPh[3], bh[q][0], bh[q][1]);
                #pragma unroll
                for (int q = 0; q < 4; q++)
                    if (q < gn)
                        MMA16816(acc[gs+q][0], acc[gs+q][1], acc[gs+q][2], acc[gs+q][3],
                                 aPh[0], aPh[1], aPh[2], aPh[3], bl[q][0], bl[q][1]);
                #pragma unroll
                for (int q = 0; q < 4; q++)
                    if (q < gn)
                        MMA16816(acc[gs+q][0], acc[gs+q][1], acc[gs+q][2], acc[gs+q][3],
                                 aPl[0], aPl[1], aPl[2], aPl[3], bh[q][0], bh[q][1]);
            }
        }
    }

    float il0 = (l0 > 0.f) ? (1.f / l0) : 0.f;
    float il1 = (l1 > 0.f) ? (1.f / l1) : 0.f;
    #pragma unroll
    for (int n = 0; n < 10; n++) {
        int d = n * 8 + kq;
        size_t o0 = (size_t)(qbase + row0) * DIM + head * HEAD_DIM + d;
        size_t o1 = (size_t)(qbase + row1) * DIM + head * HEAD_DIM + d;
        float v00 = acc[n][0] * il0, v01 = acc[n][1] * il0;
        float v10 = acc[n][2] * il1, v11 = acc[n][3] * il1;
        __nv_bfloat16 h00 = __float2bfloat16(v00);
        __nv_bfloat16 h01 = __float2bfloat16(v01);
        __nv_bfloat16 h10 = __float2bfloat16(v10);
        __nv_bfloat16 h11 = __float2bfloat16(v11);
        g_at_h[o0]     = h00;
        g_at_h[o0 + 1] = h01;
        g_at_h[o1]     = h10;
        g_at_h[o1 + 1] = h11;
        g_at_l[o0]     = __float2bfloat16(v00 - __bfloat162float(h00));
        g_at_l[o0 + 1] = __float2bfloat16(v01 - __bfloat162float(h01));
        g_at_l[o1]     = __float2bfloat16(v10 - __bfloat162float(h10));
        g_at_l[o1 + 1] = __float2bfloat16(v11 - __bfloat162float(h11));
    }
}

// ---------------------------------------------------------------------------
extern "C" void kernel_launch(void* const* d_in, const int* in_sizes, int n_in,
                              void* d_out, int out_size)
{
    const float* hidden = (const float*)d_in[0];
    const float* rotary = (const float*)d_in[1];
    const int*   cu     = (const int*)d_in[2];
    const float* qkv_w  = (const float*)d_in[3];
    const float* qkv_b  = (const float*)d_in[4];
    const float* proj_w = (const float*)d_in[5];
    const float* proj_b = (const float*)d_in[6];
    float* out = (float*)d_out;
    int ncu = in_sizes[2];

    float *qkv_ptr;
    __nv_bfloat16 *hidH, *hidL, *wqH, *wqL, *wpH, *wpL, *atH, *atL;
    cudaGetSymbolAddress((void**)&qkv_ptr, g_qkv);
    cudaGetSymbolAddress((void**)&hidH, g_hid_h);
    cudaGetSymbolAddress((void**)&hidL, g_hid_l);
    cudaGetSymbolAddress((void**)&wqH, g_wq_h);
    cudaGetSymbolAddress((void**)&wqL, g_wq_l);
    cudaGetSymbolAddress((void**)&wpH, g_wp_h);
    cudaGetSymbolAddress((void**)&wpL, g_wp_l);
    cudaGetSymbolAddress((void**)&atH, g_at_h);
    cudaGetSymbolAddress((void**)&atL, g_at_l);

    cudaFuncSetAttribute(hgemm_split_kernel,
                         cudaFuncAttributeMaxDynamicSharedMemorySize, HG_SMEM);

    // 0) Decompose inputs
    decomp4_kernel<<<(SEQ * DIM / 4 + 255) / 256, 256>>>(
        (const float4*)hidden, (uint32_t*)hidH, (uint32_t*)hidL, SEQ * DIM / 4);
    decomp4_kernel<<<(QKV_DIM * DIM / 4 + 255) / 256, 256>>>(
        (const float4*)qkv_w, (uint32_t*)wqH, (uint32_t*)wqL, QKV_DIM * DIM / 4);
    decomp4_kernel<<<(DIM * DIM / 4 + 255) / 256, 256>>>(
        (const float4*)proj_w, (uint32_t*)wpH, (uint32_t*)wpL, DIM * DIM / 4);

    // 1) QKV GEMM (128x64 tiles)
    hgemm_split_kernel<<<dim3(QKV_DIM / 64, SEQ / 128), 256, HG_SMEM>>>(
        hidH, hidL, wqH, wqL, qkv_b, qkv_ptr, SEQ, QKV_DIM, DIM);

    // 2) RoPE
    {
        int total = SEQ * 2 * HEADS * (HEAD_DIM / 2);
        rope_kernel<<<(total + 255) / 256, 256>>>(rotary);
    }

    // 3) Flash attention (HMMA, fused output decomposition)
    {
        cudaFuncSetAttribute(fattn_kernel,
                             cudaFuncAttributeMaxDynamicSharedMemorySize, FA_SMEM);
        fattn_kernel<<<dim3(SEQ / AQ, HEADS), 256, FA_SMEM>>>(cu, ncu);
    }

    // 4) proj GEMM
    hgemm_split_kernel<<<dim3(DIM / 64, SEQ / 128), 256, HG_SMEM>>>(
        atH, atL, wpH, wpL, proj_b, out, SEQ, DIM, DIM);
}

// round 9
// speedup vs baseline: 3.0126x; 1.0287x over previous
#include <cuda_runtime.h>
#include <cuda_bf16.h>
#include <math.h>
#include <stdint.h>

#define SEQ      2048
#define DIM      1280
#define HEADS    16
#define HEAD_DIM 80
#define QKV_DIM  3840

// ---------------------------------------------------------------------------
// Scratch
// ---------------------------------------------------------------------------
__device__ float g_qkv[SEQ * QKV_DIM];
__device__ __nv_bfloat16 g_hid_h[SEQ * DIM],     g_hid_l[SEQ * DIM];
__device__ __nv_bfloat16 g_wq_h[QKV_DIM * DIM],  g_wq_l[QKV_DIM * DIM];
__device__ __nv_bfloat16 g_wp_h[DIM * DIM],      g_wp_l[DIM * DIM];
__device__ __nv_bfloat16 g_at_h[SEQ * DIM],      g_at_l[SEQ * DIM];
// attention operand planes: Q/K [h][s][d], V transposed [h][d][s]
__device__ __nv_bfloat16 g_q_h[HEADS * SEQ * HEAD_DIM], g_q_l[HEADS * SEQ * HEAD_DIM];
__device__ __nv_bfloat16 g_k_h[HEADS * SEQ * HEAD_DIM], g_k_l[HEADS * SEQ * HEAD_DIM];
__device__ __nv_bfloat16 g_vt_h[HEADS * HEAD_DIM * SEQ], g_vt_l[HEADS * HEAD_DIM * SEQ];

// ---------------------------------------------------------------------------
// PTX helpers
// ---------------------------------------------------------------------------
#define CP_ASYNC16(dst, src) \
    asm volatile("cp.async.cg.shared.global [%0], [%1], 16;" :: "r"(dst), "l"(src))
#define CP_COMMIT() asm volatile("cp.async.commit_group;")
#define CP_WAIT(n)  asm volatile("cp.async.wait_group %0;" :: "n"(n))

#define LDSM_X4(r0,r1,r2,r3,addr) \
    asm volatile("ldmatrix.sync.aligned.m8n8.x4.shared.b16 {%0,%1,%2,%3}, [%4];" \
        : "=r"(r0),"=r"(r1),"=r"(r2),"=r"(r3) : "r"(addr))
#define LDSM_X2(r0,r1,addr) \
    asm volatile("ldmatrix.sync.aligned.m8n8.x2.shared.b16 {%0,%1}, [%2];" \
        : "=r"(r0),"=r"(r1) : "r"(addr))

#define MMA16816(c0,c1,c2,c3,a0,a1,a2,a3,b0,b1) \
    asm volatile("mma.sync.aligned.m16n8k16.row.col.f32.bf16.bf16.f32 " \
        "{%0,%1,%2,%3}, {%4,%5,%6,%7}, {%8,%9}, {%0,%1,%2,%3};" \
        : "+f"(c0),"+f"(c1),"+f"(c2),"+f"(c3) \
        : "r"(a0),"r"(a1),"r"(a2),"r"(a3),"r"(b0),"r"(b1))

__device__ __forceinline__ uint32_t smem_u32(const void* p) {
    return (uint32_t)__cvta_generic_to_shared(p);
}
__device__ __forceinline__ uint32_t pack_bf2(float a, float b) {
    __nv_bfloat162 v = __float22bfloat162_rn(make_float2(a, b));
    return *(uint32_t*)&v;
}

// ---------------------------------------------------------------------------
// Split-precision bf16 HGEMM (round-8, at mma.sync roofline — unchanged)
// ---------------------------------------------------------------------------
#define KBLK 32
#define KPAD 40
#define APLANE_B (128 * KPAD * 2)
#define BPLANE_B (64 * KPAD * 2)
#define STAGE_B (2 * APLANE_B + 2 * BPLANE_B)
#define HG_SMEM (2 * STAGE_B)

__global__ void __launch_bounds__(256, 3) hgemm_split_kernel(
    const __nv_bfloat16* __restrict__ Ah_, const __nv_bfloat16* __restrict__ Al_,
    const __nv_bfloat16* __restrict__ Bh_, const __nv_bfloat16* __restrict__ Bl_,
    const float* __restrict__ bias, float* __restrict__ C,
    int M, int N, int K)
{
    extern __shared__ char smraw[];
    const uint32_t sb = smem_u32(smraw);

    const int tid = threadIdx.x;
    const int ln  = tid & 31;
    const int wid = tid >> 5;
    const int wm  = wid >> 1;
    const int wn  = wid & 1;
    const int m0  = blockIdx.y * 128;
    const int n0  = blockIdx.x * 64;

    const __nv_bfloat16* gA[2] = { Ah_ + (size_t)m0 * K, Al_ + (size_t)m0 * K };
    const __nv_bfloat16* gB[2] = { Bh_ + (size_t)n0 * K, Bl_ + (size_t)n0 * K };

    const int arow0 = tid >> 2;
    const int arow1 = (tid + 256) >> 2;
    const int brow  = tid >> 2;
    const int kc16  = (tid & 3) * 8;

    auto load_stage = [&](int kt, int s) {
        const uint32_t stb = sb + s * STAGE_B;
        #pragma unroll
        for (int p = 0; p < 2; p++) {
            const uint32_t pa = stb + p * APLANE_B;
            CP_ASYNC16(pa + (uint32_t)(arow0 * KPAD + kc16) * 2,
                       gA[p] + (size_t)arow0 * K + kt + kc16);
            CP_ASYNC16(pa + (uint32_t)(arow1 * KPAD + kc16) * 2,
                       gA[p] + (size_t)arow1 * K + kt + kc16);
        }
        #pragma unroll
        for (int p = 0; p < 2; p++) {
            const uint32_t pb = stb + 2 * APLANE_B + p * BPLANE_B;
            CP_ASYNC16(pb + (uint32_t)(brow * KPAD + kc16) * 2,
                       gB[p] + (size_t)brow * K + kt + kc16);
        }
        CP_COMMIT();
    };

    float acc[2][4][4];
    #pragma unroll
    for (int mi = 0; mi < 2; mi++)
        #pragma unroll
        for (int ni = 0; ni < 4; ni++)
            #pragma unroll
            for (int c = 0; c < 4; c++) acc[mi][ni][c] = 0.f;

    load_stage(0, 0);
    CP_WAIT(0);
    __syncthreads();

    const int a_row = (ln & 15);
    const int a_kof = (ln < 16) ? 0 : 8;
    const int b_row = (ln & 7);
    const int b_kof = (ln & 8);

    int buf = 0;
    for (int kt = 0; kt < K; kt += KBLK) {
        const bool hasNext = (kt + KBLK) < K;
        if (hasNext) load_stage(kt + KBLK, buf ^ 1);

        const uint32_t stb = sb + buf * STAGE_B;
        const uint32_t pAh = stb;
        const uint32_t pAl = stb + APLANE_B;
        const uint32_t pBh = stb + 2 * APLANE_B;
        const uint32_t pBl = stb + 2 * APLANE_B + BPLANE_B;

        #pragma unroll
        for (int ks = 0; ks < 2; ks++) {
            const int k0 = ks * 16;
            uint32_t ah[2][4], al[2][4];
            #pragma unroll
            for (int mi = 0; mi < 2; mi++) {
                uint32_t off = (uint32_t)((wm * 32 + mi * 16 + a_row) * KPAD
                                          + k0 + a_kof) * 2;
                LDSM_X4(ah[mi][0], ah[mi][1], ah[mi][2], ah[mi][3], pAh + off);
                LDSM_X4(al[mi][0], al[mi][1], al[mi][2], al[mi][3], pAl + off);
            }
            uint32_t bh[4][2], bl[4][2];
            #pragma unroll
            for (int ni = 0; ni < 4; ni++) {
                uint32_t off = (uint32_t)((wn * 32 + ni * 8 + b_row) * KPAD
                                          + k0 + b_kof) * 2;
                LDSM_X2(bh[ni][0], bh[ni][1], pBh + off);
                LDSM_X2(bl[ni][0], bl[ni][1], pBl + off);
            }
            #pragma unroll
            for (int ni = 0; ni < 4; ni++)
                #pragma unroll
                for (int mi = 0; mi < 2; mi++)
                    MMA16816(acc[mi][ni][0], acc[mi][ni][1],
                             acc[mi][ni][2], acc[mi][ni][3],
                             ah[mi][0], ah[mi][1], ah[mi][2], ah[mi][3],
                             bh[ni][0], bh[ni][1]);
            #pragma unroll
            for (int ni = 0; ni < 4; ni++)
                #pragma unroll
                for (int mi = 0; mi < 2; mi++)
                    MMA16816(acc[mi][ni][0], acc[mi][ni][1],
                             acc[mi][ni][2], acc[mi][ni][3],
                             ah[mi][0], ah[mi][1], ah[mi][2], ah[mi][3],
                             bl[ni][0], bl[ni][1]);
            #pragma unroll
            for (int ni = 0; ni < 4; ni++)
                #pragma unroll
                for (int mi = 0; mi < 2; mi++)
                    MMA16816(acc[mi][ni][0], acc[mi][ni][1],
                             acc[mi][ni][2], acc[mi][ni][3],
                             al[mi][0], al[mi][1], al[mi][2], al[mi][3],
                             bh[ni][0], bh[ni][1]);
        }

        if (hasNext) {
            CP_WAIT(0);
            __syncthreads();
            buf ^= 1;
        }
    }

    const int crow = ln >> 2;
    const int ccol = (ln & 3) * 2;
    #pragma unroll
    for (int mi = 0; mi < 2; mi++) {
        #pragma unroll
        for (int ni = 0; ni < 4; ni++) {
            int col = n0 + wn * 32 + ni * 8 + ccol;
            float b0 = bias[col], b1 = bias[col + 1];
            int r0 = m0 + wm * 32 + mi * 16 + crow;
            float2 v0 = make_float2(acc[mi][ni][0] + b0, acc[mi][ni][1] + b1);
            float2 v1 = make_float2(acc[mi][ni][2] + b0, acc[mi][ni][3] + b1);
            *(float2*)(C + (size_t)r0 * N + col)       = v0;
            *(float2*)(C + (size_t)(r0 + 8) * N + col) = v1;
        }
    }
}

// ---------------------------------------------------------------------------
// Vectorized decompose
// ---------------------------------------------------------------------------
__global__ void __launch_bounds__(256) decomp4_kernel(
    const float4* __restrict__ in, uint32_t* __restrict__ hi2,
    uint32_t* __restrict__ lo2, int total4)
{
    int idx = blockIdx.x * blockDim.x + threadIdx.x;
    if (idx >= total4) return;
    float4 v = in[idx];
    __nv_bfloat16 h0 = __float2bfloat16(v.x);
    __nv_bfloat16 h1 = __float2bfloat16(v.y);
    __nv_bfloat16 h2 = __float2bfloat16(v.z);
    __nv_bfloat16 h3 = __float2bfloat16(v.w);
    float l0 = v.x - __bfloat162float(h0);
    float l1 = v.y - __bfloat162float(h1);
    float l2 = v.z - __bfloat162float(h2);
    float l3 = v.w - __bfloat162float(h3);
    __nv_bfloat162 hA = make_bfloat162(h0, h1), hB = make_bfloat162(h2, h3);
    hi2[idx * 2]     = *(uint32_t*)&hA;
    hi2[idx * 2 + 1] = *(uint32_t*)&hB;
    lo2[idx * 2]     = pack_bf2(l0, l1);
    lo2[idx * 2 + 1] = pack_bf2(l2, l3);
}

// ---------------------------------------------------------------------------
// Q/K prep: rope + scale(Q) + hi/lo decomp -> [h][s][d] planes
// ---------------------------------------------------------------------------
__global__ void __launch_bounds__(256) qkprep_kernel(const float* __restrict__ rot)
{
    int t = blockIdx.x * blockDim.x + threadIdx.x;
    const int total = SEQ * HEADS * (HEAD_DIM / 2);
    if (t >= total) return;
    int d2 = t % 40;
    int h  = (t / 40) % HEADS;
    int s  = t / (40 * HEADS);

    float f = rot[s * 40 + d2];
    float si, co;
    sincosf(f, &si, &co);
    const float scale = rsqrtf((float)HEAD_DIM);

    size_t qb = (size_t)s * QKV_DIM + h * HEAD_DIM;
    float q1 = g_qkv[qb + d2],        q2 = g_qkv[qb + 40 + d2];
    float k1 = g_qkv[qb + DIM + d2],  k2 = g_qkv[qb + DIM + 40 + d2];

    float qr1 = (q1 * co - q2 * si) * scale;
    float qr2 = (q2 * co + q1 * si) * scale;
    float kr1 = k1 * co - k2 * si;
    float kr2 = k2 * co + k1 * si;

    size_t ob = ((size_t)h * SEQ + s) * HEAD_DIM;
    __nv_bfloat16 hq1 = __float2bfloat16(qr1);
    __nv_bfloat16 hq2 = __float2bfloat16(qr2);
    __nv_bfloat16 hk1 = __float2bfloat16(kr1);
    __nv_bfloat16 hk2 = __float2bfloat16(kr2);
    g_q_h[ob + d2]      = hq1;
    g_q_h[ob + 40 + d2] = hq2;
    g_q_l[ob + d2]      = __float2bfloat16(qr1 - __bfloat162float(hq1));
    g_q_l[ob + 40 + d2] = __float2bfloat16(qr2 - __bfloat162float(hq2));
    g_k_h[ob + d2]      = hk1;
    g_k_h[ob + 40 + d2] = hk2;
    g_k_l[ob + d2]      = __float2bfloat16(kr1 - __bfloat162float(hk1));
    g_k_l[ob + 40 + d2] = __float2bfloat16(kr2 - __bfloat162float(hk2));
}

// ---------------------------------------------------------------------------
// V prep: transpose + hi/lo decomp -> [h][d][s] planes (smem transpose)
// ---------------------------------------------------------------------------
__global__ void __launch_bounds__(256) vtprep_kernel()
{
    __shared__ float T[HEAD_DIM][65];
    const int tid = threadIdx.x;
    const int s0  = blockIdx.x * 64;
    const int h   = blockIdx.y;

    #pragma unroll
    for (int i = 0; i < 20; i++) {
        int idx = tid + i * 256;           // 64*80 = 5120
        int r = idx / HEAD_DIM, d = idx % HEAD_DIM;
        T[d][r] = g_qkv[(size_t)(s0 + r) * QKV_DIM + 2 * DIM + h * HEAD_DIM + d];
    }
    __syncthreads();
    #pragma unroll
    for (int i = 0; i < 20; i++) {
        int idx = tid + i * 256;
        int d = idx / 64, r = idx % 64;
        float v = T[d][r];
        __nv_bfloat16 hi = __float2bfloat16(v);
        size_t o = ((size_t)h * HEAD_DIM + d) * SEQ + s0 + r;
        g_vt_h[o] = hi;
        g_vt_l[o] = __float2bfloat16(v - __bfloat162float(hi));
    }
}

// ---------------------------------------------------------------------------
// Tensor-core flash attention: cp.async bf16-plane loads, double-buffered K/V.
// Block = (head, 128 queries), 8 warps; warp owns 16 query rows.
// ---------------------------------------------------------------------------
#define AQ    128
#define AK    64
#define QSTR  88      // bf16 stride (176 B rows)
#define VSTR  72      // bf16 stride (144 B rows)
#define QPL   (AQ * QSTR * 2)        // 22528 B per Q plane
#define KPL   (AK * QSTR * 2)        // 11264 B per K plane
#define VPL   (HEAD_DIM * VSTR * 2)  // 11520 B per V plane
#define KSTG  (2 * KPL)
#define VSTG  (2 * VPL)
#define FA_SMEM (2*QPL + 2*KSTG + 2*VSTG + (AQ + 2*AK + 4) * 4)

__global__ void __launch_bounds__(256) fattn_kernel(const int* __restrict__ cu, int ncu)
{
    extern __shared__ char smraw[];
    char* Qb  = smraw;                       // Qh, Ql planes
    char* Kb  = Qb + 2 * QPL;                // 2 stages x (Kh, Kl)
    char* Vb  = Kb + 2 * KSTG;               // 2 stages x (Vh, Vl)
    int* segq  = (int*)(Vb + 2 * VSTG);      // AQ
    int* segk  = segq + AQ;                  // 2 x AK
    int* range = segk + 2 * AK;

    const int tid = threadIdx.x;
    const int w   = tid >> 5;
    const int ln  = tid & 31;
    const int head  = blockIdx.y;
    const int qbase = blockIdx.x * AQ;

    const __nv_bfloat16* gq[2] = { g_q_h, g_q_l };
    const __nv_bfloat16* gk[2] = { g_k_h, g_k_l };
    const __nv_bfloat16* gv[2] = { g_vt_h, g_vt_l };

    // ---- Q planes via cp.async: 2560 chunks of 16B, 10/thread ----
    {
        const uint32_t qs = smem_u32(Qb);
        #pragma unroll
        for (int i = 0; i < 10; i++) {
            int idx = tid + i * 256;
            int pl = idx / 1280, rem = idx % 1280;
            int r = rem / 10, c = rem % 10;
            CP_ASYNC16(qs + pl * QPL + (uint32_t)(r * QSTR + c * 8) * 2,
                       gq[pl] + ((size_t)head * SEQ + qbase + r) * HEAD_DIM + c * 8);
        }
        CP_COMMIT();
    }
    if (tid < AQ) {
        int i = qbase + tid;
        int s = 0;
        for (int j = 1; j < ncu; j++) s += (cu[j] <= i);
        segq[tid] = s;
    }
    __syncthreads();
    if (tid == 0) {
        int smin = segq[0], smax = segq[0];
        for (int r = 1; r < AQ; r++) { smin = min(smin, segq[r]); smax = max(smax, segq[r]); }
        range[0] = cu[smin];
        range[1] = cu[smax + 1];
    }
    __syncthreads();
    const int lo = range[0], hi_ = range[1];

    // K/V tile loader into stage st (1 commit group)
    auto load_kv = [&](int kt, int st) {
        const uint32_t ks = smem_u32(Kb) + st * KSTG;
        const uint32_t vs = smem_u32(Vb) + st * VSTG;
        #pragma unroll
        for (int i = 0; i < 5; i++) {             // K: 1280 chunks
            int idx = tid + i * 256;
            int pl = idx / 640, rem = idx % 640;
            int r = rem / 10, c = rem % 10;
            int row = min(kt + r, SEQ - 1);
            CP_ASYNC16(ks + pl * KPL + (uint32_t)(r * QSTR + c * 8) * 2,
                       gk[pl] + ((size_t)head * SEQ + row) * HEAD_DIM + c * 8);
        }
        #pragma unroll
        for (int i = 0; i < 5; i++) {             // V: 1280 chunks
            int idx = tid + i * 256;
            int pl = idx / 640, rem = idx % 640;
            int d = rem / 8, c = rem % 8;
            int col = min(kt + c * 8, SEQ - 8);
            CP_ASYNC16(vs + pl * VPL + (uint32_t)(d * VSTR + c * 8) * 2,
                       gv[pl] + ((size_t)head * HEAD_DIM + d) * SEQ + col);
        }
        CP_COMMIT();
    };

    const int qr = ln >> 2;
    const int kq = (ln & 3) * 2;
    const int row0 = w * 16 + qr;
    const int row1 = row0 + 8;
    const int sq0 = segq[row0], sq1 = segq[row1];

    float m0 = -1e30f, m1 = -1e30f, l0 = 0.f, l1 = 0.f;
    float acc[10][4];
    #pragma unroll
    for (int n = 0; n < 10; n++)
        #pragma unroll
        for (int c = 0; c < 4; c++) acc[n][c] = 0.f;

    const int a_row = (ln & 15);
    const int a_kof = (ln < 16) ? 0 : 8;
    const int b_row = (ln & 7);
    const int b_kof = (ln & 8);

    load_kv(lo, 0);       // tile 0 prefetch (group; Q group still outstanding)
    CP_WAIT(0);           // Q + tile0 complete
    __syncthreads();

    int st = 0;
    for (int kt = lo; kt < hi_; kt += AK) {
        const bool hasNext = (kt + AK) < hi_;
        if (hasNext) load_kv(kt + AK, st ^ 1);

        // segk for this tile (double-buffered slot st)
        if (tid < AK) {
            int key = kt + tid;
            int s = -1;
            if (key < hi_) {
                s = 0;
                for (int j = 1; j < ncu; j++) s += (cu[j] <= key);
            }
            segk[st * AK + tid] = s;
        }
        if (hasNext) { CP_WAIT(1); } else { CP_WAIT(0); }
        __syncthreads();

        const uint32_t pQh = smem_u32(Qb);
        const uint32_t pQl = pQh + QPL;
        const uint32_t pKh = smem_u32(Kb) + st * KSTG;
        const uint32_t pKl = pKh + KPL;
        const uint32_t pVh = smem_u32(Vb) + st * VSTG;
        const uint32_t pVl = pVh + VPL;
        const int* sk = segk + st * AK;

        // ---- S = Q @ K^T, 3-term ----
        float S[8][4];
        #pragma unroll
        for (int j = 0; j < 8; j++)
            #pragma unroll
            for (int c = 0; c < 4; c++) S[j][c] = 0.f;

        #pragma unroll
        for (int kc = 0; kc < 5; kc++) {
            uint32_t ah[4], al[4];
            uint32_t qoff = (uint32_t)((w * 16 + a_row) * QSTR + kc * 16 + a_kof) * 2;
            LDSM_X4(ah[0], ah[1], ah[2], ah[3], pQh + qoff);
            LDSM_X4(al[0], al[1], al[2], al[3], pQl + qoff);
            #pragma unroll
            for (int jg = 0; jg < 2; jg++) {
                uint32_t bh[4][2], bl[4][2];
                #pragma unroll
                for (int q = 0; q < 4; q++) {
                    uint32_t koff = (uint32_t)(((jg * 4 + q) * 8 + b_row) * QSTR
                                               + kc * 16 + b_kof) * 2;
                    LDSM_X2(bh[q][0], bh[q][1], pKh + koff);
                    LDSM_X2(bl[q][0], bl[q][1], pKl + koff);
                }
                #pragma unroll
                for (int q = 0; q < 4; q++) {
                    int j = jg * 4 + q;
                    MMA16816(S[j][0], S[j][1], S[j][2], S[j][3],
                             ah[0], ah[1], ah[2], ah[3], bh[q][0], bh[q][1]);
                }
                #pragma unroll
                for (int q = 0; q < 4; q++) {
                    int j = jg * 4 + q;
                    MMA16816(S[j][0], S[j][1], S[j][2], S[j][3],
                             ah[0], ah[1], ah[2], ah[3], bl[q][0], bl[q][1]);
                }
                #pragma unroll
                for (int q = 0; q < 4; q++) {
                    int j = jg * 4 + q;
                    MMA16816(S[j][0], S[j][1], S[j][2], S[j][3],
                             al[0], al[1], al[2], al[3], bh[q][0], bh[q][1]);
                }
            }
        }

        // ---- masked online softmax ----
        float mt0 = -1e30f, mt1 = -1e30f;
        #pragma unroll
        for (int j = 0; j < 8; j++) {
            int k0 = j * 8 + kq;
            int sk0 = sk[k0], sk1 = sk[k0 + 1];
            mt0 = fmaxf(mt0, (sk0 == sq0) ? S[j][0] : -1e30f);
            mt0 = fmaxf(mt0, (sk1 == sq0) ? S[j][1] : -1e30f);
            mt1 = fmaxf(mt1, (sk0 == sq1) ? S[j][2] : -1e30f);
            mt1 = fmaxf(mt1, (sk1 == sq1) ? S[j][3] : -1e30f);
        }
        #pragma unroll
        for (int msk = 1; msk <= 2; msk <<= 1) {
            mt0 = fmaxf(mt0, __shfl_xor_sync(0xffffffffu, mt0, msk));
            mt1 = fmaxf(mt1, __shfl_xor_sync(0xffffffffu, mt1, msk));
        }
        float mn0 = fmaxf(m0, mt0), mn1 = fmaxf(m1, mt1);
        float alpha0 = __expf(m0 - mn0), alpha1 = __expf(m1 - mn1);
        float rs0 = 0.f, rs1 = 0.f;
        #pragma unroll
        for (int j = 0; j < 8; j++) {
            int k0 = j * 8 + kq;
            int sk0 = sk[k0], sk1 = sk[k0 + 1];
            float p0 = (sk0 == sq0) ? __expf(S[j][0] - mn0) : 0.f;
            float p1 = (sk1 == sq0) ? __expf(S[j][1] - mn0) : 0.f;
            float p2 = (sk0 == sq1) ? __expf(S[j][2] - mn1) : 0.f;
            float p3 = (sk1 == sq1) ? __expf(S[j][3] - mn1) : 0.f;
            S[j][0] = p0; S[j][1] = p1; S[j][2] = p2; S[j][3] = p3;
            rs0 += p0 + p1;
            rs1 += p2 + p3;
        }
        #pragma unroll
        for (int msk = 1; msk <= 2; msk <<= 1) {
            rs0 += __shfl_xor_sync(0xffffffffu, rs0, msk);
            rs1 += __shfl_xor_sync(0xffffffffu, rs1, msk);
        }
        l0 = l0 * alpha0 + rs0;
        l1 = l1 * alpha1 + rs1;
        m0 = mn0; m1 = mn1;
        #pragma unroll
        for (int n = 0; n < 10; n++) {
            acc[n][0] *= alpha0; acc[n][1] *= alpha0;
            acc[n][2] *= alpha1; acc[n][3] *= alpha1;
        }

        // ---- O += P @ V, 3-term ----
        #pragma unroll
        for (int jc = 0; jc < 4; jc++) {
            float h00 = __bfloat162float(__float2bfloat16(S[2*jc][0]));
            float h01 = __bfloat162float(__float2bfloat16(S[2*jc][1]));
            float h02 = __bfloat162float(__float2bfloat16(S[2*jc][2]));
            float h03 = __bfloat162float(__float2bfloat16(S[2*jc][3]));
            float h10 = __bfloat162float(__float2bfloat16(S[2*jc+1][0]));
            float h11 = __bfloat162float(__float2bfloat16(S[2*jc+1][1]));
            float h12 = __bfloat162float(__float2bfloat16(S[2*jc+1][2]));
            float h13 = __bfloat162float(__float2bfloat16(S[2*jc+1][3]));
            uint32_t aPh[4], aPl[4];
            aPh[0] = pack_bf2(h00, h01);
            aPh[1] = pack_bf2(h02, h03);
            aPh[2] = pack_bf2(h10, h11);
            aPh[3] = pack_bf2(h12, h13);
            aPl[0] = pack_bf2(S[2*jc][0] - h00, S[2*jc][1] - h01);
            aPl[1] = pack_bf2(S[2*jc][2] - h02, S[2*jc][3] - h03);
            aPl[2] = pack_bf2(S[2*jc+1][0] - h10, S[2*jc+1][1] - h11);
            aPl[3] = pack_bf2(S[2*jc+1][2] - h12, S[2*jc+1][3] - h13);

            #pragma unroll
            for (int ng = 0; ng < 3; ng++) {
                const int gs = ng * 4;
                const int gn = (ng == 2) ? 2 : 4;
                uint32_t bh[4][2], bl[4][2];
                #pragma unroll
                for (int q = 0; q < 4; q++) {
                    if (q < gn) {
                        uint32_t voff = (uint32_t)(((gs + q) * 8 + b_row) * VSTR
                                                   + jc * 16 + b_kof) * 2;
                        LDSM_X2(bh[q][0], bh[q][1], pVh + voff);
                        LDSM_X2(bl[q][0], bl[q][1], pVl + voff);
                    }
                }
                #pragma unroll
                for (int q = 0; q < 4; q++)
                    if (q < gn)
                        MMA16816(acc[gs+q][0], acc[gs+q][1], acc[gs+q][2], acc[gs+q][3],
                                 aPh[0], aPh[1], aPh[2], aPh[3], bh[q][0], bh[q][1]);
                #pragma unroll
                for (int q = 0; q < 4; q++)
                    if (q < gn)
                        MMA16816(acc[gs+q][0], acc[gs+q][1], acc[gs+q][2], acc[gs+q][3],
                                 aPh[0], aPh[1], aPh[2], aPh[3], bl[q][0], bl[q][1]);
                #pragma unroll
                for (int q = 0; q < 4; q++)
                    if (q < gn)
                        MMA16816(acc[gs+q][0], acc[gs+q][1], acc[gs+q][2], acc[gs+q][3],
                                 aPl[0], aPl[1], aPl[2], aPl[3], bh[q][0], bh[q][1]);
            }
        }

        __syncthreads();   // stage st reads done before iteration i+1 prefetches into it
        st ^= 1;
    }

    // ---- epilogue: normalize + fused hi/lo decomposition ----
    float il0 = (l0 > 0.f) ? (1.f / l0) : 0.f;
    float il1 = (l1 > 0.f) ? (1.f / l1) : 0.f;
    #pragma unroll
    for (int n = 0; n < 10; n++) {
        int d = n * 8 + kq;
        size_t o0 = (size_t)(qbase + row0) * DIM + head * HEAD_DIM + d;
        size_t o1 = (size_t)(qbase + row1) * DIM + head * HEAD_DIM + d;
        float v00 = acc[n][0] * il0, v01 = acc[n][1] * il0;
        float v10 = acc[n][2] * il1, v11 = acc[n][3] * il1;
        __nv_bfloat16 h00 = __float2bfloat16(v00);
        __nv_bfloat16 h01 = __float2bfloat16(v01);
        __nv_bfloat16 h10 = __float2bfloat16(v10);
        __nv_bfloat16 h11 = __float2bfloat16(v11);
        g_at_h[o0]     = h00;
        g_at_h[o0 + 1] = h01;
        g_at_h[o1]     = h10;
        g_at_h[o1 + 1] = h11;
        g_at_l[o0]     = __float2bfloat16(v00 - __bfloat162float(h00));
        g_at_l[o0 + 1] = __float2bfloat16(v01 - __bfloat162float(h01));
        g_at_l[o1]     = __float2bfloat16(v10 - __bfloat162float(h10));
        g_at_l[o1 + 1] = __float2bfloat16(v11 - __bfloat162float(h11));
    }
}

// ---------------------------------------------------------------------------
extern "C" void kernel_launch(void* const* d_in, const int* in_sizes, int n_in,
                              void* d_out, int out_size)
{
    const float* hidden = (const float*)d_in[0];
    const float* rotary = (const float*)d_in[1];
    const int*   cu     = (const int*)d_in[2];
    const float* qkv_w  = (const float*)d_in[3];
    const float* qkv_b  = (const float*)d_in[4];
    const float* proj_w = (const float*)d_in[5];
    const float* proj_b = (const float*)d_in[6];
    float* out = (float*)d_out;
    int ncu = in_sizes[2];

    float *qkv_ptr;
    __nv_bfloat16 *hidH, *hidL, *wqH, *wqL, *wpH, *wpL, *atH, *atL;
    cudaGetSymbolAddress((void**)&qkv_ptr, g_qkv);
    cudaGetSymbolAddress((void**)&hidH, g_hid_h);
    cudaGetSymbolAddress((void**)&hidL, g_hid_l);
    cudaGetSymbolAddress((void**)&wqH, g_wq_h);
    cudaGetSymbolAddress((void**)&wqL, g_wq_l);
    cudaGetSymbolAddress((void**)&wpH, g_wp_h);
    cudaGetSymbolAddress((void**)&wpL, g_wp_l);
    cudaGetSymbolAddress((void**)&atH, g_at_h);
    cudaGetSymbolAddress((void**)&atL, g_at_l);

    cudaFuncSetAttribute(hgemm_split_kernel,
                         cudaFuncAttributeMaxDynamicSharedMemorySize, HG_SMEM);

    // 0) Decompose inputs
    decomp4_kernel<<<(SEQ * DIM / 4 + 255) / 256, 256>>>(
        (const float4*)hidden, (uint32_t*)hidH, (uint32_t*)hidL, SEQ * DIM / 4);
    decomp4_kernel<<<(QKV_DIM * DIM / 4 + 255) / 256, 256>>>(
        (const float4*)qkv_w, (uint32_t*)wqH, (uint32_t*)wqL, QKV_DIM * DIM / 4);
    decomp4_kernel<<<(DIM * DIM / 4 + 255) / 256, 256>>>(
        (const float4*)proj_w, (uint32_t*)wpH, (uint32_t*)wpL, DIM * DIM / 4);

    // 1) QKV GEMM
    hgemm_split_kernel<<<dim3(QKV_DIM / 64, SEQ / 128), 256, HG_SMEM>>>(
        hidH, hidL, wqH, wqL, qkv_b, qkv_ptr, SEQ, QKV_DIM, DIM);

    // 2) Q/K rope+scale+decomp and V transpose+decomp
    {
        int total = SEQ * HEADS * (HEAD_DIM / 2);
        qkprep_kernel<<<(total + 255) / 256, 256>>>(rotary);
        vtprep_kernel<<<dim3(SEQ / 64, HEADS), 256>>>();
    }

    // 3) Flash attention (cp.async planes, double-buffered K/V)
    {
        cudaFuncSetAttribute(fattn_kernel,
                             cudaFuncAttributeMaxDynamicSharedMemorySize, FA_SMEM);
        fattn_kernel<<<dim3(SEQ / AQ, HEADS), 256, FA_SMEM>>>(cu, ncu);
    }

    // 4) proj GEMM
    hgemm_split_kernel<<<dim3(DIM / 64, SEQ / 128), 256, HG_SMEM>>>(
        atH, atL, wpH, wpL, proj_b, out, SEQ, DIM, DIM);
}

// round 10
// speedup vs baseline: 4.1733x; 1.3853x over previous
#include <cuda_runtime.h>
#include <cuda_bf16.h>
#include <cuda_fp16.h>
#include <math.h>
#include <stdint.h>

#define SEQ      2048
#define DIM      1280
#define HEADS    16
#define HEAD_DIM 80
#define QKV_DIM  3840

// ---------------------------------------------------------------------------
// Scratch
// ---------------------------------------------------------------------------
__device__ float g_qkv[SEQ * QKV_DIM];
// fp16 GEMM operand planes
__device__ __half g_hid_h[SEQ * DIM];
__device__ __half g_wq_h[QKV_DIM * DIM], g_wq_l[QKV_DIM * DIM];
__device__ __half g_wp_h[DIM * DIM],     g_wp_l[DIM * DIM];
__device__ __half g_at_h[SEQ * DIM];
// attention operand planes (bf16 3-term): Q/K [h][s][d], V transposed [h][d][s]
__device__ __nv_bfloat16 g_q_h[HEADS * SEQ * HEAD_DIM], g_q_l[HEADS * SEQ * HEAD_DIM];
__device__ __nv_bfloat16 g_k_h[HEADS * SEQ * HEAD_DIM], g_k_l[HEADS * SEQ * HEAD_DIM];
__device__ __nv_bfloat16 g_vt_h[HEADS * HEAD_DIM * SEQ], g_vt_l[HEADS * HEAD_DIM * SEQ];

// ---------------------------------------------------------------------------
// PTX helpers
// ---------------------------------------------------------------------------
#define CP_ASYNC16(dst, src) \
    asm volatile("cp.async.cg.shared.global [%0], [%1], 16;" :: "r"(dst), "l"(src))
#define CP_COMMIT() asm volatile("cp.async.commit_group;")
#define CP_WAIT(n)  asm volatile("cp.async.wait_group %0;" :: "n"(n))

#define LDSM_X4(r0,r1,r2,r3,addr) \
    asm volatile("ldmatrix.sync.aligned.m8n8.x4.shared.b16 {%0,%1,%2,%3}, [%4];" \
        : "=r"(r0),"=r"(r1),"=r"(r2),"=r"(r3) : "r"(addr))
#define LDSM_X2(r0,r1,addr) \
    asm volatile("ldmatrix.sync.aligned.m8n8.x2.shared.b16 {%0,%1}, [%2];" \
        : "=r"(r0),"=r"(r1) : "r"(addr))

// bf16 mma (attention)
#define MMA16816(c0,c1,c2,c3,a0,a1,a2,a3,b0,b1) \
    asm volatile("mma.sync.aligned.m16n8k16.row.col.f32.bf16.bf16.f32 " \
        "{%0,%1,%2,%3}, {%4,%5,%6,%7}, {%8,%9}, {%0,%1,%2,%3};" \
        : "+f"(c0),"+f"(c1),"+f"(c2),"+f"(c3) \
        : "r"(a0),"r"(a1),"r"(a2),"r"(a3),"r"(b0),"r"(b1))

// fp16 mma (GEMMs)
#define MMAH16816(c0,c1,c2,c3,a0,a1,a2,a3,b0,b1) \
    asm volatile("mma.sync.aligned.m16n8k16.row.col.f32.f16.f16.f32 " \
        "{%0,%1,%2,%3}, {%4,%5,%6,%7}, {%8,%9}, {%0,%1,%2,%3};" \
        : "+f"(c0),"+f"(c1),"+f"(c2),"+f"(c3) \
        : "r"(a0),"r"(a1),"r"(a2),"r"(a3),"r"(b0),"r"(b1))

__device__ __forceinline__ uint32_t smem_u32(const void* p) {
    return (uint32_t)__cvta_generic_to_shared(p);
}
__device__ __forceinline__ uint32_t pack_bf2(float a, float b) {
    __nv_bfloat162 v = __float22bfloat162_rn(make_float2(a, b));
    return *(uint32_t*)&v;
}
__device__ __forceinline__ uint32_t pack_h2(float a, float b) {
    __half2 v = __floats2half2_rn(a, b);
    return *(uint32_t*)&v;
}

// ---------------------------------------------------------------------------
// fp16 2-term HGEMM (TN): C = Ah @ (Bh + Bl)^T + bias, fp32 accum.
// Block tile 128x64, 8 warps (4x2), warp tile 32x32, KBLK=32 double-buffered.
// ---------------------------------------------------------------------------
#define KBLK 32
#define KPAD 40
#define APLANE_B (128 * KPAD * 2)              // 10240
#define BPLANE_B (64 * KPAD * 2)               // 5120
#define STAGE_B (APLANE_B + 2 * BPLANE_B)      // 20480
#define HG_SMEM (2 * STAGE_B)                  // 40960

__global__ void __launch_bounds__(256, 3) hgemm2_kernel(
    const __half* __restrict__ Ah_,
    const __half* __restrict__ Bh_, const __half* __restrict__ Bl_,
    const float* __restrict__ bias, float* __restrict__ C,
    int M, int N, int K)
{
    extern __shared__ char smraw[];
    const uint32_t sb = smem_u32(smraw);

    const int tid = threadIdx.x;
    const int ln  = tid & 31;
    const int wid = tid >> 5;
    const int wm  = wid >> 1;
    const int wn  = wid & 1;
    const int m0  = blockIdx.y * 128;
    const int n0  = blockIdx.x * 64;

    const __half* gA = Ah_ + (size_t)m0 * K;
    const __half* gB[2] = { Bh_ + (size_t)n0 * K, Bl_ + (size_t)n0 * K };

    const int arow0 = tid >> 2;
    const int arow1 = (tid + 256) >> 2;
    const int brow  = tid >> 2;
    const int kc16  = (tid & 3) * 8;

    auto load_stage = [&](int kt, int s) {
        const uint32_t stb = sb + s * STAGE_B;
        CP_ASYNC16(stb + (uint32_t)(arow0 * KPAD + kc16) * 2,
                   gA + (size_t)arow0 * K + kt + kc16);
        CP_ASYNC16(stb + (uint32_t)(arow1 * KPAD + kc16) * 2,
                   gA + (size_t)arow1 * K + kt + kc16);
        #pragma unroll
        for (int p = 0; p < 2; p++) {
            const uint32_t pb = stb + APLANE_B + p * BPLANE_B;
            CP_ASYNC16(pb + (uint32_t)(brow * KPAD + kc16) * 2,
                       gB[p] + (size_t)brow * K + kt + kc16);
        }
        CP_COMMIT();
    };

    float acc[2][4][4];
    #pragma unroll
    for (int mi = 0; mi < 2; mi++)
        #pragma unroll
        for (int ni = 0; ni < 4; ni++)
            #pragma unroll
            for (int c = 0; c < 4; c++) acc[mi][ni][c] = 0.f;

    load_stage(0, 0);
    CP_WAIT(0);
    __syncthreads();

    const int a_row = (ln & 15);
    const int a_kof = (ln < 16) ? 0 : 8;
    const int b_row = (ln & 7);
    const int b_kof = (ln & 8);

    int buf = 0;
    for (int kt = 0; kt < K; kt += KBLK) {
        const bool hasNext = (kt + KBLK) < K;
        if (hasNext) load_stage(kt + KBLK, buf ^ 1);

        const uint32_t stb = sb + buf * STAGE_B;
        const uint32_t pAh = stb;
        const uint32_t pBh = stb + APLANE_B;
        const uint32_t pBl = stb + APLANE_B + BPLANE_B;

        #pragma unroll
        for (int ks = 0; ks < 2; ks++) {
            const int k0 = ks * 16;
            uint32_t ah[2][4];
            #pragma unroll
            for (int mi = 0; mi < 2; mi++) {
                uint32_t off = (uint32_t)((wm * 32 + mi * 16 + a_row) * KPAD
                                          + k0 + a_kof) * 2;
                LDSM_X4(ah[mi][0], ah[mi][1], ah[mi][2], ah[mi][3], pAh + off);
            }
            uint32_t bh[4][2], bl[4][2];
            #pragma unroll
            for (int ni = 0; ni < 4; ni++) {
                uint32_t off = (uint32_t)((wn * 32 + ni * 8 + b_row) * KPAD
                                          + k0 + b_kof) * 2;
                LDSM_X2(bh[ni][0], bh[ni][1], pBh + off);
                LDSM_X2(bl[ni][0], bl[ni][1], pBl + off);
            }
            #pragma unroll
            for (int ni = 0; ni < 4; ni++)
                #pragma unroll
                for (int mi = 0; mi < 2; mi++)
                    MMAH16816(acc[mi][ni][0], acc[mi][ni][1],
                              acc[mi][ni][2], acc[mi][ni][3],
                              ah[mi][0], ah[mi][1], ah[mi][2], ah[mi][3],
                              bh[ni][0], bh[ni][1]);
            #pragma unroll
            for (int ni = 0; ni < 4; ni++)
                #pragma unroll
                for (int mi = 0; mi < 2; mi++)
                    MMAH16816(acc[mi][ni][0], acc[mi][ni][1],
                              acc[mi][ni][2], acc[mi][ni][3],
                              ah[mi][0], ah[mi][1], ah[mi][2], ah[mi][3],
                              bl[ni][0], bl[ni][1]);
        }

        if (hasNext) {
            CP_WAIT(0);
            __syncthreads();
            buf ^= 1;
        }
    }

    const int crow = ln >> 2;
    const int ccol = (ln & 3) * 2;
    #pragma unroll
    for (int mi = 0; mi < 2; mi++) {
        #pragma unroll
        for (int ni = 0; ni < 4; ni++) {
            int col = n0 + wn * 32 + ni * 8 + ccol;
            float b0 = bias[col], b1 = bias[col + 1];
            int r0 = m0 + wm * 32 + mi * 16 + crow;
            float2 v0 = make_float2(acc[mi][ni][0] + b0, acc[mi][ni][1] + b1);
            float2 v1 = make_float2(acc[mi][ni][2] + b0, acc[mi][ni][3] + b1);
            *(float2*)(C + (size_t)r0 * N + col)       = v0;
            *(float2*)(C + (size_t)(r0 + 8) * N + col) = v1;
        }
    }
}

// ---------------------------------------------------------------------------
// Decompose: fp32 -> fp16 hi plane only (activations)
// ---------------------------------------------------------------------------
__global__ void __launch_bounds__(256) decomp_hi4_kernel(
    const float4* __restrict__ in, uint32_t* __restrict__ hi2, int total4)
{
    int idx = blockIdx.x * blockDim.x + threadIdx.x;
    if (idx >= total4) return;
    float4 v = in[idx];
    hi2[idx * 2]     = pack_h2(v.x, v.y);
    hi2[idx * 2 + 1] = pack_h2(v.z, v.w);
}

// ---------------------------------------------------------------------------
// Decompose: fp32 -> fp16 hi + lo planes (weights)
// ---------------------------------------------------------------------------
__global__ void __launch_bounds__(256) decomp_hilo4_kernel(
    const float4* __restrict__ in, uint32_t* __restrict__ hi2,
    uint32_t* __restrict__ lo2, int total4)
{
    int idx = blockIdx.x * blockDim.x + threadIdx.x;
    if (idx >= total4) return;
    float4 v = in[idx];
    __half h0 = __float2half_rn(v.x);
    __half h1 = __float2half_rn(v.y);
    __half h2 = __float2half_rn(v.z);
    __half h3 = __float2half_rn(v.w);
    hi2[idx * 2]     = pack_h2(v.x, v.y);
    hi2[idx * 2 + 1] = pack_h2(v.z, v.w);
    lo2[idx * 2]     = pack_h2(v.x - __half2float(h0), v.y - __half2float(h1));
    lo2[idx * 2 + 1] = pack_h2(v.z - __half2float(h2), v.w - __half2float(h3));
}

// ---------------------------------------------------------------------------
// Q/K prep: rope + scale(Q) + bf16 hi/lo decomp -> [h][s][d] planes
// ---------------------------------------------------------------------------
__global__ void __launch_bounds__(256) qkprep_kernel(const float* __restrict__ rot)
{
    int t = blockIdx.x * blockDim.x + threadIdx.x;
    const int total = SEQ * HEADS * (HEAD_DIM / 2);
    if (t >= total) return;
    int d2 = t % 40;
    int h  = (t / 40) % HEADS;
    int s  = t / (40 * HEADS);

    float f = rot[s * 40 + d2];
    float si, co;
    sincosf(f, &si, &co);
    const float scale = rsqrtf((float)HEAD_DIM);

    size_t qb = (size_t)s * QKV_DIM + h * HEAD_DIM;
    float q1 = g_qkv[qb + d2],        q2 = g_qkv[qb + 40 + d2];
    float k1 = g_qkv[qb + DIM + d2],  k2 = g_qkv[qb + DIM + 40 + d2];

    float qr1 = (q1 * co - q2 * si) * scale;
    float qr2 = (q2 * co + q1 * si) * scale;
    float kr1 = k1 * co - k2 * si;
    float kr2 = k2 * co + k1 * si;

    size_t ob = ((size_t)h * SEQ + s) * HEAD_DIM;
    __nv_bfloat16 hq1 = __float2bfloat16(qr1);
    __nv_bfloat16 hq2 = __float2bfloat16(qr2);
    __nv_bfloat16 hk1 = __float2bfloat16(kr1);
    __nv_bfloat16 hk2 = __float2bfloat16(kr2);
    g_q_h[ob + d2]      = hq1;
    g_q_h[ob + 40 + d2] = hq2;
    g_q_l[ob + d2]      = __float2bfloat16(qr1 - __bfloat162float(hq1));
    g_q_l[ob + 40 + d2] = __float2bfloat16(qr2 - __bfloat162float(hq2));
    g_k_h[ob + d2]      = hk1;
    g_k_h[ob + 40 + d2] = hk2;
    g_k_l[ob + d2]      = __float2bfloat16(kr1 - __bfloat162float(hk1));
    g_k_l[ob + 40 + d2] = __float2bfloat16(kr2 - __bfloat162float(hk2));
}

// ---------------------------------------------------------------------------
// V prep: transpose + bf16 hi/lo decomp -> [h][d][s] planes
// ---------------------------------------------------------------------------
__global__ void __launch_bounds__(256) vtprep_kernel()
{
    __shared__ float T[HEAD_DIM][65];
    const int tid = threadIdx.x;
    const int s0  = blockIdx.x * 64;
    const int h   = blockIdx.y;

    #pragma unroll
    for (int i = 0; i < 20; i++) {
        int idx = tid + i * 256;
        int r = idx / HEAD_DIM, d = idx % HEAD_DIM;
        T[d][r] = g_qkv[(size_t)(s0 + r) * QKV_DIM + 2 * DIM + h * HEAD_DIM + d];
    }
    __syncthreads();
    #pragma unroll
    for (int i = 0; i < 20; i++) {
        int idx = tid + i * 256;
        int d = idx / 64, r = idx % 64;
        float v = T[d][r];
        __nv_bfloat16 hi = __float2bfloat16(v);
        size_t o = ((size_t)h * HEAD_DIM + d) * SEQ + s0 + r;
        g_vt_h[o] = hi;
        g_vt_l[o] = __float2bfloat16(v - __bfloat162float(hi));
    }
}

// ---------------------------------------------------------------------------
// Tensor-core flash attention (round-9; epilogue writes fp16 hi plane only)
// ---------------------------------------------------------------------------
#define AQ    128
#define AK    64
#define QSTR  88
#define VSTR  72
#define QPL   (AQ * QSTR * 2)
#define KPL   (AK * QSTR * 2)
#define VPL   (HEAD_DIM * VSTR * 2)
#define KSTG  (2 * KPL)
#define VSTG  (2 * VPL)
#define FA_SMEM (2*QPL + 2*KSTG + 2*VSTG + (AQ + 2*AK + 4) * 4)

__global__ void __launch_bounds__(256) fattn_kernel(const int* __restrict__ cu, int ncu)
{
    extern __shared__ char smraw[];
    char* Qb  = smraw;
    char* Kb  = Qb + 2 * QPL;
    char* Vb  = Kb + 2 * KSTG;
    int* segq  = (int*)(Vb + 2 * VSTG);
    int* segk  = segq + AQ;
    int* range = segk + 2 * AK;

    const int tid = threadIdx.x;
    const int w   = tid >> 5;
    const int ln  = tid & 31;
    const int head  = blockIdx.y;
    const int qbase = blockIdx.x * AQ;

    const __nv_bfloat16* gq[2] = { g_q_h, g_q_l };
    const __nv_bfloat16* gk[2] = { g_k_h, g_k_l };
    const __nv_bfloat16* gv[2] = { g_vt_h, g_vt_l };

    {
        const uint32_t qs = smem_u32(Qb);
        #pragma unroll
        for (int i = 0; i < 10; i++) {
            int idx = tid + i * 256;
            int pl = idx / 1280, rem = idx % 1280;
            int r = rem / 10, c = rem % 10;
            CP_ASYNC16(qs + pl * QPL + (uint32_t)(r * QSTR + c * 8) * 2,
                       gq[pl] + ((size_t)head * SEQ + qbase + r) * HEAD_DIM + c * 8);
        }
        CP_COMMIT();
    }
    if (tid < AQ) {
        int i = qbase + tid;
        int s = 0;
        for (int j = 1; j < ncu; j++) s += (cu[j] <= i);
        segq[tid] = s;
    }
    __syncthreads();
    if (tid == 0) {
        int smin = segq[0], smax = segq[0];
        for (int r = 1; r < AQ; r++) { smin = min(smin, segq[r]); smax = max(smax, segq[r]); }
        range[0] = cu[smin];
        range[1] = cu[smax + 1];
    }
    __syncthreads();
    const int lo = range[0], hi_ = range[1];

    auto load_kv = [&](int kt, int st) {
        const uint32_t ks = smem_u32(Kb) + st * KSTG;
        const uint32_t vs = smem_u32(Vb) + st * VSTG;
        #pragma unroll
        for (int i = 0; i < 5; i++) {
            int idx = tid + i * 256;
            int pl = idx / 640, rem = idx % 640;
            int r = rem / 10, c = rem % 10;
            int row = min(kt + r, SEQ - 1);
            CP_ASYNC16(ks + pl * KPL + (uint32_t)(r * QSTR + c * 8) * 2,
                       gk[pl] + ((size_t)head * SEQ + row) * HEAD_DIM + c * 8);
        }
        #pragma unroll
        for (int i = 0; i < 5; i++) {
            int idx = tid + i * 256;
            int pl = idx / 640, rem = idx % 640;
            int d = rem / 8, c = rem % 8;
            int col = min(kt + c * 8, SEQ - 8);
            CP_ASYNC16(vs + pl * VPL + (uint32_t)(d * VSTR + c * 8) * 2,
                       gv[pl] + ((size_t)head * HEAD_DIM + d) * SEQ + col);
        }
        CP_COMMIT();
    };

    const int qr = ln >> 2;
    const int kq = (ln & 3) * 2;
    const int row0 = w * 16 + qr;
    const int row1 = row0 + 8;
    const int sq0 = segq[row0], sq1 = segq[row1];

    float m0 = -1e30f, m1 = -1e30f, l0 = 0.f, l1 = 0.f;
    float acc[10][4];
    #pragma unroll
    for (int n = 0; n < 10; n++)
        #pragma unroll
        for (int c = 0; c < 4; c++) acc[n][c] = 0.f;

    const int a_row = (ln & 15);
    const int a_kof = (ln < 16) ? 0 : 8;
    const int b_row = (ln & 7);
    const int b_kof = (ln & 8);

    load_kv(lo, 0);
    CP_WAIT(0);
    __syncthreads();

    int st = 0;
    for (int kt = lo; kt < hi_; kt += AK) {
        const bool hasNext = (kt + AK) < hi_;
        if (hasNext) load_kv(kt + AK, st ^ 1);

        if (tid < AK) {
            int key = kt + tid;
            int s = -1;
            if (key < hi_) {
                s = 0;
                for (int j = 1; j < ncu; j++) s += (cu[j] <= key);
            }
            segk[st * AK + tid] = s;
        }
        if (hasNext) { CP_WAIT(1); } else { CP_WAIT(0); }
        __syncthreads();

        const uint32_t pQh = smem_u32(Qb);
        const uint32_t pQl = pQh + QPL;
        const uint32_t pKh = smem_u32(Kb) + st * KSTG;
        const uint32_t pKl = pKh + KPL;
        const uint32_t pVh = smem_u32(Vb) + st * VSTG;
        const uint32_t pVl = pVh + VPL;
        const int* sk = segk + st * AK;

        float S[8][4];
        #pragma unroll
        for (int j = 0; j < 8; j++)
            #pragma unroll
            for (int c = 0; c < 4; c++) S[j][c] = 0.f;

        #pragma unroll
        for (int kc = 0; kc < 5; kc++) {
            uint32_t ah[4], al[4];
            uint32_t qoff = (uint32_t)((w * 16 + a_row) * QSTR + kc * 16 + a_kof) * 2;
            LDSM_X4(ah[0], ah[1], ah[2], ah[3], pQh + qoff);
            LDSM_X4(al[0], al[1], al[2], al[3], pQl + qoff);
            #pragma unroll
            for (int jg = 0; jg < 2; jg++) {
                uint32_t bh[4][2], bl[4][2];
                #pragma unroll
                for (int q = 0; q < 4; q++) {
                    uint32_t koff = (uint32_t)(((jg * 4 + q) * 8 + b_row) * QSTR
                                               + kc * 16 + b_kof) * 2;
                    LDSM_X2(bh[q][0], bh[q][1], pKh + koff);
                    LDSM_X2(bl[q][0], bl[q][1], pKl + koff);
                }
                #pragma unroll
                for (int q = 0; q < 4; q++) {
                    int j = jg * 4 + q;
                    MMA16816(S[j][0], S[j][1], S[j][2], S[j][3],
                             ah[0], ah[1], ah[2], ah[3], bh[q][0], bh[q][1]);
                }
                #pragma unroll
                for (int q = 0; q < 4; q++) {
                    int j = jg * 4 + q;
                    MMA16816(S[j][0], S[j][1], S[j][2], S[j][3],
                             ah[0], ah[1], ah[2], ah[3], bl[q][0], bl[q][1]);
                }
                #pragma unroll
                for (int q = 0; q < 4; q++) {
                    int j = jg * 4 + q;
                    MMA16816(S[j][0], S[j][1], S[j][2], S[j][3],
                             al[0], al[1], al[2], al[3], bh[q][0], bh[q][1]);
                }
            }
        }

        float mt0 = -1e30f, mt1 = -1e30f;
        #pragma unroll
        for (int j = 0; j < 8; j++) {
            int k0 = j * 8 + kq;
            int sk0 = sk[k0], sk1 = sk[k0 + 1];
            mt0 = fmaxf(mt0, (sk0 == sq0) ? S[j][0] : -1e30f);
            mt0 = fmaxf(mt0, (sk1 == sq0) ? S[j][1] : -1e30f);
            mt1 = fmaxf(mt1, (sk0 == sq1) ? S[j][2] : -1e30f);
            mt1 = fmaxf(mt1, (sk1 == sq1) ? S[j][3] : -1e30f);
        }
        #pragma unroll
        for (int msk = 1; msk <= 2; msk <<= 1) {
            mt0 = fmaxf(mt0, __shfl_xor_sync(0xffffffffu, mt0, msk));
            mt1 = fmaxf(mt1, __shfl_xor_sync(0xffffffffu, mt1, msk));
        }
        float mn0 = fmaxf(m0, mt0), mn1 = fmaxf(m1, mt1);
        float alpha0 = __expf(m0 - mn0), alpha1 = __expf(m1 - mn1);
        float rs0 = 0.f, rs1 = 0.f;
        #pragma unroll
        for (int j = 0; j < 8; j++) {
            int k0 = j * 8 + kq;
            int sk0 = sk[k0], sk1 = sk[k0 + 1];
            float p0 = (sk0 == sq0) ? __expf(S[j][0] - mn0) : 0.f;
            float p1 = (sk1 == sq0) ? __expf(S[j][1] - mn0) : 0.f;
            float p2 = (sk0 == sq1) ? __expf(S[j][2] - mn1) : 0.f;
            float p3 = (sk1 == sq1) ? __expf(S[j][3] - mn1) : 0.f;
            S[j][0] = p0; S[j][1] = p1; S[j][2] = p2; S[j][3] = p3;
            rs0 += p0 + p1;
            rs1 += p2 + p3;
        }
        #pragma unroll
        for (int msk = 1; msk <= 2; msk <<= 1) {
            rs0 += __shfl_xor_sync(0xffffffffu, rs0, msk);
            rs1 += __shfl_xor_sync(0xffffffffu, rs1, msk);
        }
        l0 = l0 * alpha0 + rs0;
        l1 = l1 * alpha1 + rs1;
        m0 = mn0; m1 = mn1;
        #pragma unroll
        for (int n = 0; n < 10; n++) {
            acc[n][0] *= alpha0; acc[n][1] *= alpha0;
            acc[n][2] *= alpha1; acc[n][3] *= alpha1;
        }

        #pragma unroll
        for (int jc = 0; jc < 4; jc++) {
            float h00 = __bfloat162float(__float2bfloat16(S[2*jc][0]));
            float h01 = __bfloat162float(__float2bfloat16(S[2*jc][1]));
            float h02 = __bfloat162float(__float2bfloat16(S[2*jc][2]));
            float h03 = __bfloat162float(__float2bfloat16(S[2*jc][3]));
            float h10 = __bfloat162float(__float2bfloat16(S[2*jc+1][0]));
            float h11 = __bfloat162float(__float2bfloat16(S[2*jc+1][1]));
            float h12 = __bfloat162float(__float2bfloat16(S[2*jc+1][2]));
            float h13 = __bfloat162float(__float2bfloat16(S[2*jc+1][3]));
            uint32_t aPh[4], aPl[4];
            aPh[0] = pack_bf2(h00, h01);
            aPh[1] = pack_bf2(h02, h03);
            aPh[2] = pack_bf2(h10, h11);
            aPh[3] = pack_bf2(h12, h13);
            aPl[0] = pack_bf2(S[2*jc][0] - h00, S[2*jc][1] - h01);
            aPl[1] = pack_bf2(S[2*jc][2] - h02, S[2*jc][3] - h03);
            aPl[2] = pack_bf2(S[2*jc+1][0] - h10, S[2*jc+1][1] - h11);
            aPl[3] = pack_bf2(S[2*jc+1][2] - h12, S[2*jc+1][3] - h13);

            #pragma unroll
            for (int ng = 0; ng < 3; ng++) {
                const int gs = ng * 4;
                const int gn = (ng == 2) ? 2 : 4;
                uint32_t bh[4][2], bl[4][2];
                #pragma unroll
                for (int q = 0; q < 4; q++) {
                    if (q < gn) {
                        uint32_t voff = (uint32_t)(((gs + q) * 8 + b_row) * VSTR
                                                   + jc * 16 + b_kof) * 2;
                        LDSM_X2(bh[q][0], bh[q][1], pVh + voff);
                        LDSM_X2(bl[q][0], bl[q][1], pVl + voff);
                    }
                }
                #pragma unroll
                for (int q = 0; q < 4; q++)
                    if (q < gn)
                        MMA16816(acc[gs+q][0], acc[gs+q][1], acc[gs+q][2], acc[gs+q][3],
                                 aPh[0], aPh[1], aPh[2], aPh[3], bh[q][0], bh[q][1]);
                #pragma unroll
                for (int q = 0; q < 4; q++)
                    if (q < gn)
                        MMA16816(acc[gs+q][0], acc[gs+q][1], acc[gs+q][2], acc[gs+q][3],
                                 aPh[0], aPh[1], aPh[2], aPh[3], bl[q][0], bl[q][1]);
                #pragma unroll
                for (int q = 0; q < 4; q++)
                    if (q < gn)
                        MMA16816(acc[gs+q][0], acc[gs+q][1], acc[gs+q][2], acc[gs+q][3],
                                 aPl[0], aPl[1], aPl[2], aPl[3], bh[q][0], bh[q][1]);
            }
        }

        __syncthreads();
        st ^= 1;
    }

    // Epilogue: normalize + fp16 hi plane write (proj A operand)
    float il0 = (l0 > 0.f) ? (1.f / l0) : 0.f;
    float il1 = (l1 > 0.f) ? (1.f / l1) : 0.f;
    #pragma unroll
    for (int n = 0; n < 10; n++) {
        int d = n * 8 + kq;
        size_t o0 = (size_t)(qbase + row0) * DIM + head * HEAD_DIM + d;
        size_t o1 = (size_t)(qbase + row1) * DIM + head * HEAD_DIM + d;
        *(uint32_t*)&g_at_h[o0] = pack_h2(acc[n][0] * il0, acc[n][1] * il0);
        *(uint32_t*)&g_at_h[o1] = pack_h2(acc[n][2] * il1, acc[n][3] * il1);
    }
}

// ---------------------------------------------------------------------------
extern "C" void kernel_launch(void* const* d_in, const int* in_sizes, int n_in,
                              void* d_out, int out_size)
{
    const float* hidden = (const float*)d_in[0];
    const float* rotary = (const float*)d_in[1];
    const int*   cu     = (const int*)d_in[2];
    const float* qkv_w  = (const float*)d_in[3];
    const float* qkv_b  = (const float*)d_in[4];
    const float* proj_w = (const float*)d_in[5];
    const float* proj_b = (const float*)d_in[6];
    float* out = (float*)d_out;
    int ncu = in_sizes[2];

    float *qkv_ptr;
    __half *hidH, *wqH, *wqL, *wpH, *wpL, *atH;
    cudaGetSymbolAddress((void**)&qkv_ptr, g_qkv);
    cudaGetSymbolAddress((void**)&hidH, g_hid_h);
    cudaGetSymbolAddress((void**)&wqH, g_wq_h);
    cudaGetSymbolAddress((void**)&wqL, g_wq_l);
    cudaGetSymbolAddress((void**)&wpH, g_wp_h);
    cudaGetSymbolAddress((void**)&wpL, g_wp_l);
    cudaGetSymbolAddress((void**)&atH, g_at_h);

    cudaFuncSetAttribute(hgemm2_kernel,
                         cudaFuncAttributeMaxDynamicSharedMemorySize, HG_SMEM);

    // 0) Decompose inputs (fp16: activations hi only, weights hi+lo)
    decomp_hi4_kernel<<<(SEQ * DIM / 4 + 255) / 256, 256>>>(
        (const float4*)hidden, (uint32_t*)hidH, SEQ * DIM / 4);
    decomp_hilo4_kernel<<<(QKV_DIM * DIM / 4 + 255) / 256, 256>>>(
        (const float4*)qkv_w, (uint32_t*)wqH, (uint32_t*)wqL, QKV_DIM * DIM / 4);
    decomp_hilo4_kernel<<<(DIM * DIM / 4 + 255) / 256, 256>>>(
        (const float4*)proj_w, (uint32_t*)wpH, (uint32_t*)wpL, DIM * DIM / 4);

    // 1) QKV GEMM (fp16 2-term)
    hgemm2_kernel<<<dim3(QKV_DIM / 64, SEQ / 128), 256, HG_SMEM>>>(
        hidH, wqH, wqL, qkv_b, qkv_ptr, SEQ, QKV_DIM, DIM);

    // 2) Q/K rope+scale+decomp and V transpose+decomp (bf16 3-term attention)
    {
        int total = SEQ * HEADS * (HEAD_DIM / 2);
        qkprep_kernel<<<(total + 255) / 256, 256>>>(rotary);
        vtprep_kernel<<<dim3(SEQ / 64, HEADS), 256>>>();
    }

    // 3) Flash attention
    {
        cudaFuncSetAttribute(fattn_kernel,
                             cudaFuncAttributeMaxDynamicSharedMemorySize, FA_SMEM);
        fattn_kernel<<<dim3(SEQ / AQ, HEADS), 256, FA_SMEM>>>(cu, ncu);
    }

    // 4) proj GEMM (fp16 2-term)
    hgemm2_kernel<<<dim3(DIM / 64, SEQ / 128), 256, HG_SMEM>>>(
        atH, wpH, wpL, proj_b, out, SEQ, DIM, DIM);
}